// round 7
// baseline (speedup 1.0000x reference)
#include <cuda_runtime.h>
#include <cstdint>

#define SS   256
#define BB   8
#define VV   32000
#define DD   512
#define NCELL 16
#define RR   512
#define GG   2048   // 4*R
#define HH   8
#define MROWS 2048  // S*B

// ---------------- scratch (__device__ globals; no allocation) ----------------
__device__ float g_xs   [(size_t)SS*BB*DD];            // (S,B,D)   4 MB
__device__ float g_qpre [(size_t)SS*BB*DD];            // (S,B,D)   4 MB
__device__ float g_ihp  [(size_t)SS*NCELL*GG*BB];      // (S,N,G,B) 256 MB
__device__ float g_wp   [(size_t)NCELL*GG*RR];         // repacked W_hh 64 MB
__device__ float g_hall [(size_t)NCELL*SS*BB*RR];      // (N,S,B,R) 64 MB
__device__ float g_nout [(size_t)NCELL*SS*BB*DD];      // (N,S,B,D) 64 MB
__device__ float g_kv   [(size_t)NCELL*SS*BB*1024];    // (N,S,B,1024) 128 MB
__device__ float g_att  [(size_t)SS*BB*DD];
__device__ float g_yraw [(size_t)SS*BB*DD];
__device__ float g_mixed[(size_t)SS*BB*DD];
__device__ float g_hbuf [2*NCELL*RR*BB];               // [parity][n][k][b]
__device__ int   g_cnt  [NCELL];

// ---------------- embed + counter reset ----------------
__global__ __launch_bounds__(128)
void embed_kernel(const int* __restrict__ x, const float* __restrict__ emb)
{
    int tb = blockIdx.x;               // t*8+b
    int t = tb >> 3, b = tb & 7;
    if (tb == 0 && threadIdx.x < NCELL) g_cnt[threadIdx.x] = 0;
    int idx = x[b*SS + t];
    const float4* src = (const float4*)(emb + (size_t)idx*DD);
    float4* dst = (float4*)(g_xs + (size_t)tb*DD);
    dst[threadIdx.x] = src[threadIdx.x];   // 128 threads * float4 = 512 floats
}

// ---------------- W_hh repack: Wp[n][c][k4][lr][0..3] ----------------
__global__ __launch_bounds__(256)
void repack_kernel(const float* __restrict__ whh)
{
    int o = blockIdx.x*256 + threadIdx.x;     // float4 index
    int lr = o & 255;
    int k4 = (o >> 8) & 127;
    int c  = (o >> 15) & 7;
    int n  = o >> 18;
    int grow = (lr >> 6)*512 + c*64 + (lr & 63);
    float4 v = *(const float4*)(whh + ((size_t)n*GG + grow)*RR + k4*4);
    ((float4*)g_wp)[o] = v;
}

// ---------------- generic fp32 GEMM: C = A @ B^T + bias ----------------
// A rows addressed by (m>>3)*sAt + (m&7)*sAb (+ z*sAz), K contiguous.
// B is (Nc,K) row-major (+ z*sBz).  C elem at (m>>3)*sCt + (m&7)*sCb + col*sCc (+ z*sCz).
__global__ __launch_bounds__(256)
void gemm_kernel(const float* __restrict__ A, const float* __restrict__ Bw,
                 const float* __restrict__ bias1, const float* __restrict__ bias2,
                 float* __restrict__ C, int K,
                 long sAt, long sAb, long sAz, long sBz,
                 long sCt, long sCb, long sCc, long sCz, long sBiasZ)
{
    __shared__ float As[16][68];
    __shared__ float Bs[16][68];
    int tid = threadIdx.x;
    int bx = blockIdx.x, by = blockIdx.y, bz = blockIdx.z;
    const float* Ab  = A  + (size_t)bz * sAz;
    const float* Bwb = Bw + (size_t)bz * sBz;
    float*       Cb  = C  + (size_t)bz * sCz;

    int lm  = tid >> 2;          // 0..63
    int lk4 = (tid & 3) * 4;     // 0,4,8,12
    int arow = by*64 + lm;
    long aoff = (long)(arow >> 3)*sAt + (long)(arow & 7)*sAb;
    long boff = (long)(bx*64 + lm) * K;

    int tx = tid & 15, ty = tid >> 4;
    float acc[4][4] = {};

    for (int kt = 0; kt < K; kt += 16) {
        float4 av = *(const float4*)(Ab  + aoff + kt + lk4);
        float4 bv = *(const float4*)(Bwb + boff + kt + lk4);
        As[lk4+0][lm]=av.x; As[lk4+1][lm]=av.y; As[lk4+2][lm]=av.z; As[lk4+3][lm]=av.w;
        Bs[lk4+0][lm]=bv.x; Bs[lk4+1][lm]=bv.y; Bs[lk4+2][lm]=bv.z; Bs[lk4+3][lm]=bv.w;
        __syncthreads();
        #pragma unroll
        for (int k = 0; k < 16; k++) {
            float4 ra = *(const float4*)&As[k][ty*4];
            float4 rb = *(const float4*)&Bs[k][tx*4];
            acc[0][0]+=ra.x*rb.x; acc[0][1]+=ra.x*rb.y; acc[0][2]+=ra.x*rb.z; acc[0][3]+=ra.x*rb.w;
            acc[1][0]+=ra.y*rb.x; acc[1][1]+=ra.y*rb.y; acc[1][2]+=ra.y*rb.z; acc[1][3]+=ra.y*rb.w;
            acc[2][0]+=ra.z*rb.x; acc[2][1]+=ra.z*rb.y; acc[2][2]+=ra.z*rb.z; acc[2][3]+=ra.z*rb.w;
            acc[3][0]+=ra.w*rb.x; acc[3][1]+=ra.w*rb.y; acc[3][2]+=ra.w*rb.z; acc[3][3]+=ra.w*rb.w;
        }
        __syncthreads();
    }
    #pragma unroll
    for (int i = 0; i < 4; i++) {
        int r = by*64 + ty*4 + i;
        long cro = (long)(r >> 3)*sCt + (long)(r & 7)*sCb;
        #pragma unroll
        for (int j = 0; j < 4; j++) {
            int cc = bx*64 + tx*4 + j;
            float bvv = 0.f;
            if (bias1) bvv  = bias1[(long)bz*sBiasZ + cc];
            if (bias2) bvv += bias2[cc];
            Cb[cro + (long)cc*sCc] = acc[i][j] + bvv;
        }
    }
}

// ---------------- persistent LSTM recurrence ----------------
// grid 128: blockIdx = cell*8 + chunk.  512 threads.
__global__ __launch_bounds__(512)
void recurrence_kernel(const float* __restrict__ h0, const float* __restrict__ c0,
                       float* hf_out, float* cf_out)
{
    __shared__ float h_s[RR][BB];       // 16 KB, [k][b]
    __shared__ float g_sm[256][9];      // padded gate exchange

    int tid  = threadIdx.x;
    int cell = blockIdx.x >> 3;
    int cb   = blockIdx.x & 7;

    // compute-phase mapping: 256 gate rows x 2 batch halves
    int lr = tid & 255;
    int bh = tid >> 8;                  // 0/1 -> batches bh*4..bh*4+3
    int grow = (lr >> 6)*512 + cb*64 + (lr & 63);

    // update-phase mapping: 64 units x 8 batches
    int ub = tid >> 6;                  // 0..7
    int uj = tid & 63;

    // init h (step-0 input) and c
    {
        int k = tid;
        #pragma unroll
        for (int b = 0; b < BB; b++)
            h_s[k][b] = h0[((size_t)cell*BB + b)*RR + k];
    }
    float c_reg = c0[((size_t)cell*BB + ub)*RR + cb*64 + uj];
    __syncthreads();

    const float4* wbase = (const float4*)g_wp + (size_t)(cell*8 + cb)*128*256;

    for (int t = 0; t < SS; t++) {
        // gates = W_hh@h + precomputed (ih + biases)
        float4 acc = *(const float4*)(g_ihp + (((size_t)t*NCELL + cell)*GG + grow)*BB + bh*4);
        #pragma unroll 4
        for (int k4 = 0; k4 < 128; k4++) {
            float4 w = __ldg(&wbase[k4*256 + lr]);
            const float4* hv = (const float4*)&h_s[k4*4][bh*4];  // stride 2 float4 per k
            float4 h0v = hv[0], h1v = hv[2], h2v = hv[4], h3v = hv[6];
            acc.x += w.x*h0v.x + w.y*h1v.x + w.z*h2v.x + w.w*h3v.x;
            acc.y += w.x*h0v.y + w.y*h1v.y + w.z*h2v.y + w.w*h3v.y;
            acc.z += w.x*h0v.z + w.y*h1v.z + w.z*h2v.z + w.w*h3v.z;
            acc.w += w.x*h0v.w + w.y*h1v.w + w.z*h2v.w + w.w*h3v.w;
        }
        g_sm[lr][bh*4+0] = acc.x;
        g_sm[lr][bh*4+1] = acc.y;
        g_sm[lr][bh*4+2] = acc.z;
        g_sm[lr][bh*4+3] = acc.w;
        __syncthreads();

        // LSTM update for (unit uj, batch ub)
        float gi = g_sm[      uj][ub];
        float gf = g_sm[ 64 + uj][ub];
        float gg = g_sm[128 + uj][ub];
        float go = g_sm[192 + uj][ub];
        float si = 1.f/(1.f + expf(-gi));
        float sf = 1.f/(1.f + expf(-gf));
        float so = 1.f/(1.f + expf(-go));
        float cn = sf*c_reg + si*tanhf(gg);
        float hn = so*tanhf(cn);
        c_reg = cn;

        g_hall[(((size_t)cell*SS + t)*BB + ub)*RR + cb*64 + uj] = hn;
        int par = (t + 1) & 1;
        g_hbuf[((size_t)(par*NCELL + cell)*RR + (cb*64 + uj))*BB + ub] = hn;
        if (t == SS-1) {
            if (hf_out) hf_out[((size_t)cell*BB + ub)*RR + cb*64 + uj] = hn;
            if (cf_out) cf_out[((size_t)cell*BB + ub)*RR + cb*64 + uj] = cn;
        }

        // cross-CTA barrier among the 8 chunks of this cell
        __threadfence();
        __syncthreads();
        if (tid == 0) {
            atomicAdd(&g_cnt[cell], 1);
            int target = 8*(t+1);
            while (atomicAdd(&g_cnt[cell], 0) < target) { }
        }
        __syncthreads();

        // reload full h for next step (L1-bypass: written by peer CTAs)
        {
            const float* src = g_hbuf + ((size_t)(par*NCELL + cell)*RR + tid)*BB;
            float4 p0 = __ldcg((const float4*)src);
            float4 p1 = __ldcg((const float4*)(src + 4));
            *(float4*)&h_s[tid][0] = p0;
            *(float4*)&h_s[tid][4] = p1;
        }
        __syncthreads();
    }
}

// ---------------- attention (q,k,v -> att) ----------------
__global__ __launch_bounds__(256)
void attn_kernel()
{
    int tb = blockIdx.x;                // t*8+b
    int t = tb >> 3, b = tb & 7;
    int h = threadIdx.x >> 5;
    int lane = threadIdx.x & 31;

    const float* qrow = g_qpre + (size_t)tb*DD + h*64;
    float q0 = qrow[2*lane], q1 = qrow[2*lane + 1];

    float s[NCELL];
    #pragma unroll
    for (int n = 0; n < NCELL; n++) {
        const float* kp = g_kv + (((size_t)n*SS + t)*BB + b)*1024 + h*64;
        float2 k2 = *(const float2*)(kp + 2*lane);
        float p = q0*k2.x + q1*k2.y;
        #pragma unroll
        for (int o = 16; o > 0; o >>= 1) p += __shfl_xor_sync(0xffffffffu, p, o);
        s[n] = p * 0.125f;              // 1/sqrt(64)
    }
    float m = s[0];
    #pragma unroll
    for (int n = 1; n < NCELL; n++) m = fmaxf(m, s[n]);
    float sum = 0.f;
    #pragma unroll
    for (int n = 0; n < NCELL; n++) { s[n] = expf(s[n] - m); sum += s[n]; }
    float inv = 1.f/sum;

    float a0 = 0.f, a1 = 0.f;
    #pragma unroll
    for (int n = 0; n < NCELL; n++) {
        const float* vp = g_kv + (((size_t)n*SS + t)*BB + b)*1024 + 512 + h*64;
        float2 v2 = *(const float2*)(vp + 2*lane);
        float w = s[n]*inv;
        a0 += w*v2.x; a1 += w*v2.y;
    }
    float* ap = g_att + (size_t)tb*DD + h*64;
    ap[2*lane] = a0; ap[2*lane + 1] = a1;
}

// ---------------- residual + layernorm ----------------
__global__ __launch_bounds__(256)
void ln_kernel(const float* __restrict__ lng, const float* __restrict__ lnb)
{
    __shared__ float red[8];
    int tb = blockIdx.x;
    int tid = threadIdx.x;
    const float* yp = g_yraw + (size_t)tb*DD;
    const float* xp = g_xs   + (size_t)tb*DD;
    float y0 = yp[2*tid]   + xp[2*tid];
    float y1 = yp[2*tid+1] + xp[2*tid+1];

    float v = y0 + y1;
    #pragma unroll
    for (int o = 16; o > 0; o >>= 1) v += __shfl_xor_sync(0xffffffffu, v, o);
    if ((tid & 31) == 0) red[tid >> 5] = v;
    __syncthreads();
    float r = (tid < 8) ? red[tid] : 0.f;
    if (tid < 32) {
        #pragma unroll
        for (int o = 4; o > 0; o >>= 1) r += __shfl_xor_sync(0xffffffffu, r, o);
        if (tid == 0) red[0] = r;
    }
    __syncthreads();
    float mu = red[0] * (1.f/512.f);
    __syncthreads();

    float d0 = y0 - mu, d1 = y1 - mu;
    float sq = d0*d0 + d1*d1;
    #pragma unroll
    for (int o = 16; o > 0; o >>= 1) sq += __shfl_xor_sync(0xffffffffu, sq, o);
    if ((tid & 31) == 0) red[tid >> 5] = sq;
    __syncthreads();
    float r2 = (tid < 8) ? red[tid] : 0.f;
    if (tid < 32) {
        #pragma unroll
        for (int o = 4; o > 0; o >>= 1) r2 += __shfl_xor_sync(0xffffffffu, r2, o);
        if (tid == 0) red[0] = r2;
    }
    __syncthreads();
    float rstd = rsqrtf(red[0] * (1.f/512.f) + 1e-5f);

    float* mp = g_mixed + (size_t)tb*DD;
    mp[2*tid]   = d0*rstd*lng[2*tid]   + lnb[2*tid];
    mp[2*tid+1] = d1*rstd*lng[2*tid+1] + lnb[2*tid+1];
}

// ---------------- host launcher ----------------
extern "C" void kernel_launch(void* const* d_in, const int* in_sizes, int n_in,
                              void* d_out, int out_size)
{
    const int*   x      = (const int*)  d_in[0];
    const float* h0     = (const float*)d_in[1];
    const float* c0     = (const float*)d_in[2];
    const float* emb    = (const float*)d_in[3];
    const float* W_ih   = (const float*)d_in[4];
    const float* b_ih   = (const float*)d_in[5];
    const float* W_hh   = (const float*)d_in[6];
    const float* b_hh   = (const float*)d_in[7];
    const float* W_np   = (const float*)d_in[8];
    const float* b_np   = (const float*)d_in[9];
    const float* in_w   = (const float*)d_in[10];
    const float* in_b   = (const float*)d_in[11];
    const float* op_w   = (const float*)d_in[12];
    const float* op_b   = (const float*)d_in[13];
    const float* ln_g   = (const float*)d_in[14];
    const float* ln_b   = (const float*)d_in[15];
    const float* head_w = (const float*)d_in[16];
    const float* head_b = (const float*)d_in[17];
    float* out = (float*)d_out;

    float *xs, *qpre, *ihp, *hall, *nout, *kv, *att, *yraw, *mixed;
    cudaGetSymbolAddress((void**)&xs,    g_xs);
    cudaGetSymbolAddress((void**)&qpre,  g_qpre);
    cudaGetSymbolAddress((void**)&ihp,   g_ihp);
    cudaGetSymbolAddress((void**)&hall,  g_hall);
    cudaGetSymbolAddress((void**)&nout,  g_nout);
    cudaGetSymbolAddress((void**)&kv,    g_kv);
    cudaGetSymbolAddress((void**)&att,   g_att);
    cudaGetSymbolAddress((void**)&yraw,  g_yraw);
    cudaGetSymbolAddress((void**)&mixed, g_mixed);

    const long BSV = (long)BB*SS*VV;          // 65,536,000
    const long NBR = (long)NCELL*BB*RR;       // 65,536
    bool write_state = ((long)out_size >= BSV + 2*NBR);
    float* hf_out = write_state ? out + BSV        : nullptr;
    float* cf_out = write_state ? out + BSV + NBR  : nullptr;

    // 1. embed + counter reset
    embed_kernel<<<MROWS, 128>>>(x, emb);
    // 2. repack W_hh
    repack_kernel<<<(NCELL*GG*RR/4)/256, 256>>>(W_hh);
    // 3. q = xs @ Wq^T + bq          (S,B,D)
    gemm_kernel<<<dim3(DD/64, MROWS/64, 1), 256>>>(
        xs, in_w, in_b, nullptr, qpre, DD,
        8L*DD, DD, 0, 0,   8L*DD, DD, 1, 0, 0);
    // 4. gates_ih = xs @ W_ih^T + (b_ih+b_hh)   -> (S,N,G,B) scatter
    gemm_kernel<<<dim3(NCELL*GG/64, MROWS/64, 1), 256>>>(
        xs, W_ih, b_ih, b_hh, ihp, DD,
        8L*DD, DD, 0, 0,
        (long)NCELL*GG*BB, 1, BB, 0, 0);
    // 5. recurrence (persistent, 128 CTAs)
    recurrence_kernel<<<NCELL*8, 512>>>(h0, c0, hf_out, cf_out);
    // 6. nout[n] = hall[n] @ W_np[n]^T + b_np[n]   (z over cells)
    gemm_kernel<<<dim3(DD/64, MROWS/64, NCELL), 256>>>(
        hall, W_np, b_np, nullptr, nout, RR,
        8L*RR, RR, (long)SS*BB*RR, (long)DD*RR,
        8L*DD, DD, 1, (long)SS*BB*DD, DD);
    // 7. kv = nout @ [Wk;Wv]^T + [bk;bv]   M=32768, Nc=1024
    gemm_kernel<<<dim3(1024/64, (NCELL*MROWS)/64, 1), 256>>>(
        nout, in_w + (size_t)DD*DD, in_b + DD, nullptr, kv, DD,
        8L*DD, DD, 0, 0,   8L*1024, 1024, 1, 0, 0);
    // 8. attention
    attn_kernel<<<MROWS, 256>>>();
    // 9. op projection: yraw = att @ op_w^T + op_b
    gemm_kernel<<<dim3(DD/64, MROWS/64, 1), 256>>>(
        att, op_w, op_b, nullptr, yraw, DD,
        8L*DD, DD, 0, 0,   8L*DD, DD, 1, 0, 0);
    // 10. residual + LN
    ln_kernel<<<MROWS, 256>>>(ln_g, ln_b);
    // 11. head: logits -> out (B,S,V)
    gemm_kernel<<<dim3(VV/64, MROWS/64, 1), 256>>>(
        mixed, head_w, head_b, nullptr, out, DD,
        8L*DD, DD, 0, 0,
        (long)VV, (long)SS*VV, 1, 0, 0);
}

// round 8
// speedup vs baseline: 1.2490x; 1.2490x over previous
#include <cuda_runtime.h>
#include <cstdint>

#define SS   256
#define BB   8
#define VV   32000
#define DD   512
#define NCELL 16
#define RR   512
#define GG   2048   // 4*R
#define HH   8
#define MROWS 2048  // S*B

// ---------------- scratch (__device__ globals; no allocation) ----------------
__device__ float g_xs   [(size_t)SS*BB*DD];            // (S,B,D)   4 MB
__device__ float g_qpre [(size_t)SS*BB*DD];            // (S,B,D)   4 MB
__device__ float g_ihp  [(size_t)SS*NCELL*BB*GG];      // (S,N,B,G) 256 MB
__device__ float g_wp   [(size_t)NCELL*GG*RR];         // repacked W_hh 64 MB
__device__ float g_hall [(size_t)NCELL*SS*BB*RR];      // (N,S,B,R) 64 MB
__device__ float g_nout [(size_t)NCELL*SS*BB*DD];      // (N,S,B,D) 64 MB
__device__ float g_kv   [(size_t)NCELL*SS*BB*1024];    // (N,S,B,1024) 128 MB
__device__ float g_att  [(size_t)SS*BB*DD];
__device__ float g_yraw [(size_t)SS*BB*DD];
__device__ float g_mixed[(size_t)SS*BB*DD];
__device__ float g_hbuf [2*NCELL*RR*BB];               // [parity][n][k][b]
__device__ int   g_cnt  [NCELL];

// ---------------- helpers ----------------
__device__ __forceinline__ float tf32r(float x) {
    uint32_t o;
    asm("cvt.rna.tf32.f32 %0, %1;" : "=r"(o) : "f"(x));
    return __uint_as_float(o);
}

__device__ __forceinline__ void mma8(float* c, const uint32_t* a, const uint32_t* b) {
    asm volatile(
        "mma.sync.aligned.m16n8k8.row.col.f32.tf32.tf32.f32 "
        "{%0,%1,%2,%3}, {%4,%5,%6,%7}, {%8,%9}, {%0,%1,%2,%3};\n"
        : "+f"(c[0]), "+f"(c[1]), "+f"(c[2]), "+f"(c[3])
        : "r"(a[0]), "r"(a[1]), "r"(a[2]), "r"(a[3]), "r"(b[0]), "r"(b[1]));
}

// ---------------- embed + counter reset ----------------
__global__ __launch_bounds__(128)
void embed_kernel(const int* __restrict__ x, const float* __restrict__ emb)
{
    int tb = blockIdx.x;               // t*8+b
    int t = tb >> 3, b = tb & 7;
    if (tb == 0 && threadIdx.x < NCELL) g_cnt[threadIdx.x] = 0;
    int idx = x[b*SS + t];
    const float4* src = (const float4*)(emb + (size_t)idx*DD);
    float4* dst = (float4*)(g_xs + (size_t)tb*DD);
    dst[threadIdx.x] = src[threadIdx.x];
}

// ---------------- W_hh repack: Wp[n][c][k4][lr][0..3] ----------------
__global__ __launch_bounds__(256)
void repack_kernel(const float* __restrict__ whh)
{
    int o = blockIdx.x*256 + threadIdx.x;     // float4 index
    int lr = o & 255;
    int k4 = (o >> 8) & 127;
    int c  = (o >> 15) & 7;
    int n  = o >> 18;
    int grow = (lr >> 6)*512 + c*64 + (lr & 63);
    float4 v = *(const float4*)(whh + ((size_t)n*GG + grow)*RR + k4*4);
    ((float4*)g_wp)[o] = v;
}

// ---------------- TF32 tensor-core GEMM: C = A @ B^T + bias ----------------
// A: contiguous rows, row stride lda (+ z*sAz). B: (Nc,K) row-major (+ z*sBz).
// C element (row m, col c): (m>>3)*sCt + (m&7)*sCb
//                         + (c>>blkLog)*sCcBlk + (c & mask)*sCc  (+ z*sCz)
// CTA tile 128x128, BK=32, 8 warps of 64x32 each.
__global__ __launch_bounds__(256)
void mma_gemm(const float* __restrict__ A, const float* __restrict__ Bw,
              const float* __restrict__ bias1, const float* __restrict__ bias2,
              float* __restrict__ C, int K, long lda,
              long sAz, long sBz, long sBiasZ,
              long sCt, long sCb, long sCc, long sCz,
              long sCcBlk, int blkLog)
{
    __shared__ float As[32][132];   // [k][m], pad 132 -> conflict-free frag loads
    __shared__ float Bs[32][132];   // [k][n]

    int tid  = threadIdx.x;
    int lane = tid & 31;
    int warp = tid >> 5;
    int wm = warp & 1;              // 2 warp-rows of 64
    int wn = warp >> 1;             // 4 warp-cols of 32
    int bx = blockIdx.x, by = blockIdx.y, bz = blockIdx.z;

    const float* Ab = A  + (size_t)bz * sAz;
    const float* Bb = Bw + (size_t)bz * sBz;
    float*       Cb = C  + (size_t)bz * sCz;

    int lm  = tid & 127;            // tile row (A) / tile col (B)
    int lkh = (tid >> 7) * 16;      // k-half 0 or 16
    const float* aptr = Ab + (size_t)(by*128 + lm)*lda + lkh;
    const float* bptr = Bb + (size_t)(bx*128 + lm)*K   + lkh;

    int qr = lane >> 2;             // 0..7
    int qc = lane & 3;              // 0..3
    int amBase = wm*64;
    int bnBase = wn*32;

    float acc[4][4][4];
    #pragma unroll
    for (int i = 0; i < 4; i++)
        #pragma unroll
        for (int j = 0; j < 4; j++)
            #pragma unroll
            for (int e = 0; e < 4; e++) acc[i][j][e] = 0.f;

    for (int kt = 0; kt < K; kt += 32) {
        float4 av[4], bv[4];
        #pragma unroll
        for (int q = 0; q < 4; q++) {
            av[q] = *(const float4*)(aptr + kt + q*4);
            bv[q] = *(const float4*)(bptr + kt + q*4);
        }
        __syncthreads();
        #pragma unroll
        for (int q = 0; q < 4; q++) {
            As[lkh+q*4+0][lm] = tf32r(av[q].x);
            As[lkh+q*4+1][lm] = tf32r(av[q].y);
            As[lkh+q*4+2][lm] = tf32r(av[q].z);
            As[lkh+q*4+3][lm] = tf32r(av[q].w);
            Bs[lkh+q*4+0][lm] = tf32r(bv[q].x);
            Bs[lkh+q*4+1][lm] = tf32r(bv[q].y);
            Bs[lkh+q*4+2][lm] = tf32r(bv[q].z);
            Bs[lkh+q*4+3][lm] = tf32r(bv[q].w);
        }
        __syncthreads();

        #pragma unroll
        for (int s = 0; s < 4; s++) {
            int k0 = s*8;
            uint32_t af[4][4], bf[4][2];
            #pragma unroll
            for (int i = 0; i < 4; i++) {
                int m = amBase + i*16 + qr;
                af[i][0] = __float_as_uint(As[k0+qc  ][m]);
                af[i][1] = __float_as_uint(As[k0+qc  ][m+8]);
                af[i][2] = __float_as_uint(As[k0+qc+4][m]);
                af[i][3] = __float_as_uint(As[k0+qc+4][m+8]);
            }
            #pragma unroll
            for (int j = 0; j < 4; j++) {
                int n = bnBase + j*8 + qr;
                bf[j][0] = __float_as_uint(Bs[k0+qc  ][n]);
                bf[j][1] = __float_as_uint(Bs[k0+qc+4][n]);
            }
            #pragma unroll
            for (int i = 0; i < 4; i++)
                #pragma unroll
                for (int j = 0; j < 4; j++)
                    mma8(acc[i][j], af[i], bf[j]);
        }
    }

    long msk = (1L << blkLog) - 1;
    #pragma unroll
    for (int i = 0; i < 4; i++) {
        int r0 = by*128 + amBase + i*16 + qr;
        long ro  = (long)(r0 >> 3)*sCt + (long)(r0 & 7)*sCb;
        long ro8 = (long)((r0+8) >> 3)*sCt + (long)((r0+8) & 7)*sCb;
        #pragma unroll
        for (int j = 0; j < 4; j++) {
            int c0 = bx*128 + bnBase + j*8 + 2*qc;
            float b0v = 0.f, b1v = 0.f;
            if (bias1) { b0v  = bias1[(long)bz*sBiasZ + c0];
                         b1v  = bias1[(long)bz*sBiasZ + c0 + 1]; }
            if (bias2) { b0v += bias2[c0]; b1v += bias2[c0 + 1]; }
            long cc0 = (long)(c0 >> blkLog)*sCcBlk + (long)(c0 & msk)*sCc;
            long cc1 = (long)((c0+1) >> blkLog)*sCcBlk + (long)((c0+1) & msk)*sCc;
            Cb[ro  + cc0] = acc[i][j][0] + b0v;
            Cb[ro  + cc1] = acc[i][j][1] + b1v;
            Cb[ro8 + cc0] = acc[i][j][2] + b0v;
            Cb[ro8 + cc1] = acc[i][j][3] + b1v;
        }
    }
}

// ---------------- persistent LSTM recurrence ----------------
// grid 128: blockIdx = cell*8 + chunk.  512 threads.
__global__ __launch_bounds__(512)
void recurrence_kernel(const float* __restrict__ h0, const float* __restrict__ c0,
                       float* hf_out, float* cf_out)
{
    __shared__ float h_s[RR][BB];       // 16 KB, [k][b]
    __shared__ float g_sm[256][9];      // padded gate exchange

    int tid  = threadIdx.x;
    int cell = blockIdx.x >> 3;
    int cb   = blockIdx.x & 7;

    int lr = tid & 255;
    int bh = tid >> 8;                  // 0/1 -> batches bh*4..bh*4+3
    int grow = (lr >> 6)*512 + cb*64 + (lr & 63);

    int ub = tid >> 6;                  // 0..7
    int uj = tid & 63;

    {
        int k = tid;
        #pragma unroll
        for (int b = 0; b < BB; b++)
            h_s[k][b] = h0[((size_t)cell*BB + b)*RR + k];
    }
    float c_reg = c0[((size_t)cell*BB + ub)*RR + cb*64 + uj];
    __syncthreads();

    const float4* wbase = (const float4*)g_wp + (size_t)(cell*8 + cb)*128*256;

    for (int t = 0; t < SS; t++) {
        // gates = W_hh@h + precomputed (ih + biases); ihp layout [t][n][b][g]
        const float* ib = g_ihp + (((size_t)t*NCELL + cell)*BB + bh*4)*GG + grow;
        float4 acc;
        acc.x = ib[0];
        acc.y = ib[GG];
        acc.z = ib[2*GG];
        acc.w = ib[3*GG];
        #pragma unroll 4
        for (int k4 = 0; k4 < 128; k4++) {
            float4 w = __ldg(&wbase[k4*256 + lr]);
            const float4* hv = (const float4*)&h_s[k4*4][bh*4];
            float4 h0v = hv[0], h1v = hv[2], h2v = hv[4], h3v = hv[6];
            acc.x += w.x*h0v.x + w.y*h1v.x + w.z*h2v.x + w.w*h3v.x;
            acc.y += w.x*h0v.y + w.y*h1v.y + w.z*h2v.y + w.w*h3v.y;
            acc.z += w.x*h0v.z + w.y*h1v.z + w.z*h2v.z + w.w*h3v.z;
            acc.w += w.x*h0v.w + w.y*h1v.w + w.z*h2v.w + w.w*h3v.w;
        }
        g_sm[lr][bh*4+0] = acc.x;
        g_sm[lr][bh*4+1] = acc.y;
        g_sm[lr][bh*4+2] = acc.z;
        g_sm[lr][bh*4+3] = acc.w;
        __syncthreads();

        float gi = g_sm[      uj][ub];
        float gf = g_sm[ 64 + uj][ub];
        float gg = g_sm[128 + uj][ub];
        float go = g_sm[192 + uj][ub];
        float si = 1.f/(1.f + expf(-gi));
        float sf = 1.f/(1.f + expf(-gf));
        float so = 1.f/(1.f + expf(-go));
        float cn = sf*c_reg + si*tanhf(gg);
        float hn = so*tanhf(cn);
        c_reg = cn;

        g_hall[(((size_t)cell*SS + t)*BB + ub)*RR + cb*64 + uj] = hn;
        int par = (t + 1) & 1;
        g_hbuf[((size_t)(par*NCELL + cell)*RR + (cb*64 + uj))*BB + ub] = hn;
        if (t == SS-1) {
            if (hf_out) hf_out[((size_t)cell*BB + ub)*RR + cb*64 + uj] = hn;
            if (cf_out) cf_out[((size_t)cell*BB + ub)*RR + cb*64 + uj] = cn;
        }

        __threadfence();
        __syncthreads();
        if (tid == 0) {
            atomicAdd(&g_cnt[cell], 1);
            int target = 8*(t+1);
            while (atomicAdd(&g_cnt[cell], 0) < target) { }
        }
        __syncthreads();

        {
            const float* src = g_hbuf + ((size_t)(par*NCELL + cell)*RR + tid)*BB;
            float4 p0 = __ldcg((const float4*)src);
            float4 p1 = __ldcg((const float4*)(src + 4));
            *(float4*)&h_s[tid][0] = p0;
            *(float4*)&h_s[tid][4] = p1;
        }
        __syncthreads();
    }
}

// ---------------- attention (q,k,v -> att) ----------------
__global__ __launch_bounds__(256)
void attn_kernel()
{
    int tb = blockIdx.x;                // t*8+b
    int t = tb >> 3, b = tb & 7;
    int h = threadIdx.x >> 5;
    int lane = threadIdx.x & 31;

    const float* qrow = g_qpre + (size_t)tb*DD + h*64;
    float q0 = qrow[2*lane], q1 = qrow[2*lane + 1];

    float s[NCELL];
    #pragma unroll
    for (int n = 0; n < NCELL; n++) {
        const float* kp = g_kv + (((size_t)n*SS + t)*BB + b)*1024 + h*64;
        float2 k2 = *(const float2*)(kp + 2*lane);
        float p = q0*k2.x + q1*k2.y;
        #pragma unroll
        for (int o = 16; o > 0; o >>= 1) p += __shfl_xor_sync(0xffffffffu, p, o);
        s[n] = p * 0.125f;              // 1/sqrt(64)
    }
    float m = s[0];
    #pragma unroll
    for (int n = 1; n < NCELL; n++) m = fmaxf(m, s[n]);
    float sum = 0.f;
    #pragma unroll
    for (int n = 0; n < NCELL; n++) { s[n] = expf(s[n] - m); sum += s[n]; }
    float inv = 1.f/sum;

    float a0 = 0.f, a1 = 0.f;
    #pragma unroll
    for (int n = 0; n < NCELL; n++) {
        const float* vp = g_kv + (((size_t)n*SS + t)*BB + b)*1024 + 512 + h*64;
        float2 v2 = *(const float2*)(vp + 2*lane);
        float w = s[n]*inv;
        a0 += w*v2.x; a1 += w*v2.y;
    }
    float* ap = g_att + (size_t)tb*DD + h*64;
    ap[2*lane] = a0; ap[2*lane + 1] = a1;
}

// ---------------- residual + layernorm ----------------
__global__ __launch_bounds__(256)
void ln_kernel(const float* __restrict__ lng, const float* __restrict__ lnb)
{
    __shared__ float red[8];
    int tb = blockIdx.x;
    int tid = threadIdx.x;
    const float* yp = g_yraw + (size_t)tb*DD;
    const float* xp = g_xs   + (size_t)tb*DD;
    float y0 = yp[2*tid]   + xp[2*tid];
    float y1 = yp[2*tid+1] + xp[2*tid+1];

    float v = y0 + y1;
    #pragma unroll
    for (int o = 16; o > 0; o >>= 1) v += __shfl_xor_sync(0xffffffffu, v, o);
    if ((tid & 31) == 0) red[tid >> 5] = v;
    __syncthreads();
    float r = (tid < 8) ? red[tid] : 0.f;
    if (tid < 32) {
        #pragma unroll
        for (int o = 4; o > 0; o >>= 1) r += __shfl_xor_sync(0xffffffffu, r, o);
        if (tid == 0) red[0] = r;
    }
    __syncthreads();
    float mu = red[0] * (1.f/512.f);
    __syncthreads();

    float d0 = y0 - mu, d1 = y1 - mu;
    float sq = d0*d0 + d1*d1;
    #pragma unroll
    for (int o = 16; o > 0; o >>= 1) sq += __shfl_xor_sync(0xffffffffu, sq, o);
    if ((tid & 31) == 0) red[tid >> 5] = sq;
    __syncthreads();
    float r2 = (tid < 8) ? red[tid] : 0.f;
    if (tid < 32) {
        #pragma unroll
        for (int o = 4; o > 0; o >>= 1) r2 += __shfl_xor_sync(0xffffffffu, r2, o);
        if (tid == 0) red[0] = r2;
    }
    __syncthreads();
    float rstd = rsqrtf(red[0] * (1.f/512.f) + 1e-5f);

    float* mp = g_mixed + (size_t)tb*DD;
    mp[2*tid]   = d0*rstd*lng[2*tid]   + lnb[2*tid];
    mp[2*tid+1] = d1*rstd*lng[2*tid+1] + lnb[2*tid+1];
}

// ---------------- host launcher ----------------
extern "C" void kernel_launch(void* const* d_in, const int* in_sizes, int n_in,
                              void* d_out, int out_size)
{
    const int*   x      = (const int*)  d_in[0];
    const float* h0     = (const float*)d_in[1];
    const float* c0     = (const float*)d_in[2];
    const float* emb    = (const float*)d_in[3];
    const float* W_ih   = (const float*)d_in[4];
    const float* b_ih   = (const float*)d_in[5];
    const float* W_hh   = (const float*)d_in[6];
    const float* b_hh   = (const float*)d_in[7];
    const float* W_np   = (const float*)d_in[8];
    const float* b_np   = (const float*)d_in[9];
    const float* in_w   = (const float*)d_in[10];
    const float* in_b   = (const float*)d_in[11];
    const float* op_w   = (const float*)d_in[12];
    const float* op_b   = (const float*)d_in[13];
    const float* ln_g   = (const float*)d_in[14];
    const float* ln_b   = (const float*)d_in[15];
    const float* head_w = (const float*)d_in[16];
    const float* head_b = (const float*)d_in[17];
    float* out = (float*)d_out;

    float *xs, *qpre, *ihp, *hall, *nout, *kv, *att, *mixed;
    cudaGetSymbolAddress((void**)&xs,    g_xs);
    cudaGetSymbolAddress((void**)&qpre,  g_qpre);
    cudaGetSymbolAddress((void**)&ihp,   g_ihp);
    cudaGetSymbolAddress((void**)&hall,  g_hall);
    cudaGetSymbolAddress((void**)&nout,  g_nout);
    cudaGetSymbolAddress((void**)&kv,    g_kv);
    cudaGetSymbolAddress((void**)&att,   g_att);
    float* yraw; cudaGetSymbolAddress((void**)&yraw, g_yraw);
    cudaGetSymbolAddress((void**)&mixed, g_mixed);

    const long BSV = (long)BB*SS*VV;          // 65,536,000
    const long NBR = (long)NCELL*BB*RR;       // 65,536
    bool write_state = ((long)out_size >= BSV + 2*NBR);
    float* hf_out = write_state ? out + BSV        : nullptr;
    float* cf_out = write_state ? out + BSV + NBR  : nullptr;

    // 1. embed + counter reset
    embed_kernel<<<MROWS, 128>>>(x, emb);
    // 2. repack W_hh
    repack_kernel<<<(NCELL*GG*RR/4)/256, 256>>>(W_hh);
    // 3. q = xs @ Wq^T + bq          (S,B,D)
    mma_gemm<<<dim3(DD/128, MROWS/128, 1), 256>>>(
        xs, in_w, in_b, nullptr, qpre, DD, DD,
        0, 0, 0,
        8L*DD, DD, 1, 0, 0, 30);
    // 4. gates_ih = xs @ W_ih^T + (b_ih+b_hh)  -> ihp[t][n][b][g]
    mma_gemm<<<dim3(NCELL*GG/128, MROWS/128, 1), 256>>>(
        xs, W_ih, b_ih, b_hh, ihp, DD, DD,
        0, 0, 0,
        (long)NCELL*BB*GG, GG, 1, 0,
        (long)BB*GG, 11);
    // 5. recurrence (persistent, 128 CTAs)
    recurrence_kernel<<<NCELL*8, 512>>>(h0, c0, hf_out, cf_out);
    // 6. nout[n] = hall[n] @ W_np[n]^T + b_np[n]
    mma_gemm<<<dim3(DD/128, MROWS/128, NCELL), 256>>>(
        hall, W_np, b_np, nullptr, nout, RR, RR,
        (long)SS*BB*RR, (long)DD*RR, DD,
        8L*DD, DD, 1, (long)SS*BB*DD, 0, 30);
    // 7. kv = nout @ [Wk;Wv]^T + [bk;bv]   M=32768, Nc=1024
    mma_gemm<<<dim3(1024/128, (NCELL*MROWS)/128, 1), 256>>>(
        nout, in_w + (size_t)DD*DD, in_b + DD, nullptr, kv, DD, DD,
        0, 0, 0,
        8L*1024, 1024, 1, 0, 0, 30);
    // 8. attention
    attn_kernel<<<MROWS, 256>>>();
    // 9. op projection: yraw = att @ op_w^T + op_b
    mma_gemm<<<dim3(DD/128, MROWS/128, 1), 256>>>(
        att, op_w, op_b, nullptr, yraw, DD, DD,
        0, 0, 0,
        8L*DD, DD, 1, 0, 0, 30);
    // 10. residual + LN
    ln_kernel<<<MROWS, 256>>>(ln_g, ln_b);
    // 11. head: logits -> out (B,S,V)
    mma_gemm<<<dim3(VV/128, MROWS/128, 1), 256>>>(
        mixed, head_w, head_b, nullptr, out, DD, DD,
        0, 0, 0,
        (long)VV, (long)SS*VV, 1, 0, 0, 30);
}

// round 9
// speedup vs baseline: 1.2574x; 1.0067x over previous
#include <cuda_runtime.h>
#include <cstdint>

#define SS   256
#define BB   8
#define VV   32000
#define DD   512
#define NCELL 16
#define RR   512
#define GG   2048   // 4*R
#define HH   8
#define MROWS 2048  // S*B

// ---------------- scratch (__device__ globals; no allocation) ----------------
__device__ float g_xs   [(size_t)SS*BB*DD];            // (S,B,D)   4 MB
__device__ float g_qpre [(size_t)SS*BB*DD];            // (S,B,D)   4 MB
__device__ float g_ihp  [(size_t)SS*NCELL*BB*GG];      // (S,N,B,G) 256 MB
__device__ float g_wp   [(size_t)NCELL*GG*RR];         // repacked W_hh 64 MB
__device__ float g_hall [(size_t)NCELL*SS*BB*RR];      // (N,S,B,R) 64 MB
__device__ float g_nout [(size_t)NCELL*SS*BB*DD];      // (N,S,B,D) 64 MB
__device__ float g_kv   [(size_t)NCELL*SS*BB*1024];    // (N,S,B,1024) 128 MB
__device__ float g_att  [(size_t)SS*BB*DD];
__device__ float g_yraw [(size_t)SS*BB*DD];
__device__ float g_mixed[(size_t)SS*BB*DD];
__device__ float g_hbuf [2*NCELL*RR*BB];               // [parity][n][k][b]
__device__ volatile int g_cnt[NCELL];

// ---------------- helpers ----------------
__device__ __forceinline__ float tf32r(float x) {
    uint32_t o;
    asm("cvt.rna.tf32.f32 %0, %1;" : "=r"(o) : "f"(x));
    return __uint_as_float(o);
}

__device__ __forceinline__ void mma8(float* c, const uint32_t* a, const uint32_t* b) {
    asm volatile(
        "mma.sync.aligned.m16n8k8.row.col.f32.tf32.tf32.f32 "
        "{%0,%1,%2,%3}, {%4,%5,%6,%7}, {%8,%9}, {%0,%1,%2,%3};\n"
        : "+f"(c[0]), "+f"(c[1]), "+f"(c[2]), "+f"(c[3])
        : "r"(a[0]), "r"(a[1]), "r"(a[2]), "r"(a[3]), "r"(b[0]), "r"(b[1]));
}

// ---------------- embed + counter reset ----------------
__global__ __launch_bounds__(128)
void embed_kernel(const int* __restrict__ x, const float* __restrict__ emb)
{
    int tb = blockIdx.x;               // t*8+b
    int t = tb >> 3, b = tb & 7;
    if (tb == 0 && threadIdx.x < NCELL) g_cnt[threadIdx.x] = 0;
    int idx = x[b*SS + t];
    const float4* src = (const float4*)(emb + (size_t)idx*DD);
    float4* dst = (float4*)(g_xs + (size_t)tb*DD);
    dst[threadIdx.x] = src[threadIdx.x];
}

// ---------------- W_hh repack: Wp[n][c][k4][lr][0..3] ----------------
__global__ __launch_bounds__(256)
void repack_kernel(const float* __restrict__ whh)
{
    int o = blockIdx.x*256 + threadIdx.x;     // float4 index
    int lr = o & 255;
    int k4 = (o >> 8) & 127;
    int c  = (o >> 15) & 7;
    int n  = o >> 18;
    int grow = (lr >> 6)*512 + c*64 + (lr & 63);
    float4 v = *(const float4*)(whh + ((size_t)n*GG + grow)*RR + k4*4);
    ((float4*)g_wp)[o] = v;
}

// ---------------- TF32 tensor-core GEMM: C = A @ B^T + bias ----------------
// Double-buffered pipelined version. CTA tile 128x128, BK=32, 8 warps of 64x32.
// A: contiguous rows, row stride lda (+ z*sAz). B: (Nc,K) row-major (+ z*sBz).
// C element (row m, col c): (m>>3)*sCt + (m&7)*sCb
//                         + (c>>blkLog)*sCcBlk + (c & mask)*sCc  (+ z*sCz)
#define TILE_F (32*132)   // floats per buffer per operand
__global__ __launch_bounds__(256)
void mma_gemm(const float* __restrict__ A, const float* __restrict__ Bw,
              const float* __restrict__ bias1, const float* __restrict__ bias2,
              float* __restrict__ C, int K, long lda,
              long sAz, long sBz, long sBiasZ,
              long sCt, long sCb, long sCc, long sCz,
              long sCcBlk, int blkLog)
{
    extern __shared__ float smem[];
    float* Abuf = smem;                 // [2][32][132]
    float* Bbuf = smem + 2*TILE_F;      // [2][32][132]

    int tid  = threadIdx.x;
    int lane = tid & 31;
    int warp = tid >> 5;
    int wm = warp & 1;              // 2 warp-rows of 64
    int wn = warp >> 1;             // 4 warp-cols of 32
    int bx = blockIdx.x, by = blockIdx.y, bz = blockIdx.z;

    const float* Ab = A  + (size_t)bz * sAz;
    const float* Bb = Bw + (size_t)bz * sBz;
    float*       Cb = C  + (size_t)bz * sCz;

    int lm  = tid & 127;            // tile row (A) / tile col (B)
    int lkh = (tid >> 7) * 16;      // k-half 0 or 16
    const float* aptr = Ab + (size_t)(by*128 + lm)*lda + lkh;
    const float* bptr = Bb + (size_t)(bx*128 + lm)*K   + lkh;

    int qr = lane >> 2;             // 0..7
    int qc = lane & 3;              // 0..3
    int amBase = wm*64;
    int bnBase = wn*32;

    float acc[4][4][4];
    #pragma unroll
    for (int i = 0; i < 4; i++)
        #pragma unroll
        for (int j = 0; j < 4; j++)
            #pragma unroll
            for (int e = 0; e < 4; e++) acc[i][j][e] = 0.f;

    float4 av[4], bv[4];
    // prologue: load + store tile 0
    #pragma unroll
    for (int q = 0; q < 4; q++) {
        av[q] = *(const float4*)(aptr + q*4);
        bv[q] = *(const float4*)(bptr + q*4);
    }
    {
        float* As = Abuf;  float* Bs = Bbuf;
        #pragma unroll
        for (int q = 0; q < 4; q++) {
            As[(lkh+q*4+0)*132+lm] = tf32r(av[q].x);
            As[(lkh+q*4+1)*132+lm] = tf32r(av[q].y);
            As[(lkh+q*4+2)*132+lm] = tf32r(av[q].z);
            As[(lkh+q*4+3)*132+lm] = tf32r(av[q].w);
            Bs[(lkh+q*4+0)*132+lm] = tf32r(bv[q].x);
            Bs[(lkh+q*4+1)*132+lm] = tf32r(bv[q].y);
            Bs[(lkh+q*4+2)*132+lm] = tf32r(bv[q].z);
            Bs[(lkh+q*4+3)*132+lm] = tf32r(bv[q].w);
        }
    }
    __syncthreads();

    int buf = 0;
    for (int kt = 0; kt < K; kt += 32) {
        bool has_next = (kt + 32) < K;
        if (has_next) {
            #pragma unroll
            for (int q = 0; q < 4; q++) {
                av[q] = *(const float4*)(aptr + kt + 32 + q*4);
                bv[q] = *(const float4*)(bptr + kt + 32 + q*4);
            }
        }
        // MMA on current buffer
        {
            const float* As = Abuf + buf*TILE_F;
            const float* Bs = Bbuf + buf*TILE_F;
            #pragma unroll
            for (int s = 0; s < 4; s++) {
                int k0 = s*8;
                uint32_t af[4][4], bf[4][2];
                #pragma unroll
                for (int i = 0; i < 4; i++) {
                    int m = amBase + i*16 + qr;
                    af[i][0] = __float_as_uint(As[(k0+qc  )*132 + m]);
                    af[i][1] = __float_as_uint(As[(k0+qc  )*132 + m+8]);
                    af[i][2] = __float_as_uint(As[(k0+qc+4)*132 + m]);
                    af[i][3] = __float_as_uint(As[(k0+qc+4)*132 + m+8]);
                }
                #pragma unroll
                for (int j = 0; j < 4; j++) {
                    int n = bnBase + j*8 + qr;
                    bf[j][0] = __float_as_uint(Bs[(k0+qc  )*132 + n]);
                    bf[j][1] = __float_as_uint(Bs[(k0+qc+4)*132 + n]);
                }
                #pragma unroll
                for (int i = 0; i < 4; i++)
                    #pragma unroll
                    for (int j = 0; j < 4; j++)
                        mma8(acc[i][j], af[i], bf[j]);
            }
        }
        if (has_next) {
            float* As = Abuf + (buf^1)*TILE_F;
            float* Bs = Bbuf + (buf^1)*TILE_F;
            #pragma unroll
            for (int q = 0; q < 4; q++) {
                As[(lkh+q*4+0)*132+lm] = tf32r(av[q].x);
                As[(lkh+q*4+1)*132+lm] = tf32r(av[q].y);
                As[(lkh+q*4+2)*132+lm] = tf32r(av[q].z);
                As[(lkh+q*4+3)*132+lm] = tf32r(av[q].w);
                Bs[(lkh+q*4+0)*132+lm] = tf32r(bv[q].x);
                Bs[(lkh+q*4+1)*132+lm] = tf32r(bv[q].y);
                Bs[(lkh+q*4+2)*132+lm] = tf32r(bv[q].z);
                Bs[(lkh+q*4+3)*132+lm] = tf32r(bv[q].w);
            }
        }
        __syncthreads();
        buf ^= 1;
    }

    long msk = (1L << blkLog) - 1;
    #pragma unroll
    for (int i = 0; i < 4; i++) {
        int r0 = by*128 + amBase + i*16 + qr;
        long ro  = (long)(r0 >> 3)*sCt + (long)(r0 & 7)*sCb;
        long ro8 = (long)((r0+8) >> 3)*sCt + (long)((r0+8) & 7)*sCb;
        #pragma unroll
        for (int j = 0; j < 4; j++) {
            int c0 = bx*128 + bnBase + j*8 + 2*qc;
            float b0v = 0.f, b1v = 0.f;
            if (bias1) { b0v  = bias1[(long)bz*sBiasZ + c0];
                         b1v  = bias1[(long)bz*sBiasZ + c0 + 1]; }
            if (bias2) { b0v += bias2[c0]; b1v += bias2[c0 + 1]; }
            long cc0 = (long)(c0 >> blkLog)*sCcBlk + (long)(c0 & msk)*sCc;
            long cc1 = (long)((c0+1) >> blkLog)*sCcBlk + (long)((c0+1) & msk)*sCc;
            Cb[ro  + cc0] = acc[i][j][0] + b0v;
            Cb[ro  + cc1] = acc[i][j][1] + b1v;
            Cb[ro8 + cc0] = acc[i][j][2] + b0v;
            Cb[ro8 + cc1] = acc[i][j][3] + b1v;
        }
    }
}

// ---------------- persistent LSTM recurrence ----------------
// grid 128: blockIdx = cell*8 + chunk.  512 threads.
__global__ __launch_bounds__(512)
void recurrence_kernel(const float* __restrict__ h0, const float* __restrict__ c0,
                       float* hf_out, float* cf_out)
{
    __shared__ float h_s[RR][BB];       // 16 KB, [k][b]
    __shared__ float g_sm[256][9];      // padded gate exchange

    int tid  = threadIdx.x;
    int cell = blockIdx.x >> 3;
    int cb   = blockIdx.x & 7;

    int lr = tid & 255;
    int bh = tid >> 8;                  // 0/1 -> batches bh*4..bh*4+3
    int grow = (lr >> 6)*512 + cb*64 + (lr & 63);

    int ub = tid >> 6;                  // 0..7
    int uj = tid & 63;

    {
        int k = tid;
        #pragma unroll
        for (int b = 0; b < BB; b++)
            h_s[k][b] = h0[((size_t)cell*BB + b)*RR + k];
    }
    float c_reg = c0[((size_t)cell*BB + ub)*RR + cb*64 + uj];
    __syncthreads();

    const float4* wbase = (const float4*)g_wp + (size_t)(cell*8 + cb)*128*256;

    for (int t = 0; t < SS; t++) {
        // gates = W_hh@h + precomputed (ih + biases); ihp layout [t][n][b][g]
        const float* ib = g_ihp + (((size_t)t*NCELL + cell)*BB + bh*4)*GG + grow;
        float4 acc;
        acc.x = ib[0];
        acc.y = ib[GG];
        acc.z = ib[2*GG];
        acc.w = ib[3*GG];
        #pragma unroll 4
        for (int k4 = 0; k4 < 128; k4++) {
            float4 w = __ldg(&wbase[k4*256 + lr]);
            const float4* hv = (const float4*)&h_s[k4*4][bh*4];
            float4 h0v = hv[0], h1v = hv[2], h2v = hv[4], h3v = hv[6];
            acc.x += w.x*h0v.x + w.y*h1v.x + w.z*h2v.x + w.w*h3v.x;
            acc.y += w.x*h0v.y + w.y*h1v.y + w.z*h2v.y + w.w*h3v.y;
            acc.z += w.x*h0v.z + w.y*h1v.z + w.z*h2v.z + w.w*h3v.z;
            acc.w += w.x*h0v.w + w.y*h1v.w + w.z*h2v.w + w.w*h3v.w;
        }
        g_sm[lr][bh*4+0] = acc.x;
        g_sm[lr][bh*4+1] = acc.y;
        g_sm[lr][bh*4+2] = acc.z;
        g_sm[lr][bh*4+3] = acc.w;
        __syncthreads();

        float gi = g_sm[      uj][ub];
        float gf = g_sm[ 64 + uj][ub];
        float gg = g_sm[128 + uj][ub];
        float go = g_sm[192 + uj][ub];
        float si = 1.f/(1.f + expf(-gi));
        float sf = 1.f/(1.f + expf(-gf));
        float so = 1.f/(1.f + expf(-go));
        float cn = sf*c_reg + si*tanhf(gg);
        float hn = so*tanhf(cn);
        c_reg = cn;

        g_hall[(((size_t)cell*SS + t)*BB + ub)*RR + cb*64 + uj] = hn;
        int par = (t + 1) & 1;
        g_hbuf[((size_t)(par*NCELL + cell)*RR + (cb*64 + uj))*BB + ub] = hn;
        if (t == SS-1) {
            if (hf_out) hf_out[((size_t)cell*BB + ub)*RR + cb*64 + uj] = hn;
            if (cf_out) cf_out[((size_t)cell*BB + ub)*RR + cb*64 + uj] = cn;
        }

        __threadfence();
        __syncthreads();
        if (tid == 0) {
            atomicAdd((int*)&g_cnt[cell], 1);
            int target = 8*(t+1);
            while (g_cnt[cell] < target) { }
        }
        __syncthreads();

        {
            const float* src = g_hbuf + ((size_t)(par*NCELL + cell)*RR + tid)*BB;
            float4 p0 = __ldcg((const float4*)src);
            float4 p1 = __ldcg((const float4*)(src + 4));
            *(float4*)&h_s[tid][0] = p0;
            *(float4*)&h_s[tid][4] = p1;
        }
        __syncthreads();
    }
}

// ---------------- attention (q,k,v -> att) ----------------
__global__ __launch_bounds__(256)
void attn_kernel()
{
    int tb = blockIdx.x;                // t*8+b
    int t = tb >> 3, b = tb & 7;
    int h = threadIdx.x >> 5;
    int lane = threadIdx.x & 31;

    const float* qrow = g_qpre + (size_t)tb*DD + h*64;
    float q0 = qrow[2*lane], q1 = qrow[2*lane + 1];

    float s[NCELL];
    #pragma unroll
    for (int n = 0; n < NCELL; n++) {
        const float* kp = g_kv + (((size_t)n*SS + t)*BB + b)*1024 + h*64;
        float2 k2 = *(const float2*)(kp + 2*lane);
        float p = q0*k2.x + q1*k2.y;
        #pragma unroll
        for (int o = 16; o > 0; o >>= 1) p += __shfl_xor_sync(0xffffffffu, p, o);
        s[n] = p * 0.125f;              // 1/sqrt(64)
    }
    float m = s[0];
    #pragma unroll
    for (int n = 1; n < NCELL; n++) m = fmaxf(m, s[n]);
    float sum = 0.f;
    #pragma unroll
    for (int n = 0; n < NCELL; n++) { s[n] = expf(s[n] - m); sum += s[n]; }
    float inv = 1.f/sum;

    float a0 = 0.f, a1 = 0.f;
    #pragma unroll
    for (int n = 0; n < NCELL; n++) {
        const float* vp = g_kv + (((size_t)n*SS + t)*BB + b)*1024 + 512 + h*64;
        float2 v2 = *(const float2*)(vp + 2*lane);
        float w = s[n]*inv;
        a0 += w*v2.x; a1 += w*v2.y;
    }
    float* ap = g_att + (size_t)tb*DD + h*64;
    ap[2*lane] = a0; ap[2*lane + 1] = a1;
}

// ---------------- residual + layernorm ----------------
__global__ __launch_bounds__(256)
void ln_kernel(const float* __restrict__ lng, const float* __restrict__ lnb)
{
    __shared__ float red[8];
    int tb = blockIdx.x;
    int tid = threadIdx.x;
    const float* yp = g_yraw + (size_t)tb*DD;
    const float* xp = g_xs   + (size_t)tb*DD;
    float y0 = yp[2*tid]   + xp[2*tid];
    float y1 = yp[2*tid+1] + xp[2*tid+1];

    float v = y0 + y1;
    #pragma unroll
    for (int o = 16; o > 0; o >>= 1) v += __shfl_xor_sync(0xffffffffu, v, o);
    if ((tid & 31) == 0) red[tid >> 5] = v;
    __syncthreads();
    float r = (tid < 8) ? red[tid] : 0.f;
    if (tid < 32) {
        #pragma unroll
        for (int o = 4; o > 0; o >>= 1) r += __shfl_xor_sync(0xffffffffu, r, o);
        if (tid == 0) red[0] = r;
    }
    __syncthreads();
    float mu = red[0] * (1.f/512.f);
    __syncthreads();

    float d0 = y0 - mu, d1 = y1 - mu;
    float sq = d0*d0 + d1*d1;
    #pragma unroll
    for (int o = 16; o > 0; o >>= 1) sq += __shfl_xor_sync(0xffffffffu, sq, o);
    if ((tid & 31) == 0) red[tid >> 5] = sq;
    __syncthreads();
    float r2 = (tid < 8) ? red[tid] : 0.f;
    if (tid < 32) {
        #pragma unroll
        for (int o = 4; o > 0; o >>= 1) r2 += __shfl_xor_sync(0xffffffffu, r2, o);
        if (tid == 0) red[0] = r2;
    }
    __syncthreads();
    float rstd = rsqrtf(red[0] * (1.f/512.f) + 1e-5f);

    float* mp = g_mixed + (size_t)tb*DD;
    mp[2*tid]   = d0*rstd*lng[2*tid]   + lnb[2*tid];
    mp[2*tid+1] = d1*rstd*lng[2*tid+1] + lnb[2*tid+1];
}

// ---------------- host launcher ----------------
extern "C" void kernel_launch(void* const* d_in, const int* in_sizes, int n_in,
                              void* d_out, int out_size)
{
    const int*   x      = (const int*)  d_in[0];
    const float* h0     = (const float*)d_in[1];
    const float* c0     = (const float*)d_in[2];
    const float* emb    = (const float*)d_in[3];
    const float* W_ih   = (const float*)d_in[4];
    const float* b_ih   = (const float*)d_in[5];
    const float* W_hh   = (const float*)d_in[6];
    const float* b_hh   = (const float*)d_in[7];
    const float* W_np   = (const float*)d_in[8];
    const float* b_np   = (const float*)d_in[9];
    const float* in_w   = (const float*)d_in[10];
    const float* in_b   = (const float*)d_in[11];
    const float* op_w   = (const float*)d_in[12];
    const float* op_b   = (const float*)d_in[13];
    const float* ln_g   = (const float*)d_in[14];
    const float* ln_b   = (const float*)d_in[15];
    const float* head_w = (const float*)d_in[16];
    const float* head_b = (const float*)d_in[17];
    float* out = (float*)d_out;

    float *xs, *qpre, *ihp, *hall, *nout, *kv, *att, *mixed;
    cudaGetSymbolAddress((void**)&xs,    g_xs);
    cudaGetSymbolAddress((void**)&qpre,  g_qpre);
    cudaGetSymbolAddress((void**)&ihp,   g_ihp);
    cudaGetSymbolAddress((void**)&hall,  g_hall);
    cudaGetSymbolAddress((void**)&nout,  g_nout);
    cudaGetSymbolAddress((void**)&kv,    g_kv);
    cudaGetSymbolAddress((void**)&att,   g_att);
    float* yraw; cudaGetSymbolAddress((void**)&yraw, g_yraw);
    cudaGetSymbolAddress((void**)&mixed, g_mixed);

    const int GEMM_SMEM = 4 * TILE_F * 2 * (int)sizeof(float);   // 67584 B
    static int smem_set = 0;
    if (!smem_set) {
        cudaFuncSetAttribute(mma_gemm, cudaFuncAttributeMaxDynamicSharedMemorySize, GEMM_SMEM);
        smem_set = 1;
    }

    const long BSV = (long)BB*SS*VV;          // 65,536,000
    const long NBR = (long)NCELL*BB*RR;       // 65,536
    bool write_state = ((long)out_size >= BSV + 2*NBR);
    float* hf_out = write_state ? out + BSV        : nullptr;
    float* cf_out = write_state ? out + BSV + NBR  : nullptr;

    // 1. embed + counter reset
    embed_kernel<<<MROWS, 128>>>(x, emb);
    // 2. repack W_hh
    repack_kernel<<<(NCELL*GG*RR/4)/256, 256>>>(W_hh);
    // 3. q = xs @ Wq^T + bq          (S,B,D)
    mma_gemm<<<dim3(DD/128, MROWS/128, 1), 256, GEMM_SMEM>>>(
        xs, in_w, in_b, nullptr, qpre, DD, DD,
        0, 0, 0,
        8L*DD, DD, 1, 0, 0, 30);
    // 4. gates_ih = xs @ W_ih^T + (b_ih+b_hh)  -> ihp[t][n][b][g]
    mma_gemm<<<dim3(NCELL*GG/128, MROWS/128, 1), 256, GEMM_SMEM>>>(
        xs, W_ih, b_ih, b_hh, ihp, DD, DD,
        0, 0, 0,
        (long)NCELL*BB*GG, GG, 1, 0,
        (long)BB*GG, 11);
    // 5. recurrence (persistent, 128 CTAs)
    recurrence_kernel<<<NCELL*8, 512>>>(h0, c0, hf_out, cf_out);
    // 6. nout[n] = hall[n] @ W_np[n]^T + b_np[n]
    mma_gemm<<<dim3(DD/128, MROWS/128, NCELL), 256, GEMM_SMEM>>>(
        hall, W_np, b_np, nullptr, nout, RR, RR,
        (long)SS*BB*RR, (long)DD*RR, DD,
        8L*DD, DD, 1, (long)SS*BB*DD, 0, 30);
    // 7. kv = nout @ [Wk;Wv]^T + [bk;bv]   M=32768, Nc=1024
    mma_gemm<<<dim3(1024/128, (NCELL*MROWS)/128, 1), 256, GEMM_SMEM>>>(
        nout, in_w + (size_t)DD*DD, in_b + DD, nullptr, kv, DD, DD,
        0, 0, 0,
        8L*1024, 1024, 1, 0, 0, 30);
    // 8. attention
    attn_kernel<<<MROWS, 256>>>();
    // 9. op projection: yraw = att @ op_w^T + op_b
    mma_gemm<<<dim3(DD/128, MROWS/128, 1), 256, GEMM_SMEM>>>(
        att, op_w, op_b, nullptr, yraw, DD, DD,
        0, 0, 0,
        8L*DD, DD, 1, 0, 0, 30);
    // 10. residual + LN
    ln_kernel<<<MROWS, 256>>>(ln_g, ln_b);
    // 11. head: logits -> out (B,S,V)
    mma_gemm<<<dim3(VV/128, MROWS/128, 1), 256, GEMM_SMEM>>>(
        mixed, head_w, head_b, nullptr, out, DD, DD,
        0, 0, 0,
        (long)VV, (long)SS*VV, 1, 0, 0, 30);
}

// round 11
// speedup vs baseline: 1.5130x; 1.2033x over previous
#include <cuda_runtime.h>
#include <cstdint>

#define SS   256
#define BB   8
#define VV   32000
#define DD   512
#define NCELL 16
#define RR   512
#define GG   2048   // 4*R
#define HH   8
#define MROWS 2048  // S*B

// ---------------- scratch (__device__ globals; no allocation) ----------------
__device__ float g_xs   [(size_t)SS*BB*DD];            // raw embeddings (residual)
__device__ float g_xst  [(size_t)SS*BB*DD];            // tf32-rounded embeddings
__device__ float g_qpre [(size_t)SS*BB*DD];
__device__ float g_ihp  [(size_t)SS*NCELL*BB*GG];      // (S,N,B,G) 268 MB
__device__ float g_wp   [(size_t)NCELL*GG*RR];         // repacked W_hh
__device__ float g_hall [(size_t)NCELL*SS*BB*RR];      // tf32-rounded h history
__device__ float g_nout [(size_t)NCELL*SS*BB*DD];      // tf32-rounded (GEMM flag)
__device__ float g_kv   [(size_t)NCELL*SS*BB*1024];
__device__ float g_att  [(size_t)SS*BB*DD];            // tf32-rounded
__device__ float g_yraw [(size_t)SS*BB*DD];
__device__ float g_mixed[(size_t)SS*BB*DD];            // tf32-rounded
__device__ float g_hbuf [2*NCELL*BB*RR];               // [parity][n][b][k]
__device__ volatile int g_cnt[NCELL];
// tf32-rounded weight copies
__device__ float g_inwt [(size_t)3*DD*DD];
__device__ float g_wiht [(size_t)NCELL*GG*DD];
__device__ float g_wnpt [(size_t)NCELL*DD*RR];
__device__ float g_opwt [(size_t)DD*DD];
__device__ float g_hdwt [(size_t)VV*DD];

// ---------------- helpers ----------------
__device__ __forceinline__ float tf32r(float x) {
    uint32_t o;
    asm("cvt.rna.tf32.f32 %0, %1;" : "=r"(o) : "f"(x));
    return __uint_as_float(o);
}
__device__ __forceinline__ void mma8(float* c, const uint32_t* a, const uint32_t* b) {
    asm volatile(
        "mma.sync.aligned.m16n8k8.row.col.f32.tf32.tf32.f32 "
        "{%0,%1,%2,%3}, {%4,%5,%6,%7}, {%8,%9}, {%0,%1,%2,%3};\n"
        : "+f"(c[0]), "+f"(c[1]), "+f"(c[2]), "+f"(c[3])
        : "r"(a[0]), "r"(a[1]), "r"(a[2]), "r"(a[3]), "r"(b[0]), "r"(b[1]));
}
__device__ __forceinline__ void fma2(unsigned long long& d, unsigned long long a, unsigned long long b) {
    asm("fma.rn.f32x2 %0, %1, %2, %0;" : "+l"(d) : "l"(a), "l"(b));
}
__device__ __forceinline__ unsigned long long pk2(float lo, float hi) {
    unsigned long long r;
    asm("mov.b64 %0, {%1,%2};" : "=l"(r) : "f"(lo), "f"(hi));
    return r;
}
__device__ __forceinline__ float upk_sum(unsigned long long v) {
    float lo, hi;
    asm("mov.b64 {%0,%1}, %2;" : "=f"(lo), "=f"(hi) : "l"(v));
    return lo + hi;
}
__device__ __forceinline__ void cp16(uint32_t saddr, const void* gaddr) {
    asm volatile("cp.async.ca.shared.global [%0], [%1], 16;\n" :: "r"(saddr), "l"(gaddr));
}
#define CP_COMMIT() asm volatile("cp.async.commit_group;\n")
#define CP_WAIT1()  asm volatile("cp.async.wait_group 1;\n")

// ---------------- tf32 convert (elementwise, float4) ----------------
__global__ __launch_bounds__(256)
void conv_kernel(const float* __restrict__ src, float* __restrict__ dst)
{
    size_t i = ((size_t)blockIdx.x*256 + threadIdx.x)*4;
    float4 v = *(const float4*)(src + i);
    v.x = tf32r(v.x); v.y = tf32r(v.y); v.z = tf32r(v.z); v.w = tf32r(v.w);
    *(float4*)(dst + i) = v;
}

// ---------------- embed + counter reset ----------------
__global__ __launch_bounds__(128)
void embed_kernel(const int* __restrict__ x, const float* __restrict__ emb)
{
    int tb = blockIdx.x;               // t*8+b
    int t = tb >> 3, b = tb & 7;
    if (tb == 0 && threadIdx.x < NCELL) g_cnt[threadIdx.x] = 0;
    int idx = x[b*SS + t];
    float4 v = ((const float4*)(emb + (size_t)idx*DD))[threadIdx.x];
    ((float4*)(g_xs + (size_t)tb*DD))[threadIdx.x] = v;
    v.x = tf32r(v.x); v.y = tf32r(v.y); v.z = tf32r(v.z); v.w = tf32r(v.w);
    ((float4*)(g_xst + (size_t)tb*DD))[threadIdx.x] = v;
}

// ---------------- W_hh repack: Wp[n][c][k4][lr][0..3] ----------------
__global__ __launch_bounds__(256)
void repack_kernel(const float* __restrict__ whh)
{
    int o = blockIdx.x*256 + threadIdx.x;     // float4 index
    int lr = o & 255;
    int k4 = (o >> 8) & 127;
    int c  = (o >> 15) & 7;
    int n  = o >> 18;
    int grow = (lr >> 6)*512 + c*64 + (lr & 63);
    float4 v = *(const float4*)(whh + ((size_t)n*GG + grow)*RR + k4*4);
    ((float4*)g_wp)[o] = v;
}

// ---------------- TF32 GEMM, cp.async 3-stage, 2 CTAs/SM ----------------
// Inputs MUST be pre-rounded to tf32. CTA tile 128x128, BK=32.
// SMEM per operand per stage: 128 rows x 36 floats ([m][k] stride 36).
#define ST_F   (128*36)      // floats per operand per stage
#define NSTG   3
__global__ __launch_bounds__(256, 2)
void mma_gemm(const float* __restrict__ A, const float* __restrict__ Bw,
              const float* __restrict__ bias1, const float* __restrict__ bias2,
              float* __restrict__ C, int K, long lda,
              long sAz, long sBz, long sBiasZ,
              long sCt, long sCb, long sCc, long sCz,
              long sCcBlk, int blkLog, int roundOut)
{
    extern __shared__ float smem[];
    float* Abuf = smem;                 // [3][128][36]
    float* Bbuf = smem + NSTG*ST_F;

    int tid  = threadIdx.x;
    int lane = tid & 31;
    int warp = tid >> 5;
    int wm = warp & 1;
    int wn = warp >> 1;
    int bx = blockIdx.x, by = blockIdx.y, bz = blockIdx.z;

    const float* Ab = A  + (size_t)bz * sAz;
    const float* Bb = Bw + (size_t)bz * sBz;
    float*       Cb = C  + (size_t)bz * sCz;

    // load mapping: 256 threads, each 4 x 16B per operand per stage
    int lm   = tid >> 1;           // 0..127
    int half = tid & 1;            // k offset half*16
    const float* ag = Ab + (size_t)(by*128 + lm)*lda + half*16;
    const float* bg = Bb + (size_t)(bx*128 + lm)*K   + half*16;
    uint32_t sA = (uint32_t)__cvta_generic_to_shared(Abuf) + (uint32_t)(lm*36 + half*16)*4u;
    uint32_t sB = (uint32_t)__cvta_generic_to_shared(Bbuf) + (uint32_t)(lm*36 + half*16)*4u;

    int qr = lane >> 2;
    int qc = lane & 3;
    int amBase = wm*64;
    int bnBase = wn*32;

    float acc[4][4][4];
    #pragma unroll
    for (int i = 0; i < 4; i++)
        #pragma unroll
        for (int j = 0; j < 4; j++)
            #pragma unroll
            for (int e = 0; e < 4; e++) acc[i][j][e] = 0.f;

    int KT = K >> 5;

    // prologue: stages 0,1
    #pragma unroll
    for (int p = 0; p < NSTG-1; p++) {
        uint32_t aoff = sA + p*ST_F*4;
        uint32_t boff = sB + p*ST_F*4;
        #pragma unroll
        for (int q = 0; q < 4; q++) {
            cp16(aoff + q*16, ag + p*32 + q*4);
            cp16(boff + q*16, bg + p*32 + q*4);
        }
        CP_COMMIT();
    }

    for (int kt = 0; kt < KT; kt++) {
        CP_WAIT1();
        __syncthreads();
        // prefetch stage kt+2
        if (kt + NSTG-1 < KT) {
            int stg = (kt + NSTG-1) % NSTG;
            uint32_t aoff = sA + stg*ST_F*4;
            uint32_t boff = sB + stg*ST_F*4;
            #pragma unroll
            for (int q = 0; q < 4; q++) {
                cp16(aoff + q*16, ag + (kt+NSTG-1)*32 + q*4);
                cp16(boff + q*16, bg + (kt+NSTG-1)*32 + q*4);
            }
        }
        CP_COMMIT();

        const float* As = Abuf + (kt % NSTG)*ST_F;
        const float* Bs = Bbuf + (kt % NSTG)*ST_F;
        #pragma unroll
        for (int s = 0; s < 4; s++) {
            int k0 = s*8;
            uint32_t af[4][4], bf[4][2];
            #pragma unroll
            for (int i = 0; i < 4; i++) {
                int m = amBase + i*16 + qr;
                af[i][0] = __float_as_uint(As[m*36      + k0 + qc]);
                af[i][1] = __float_as_uint(As[(m+8)*36  + k0 + qc]);
                af[i][2] = __float_as_uint(As[m*36      + k0 + qc + 4]);
                af[i][3] = __float_as_uint(As[(m+8)*36  + k0 + qc + 4]);
            }
            #pragma unroll
            for (int j = 0; j < 4; j++) {
                int n = bnBase + j*8 + qr;
                bf[j][0] = __float_as_uint(Bs[n*36 + k0 + qc]);
                bf[j][1] = __float_as_uint(Bs[n*36 + k0 + qc + 4]);
            }
            #pragma unroll
            for (int i = 0; i < 4; i++)
                #pragma unroll
                for (int j = 0; j < 4; j++)
                    mma8(acc[i][j], af[i], bf[j]);
        }
    }

    long msk = (1L << blkLog) - 1;
    #pragma unroll
    for (int i = 0; i < 4; i++) {
        int r0 = by*128 + amBase + i*16 + qr;
        long ro  = (long)(r0 >> 3)*sCt + (long)(r0 & 7)*sCb;
        long ro8 = (long)((r0+8) >> 3)*sCt + (long)((r0+8) & 7)*sCb;
        #pragma unroll
        for (int j = 0; j < 4; j++) {
            int c0 = bx*128 + bnBase + j*8 + 2*qc;
            float b0v = 0.f, b1v = 0.f;
            if (bias1) { b0v  = bias1[(long)bz*sBiasZ + c0];
                         b1v  = bias1[(long)bz*sBiasZ + c0 + 1]; }
            if (bias2) { b0v += bias2[c0]; b1v += bias2[c0 + 1]; }
            long cc0 = (long)(c0 >> blkLog)*sCcBlk + (long)(c0 & msk)*sCc;
            long cc1 = (long)((c0+1) >> blkLog)*sCcBlk + (long)((c0+1) & msk)*sCc;
            float v00 = acc[i][j][0] + b0v, v01 = acc[i][j][1] + b1v;
            float v10 = acc[i][j][2] + b0v, v11 = acc[i][j][3] + b1v;
            if (roundOut) { v00 = tf32r(v00); v01 = tf32r(v01);
                            v10 = tf32r(v10); v11 = tf32r(v11); }
            Cb[ro  + cc0] = v00;
            Cb[ro  + cc1] = v01;
            Cb[ro8 + cc0] = v10;
            Cb[ro8 + cc1] = v11;
        }
    }
}

// ---------------- persistent LSTM recurrence (f32x2 FMA) ----------------
// grid 128: blockIdx = cell*8 + chunk.  512 threads.
__global__ __launch_bounds__(512)
void recurrence_kernel(const float* __restrict__ h0, const float* __restrict__ c0,
                       float* hf_out, float* cf_out)
{
    __shared__ float h_s[BB*RR];        // [b][k] flat, 16 KB
    __shared__ float g_sm[256][9];      // padded gate exchange

    int tid  = threadIdx.x;
    int cell = blockIdx.x >> 3;
    int cb   = blockIdx.x & 7;

    int lr = tid & 255;
    int bh = tid >> 8;                  // 0/1 -> batches bh*4..bh*4+3
    int grow = (lr >> 6)*512 + cb*64 + (lr & 63);

    int ub = tid >> 6;                  // 0..7
    int uj = tid & 63;

    // init h_s [b][k]  (h0 layout (cell,b,r) == same flat order)
    {
        const float4* src = (const float4*)(h0 + (size_t)cell*BB*RR) + tid*2;
        float4* dst = (float4*)h_s + tid*2;
        dst[0] = src[0]; dst[1] = src[1];
    }
    float c_reg = c0[((size_t)cell*BB + ub)*RR + cb*64 + uj];
    __syncthreads();

    const ulonglong2* wbase = (const ulonglong2*)g_wp + (size_t)(cell*8 + cb)*128*256;

    for (int t = 0; t < SS; t++) {
        // gates = W_hh@h + precomputed (ih+bias); ihp layout [t][n][b][g]
        const float* ib = g_ihp + (((size_t)t*NCELL + cell)*BB + bh*4)*GG + grow;
        unsigned long long a0 = pk2(ib[0],    0.f);
        unsigned long long a1 = pk2(ib[GG],   0.f);
        unsigned long long a2 = pk2(ib[2*GG], 0.f);
        unsigned long long a3 = pk2(ib[3*GG], 0.f);
        #pragma unroll 4
        for (int k4 = 0; k4 < 128; k4++) {
            ulonglong2 w2 = __ldg(&wbase[k4*256 + lr]);   // (wk0,wk1),(wk2,wk3)
            const ulonglong2* hp = (const ulonglong2*)&h_s[(bh*4)*RR + k4*4];
            ulonglong2 h0p = hp[0];                       // batch bh*4+0
            ulonglong2 h1p = *(const ulonglong2*)&h_s[(bh*4+1)*RR + k4*4];
            ulonglong2 h2p = *(const ulonglong2*)&h_s[(bh*4+2)*RR + k4*4];
            ulonglong2 h3p = *(const ulonglong2*)&h_s[(bh*4+3)*RR + k4*4];
            fma2(a0, w2.x, h0p.x); fma2(a0, w2.y, h0p.y);
            fma2(a1, w2.x, h1p.x); fma2(a1, w2.y, h1p.y);
            fma2(a2, w2.x, h2p.x); fma2(a2, w2.y, h2p.y);
            fma2(a3, w2.x, h3p.x); fma2(a3, w2.y, h3p.y);
        }
        g_sm[lr][bh*4+0] = upk_sum(a0);
        g_sm[lr][bh*4+1] = upk_sum(a1);
        g_sm[lr][bh*4+2] = upk_sum(a2);
        g_sm[lr][bh*4+3] = upk_sum(a3);
        __syncthreads();

        float gi = g_sm[      uj][ub];
        float gf = g_sm[ 64 + uj][ub];
        float gg = g_sm[128 + uj][ub];
        float go = g_sm[192 + uj][ub];
        float si = 1.f/(1.f + expf(-gi));
        float sf = 1.f/(1.f + expf(-gf));
        float so = 1.f/(1.f + expf(-go));
        float cn = sf*c_reg + si*tanhf(gg);
        float hn = so*tanhf(cn);
        c_reg = cn;

        g_hall[(((size_t)cell*SS + t)*BB + ub)*RR + cb*64 + uj] = tf32r(hn);
        int par = (t + 1) & 1;
        // hbuf layout [parity][n][b][k]
        g_hbuf[((size_t)(par*NCELL + cell)*BB + ub)*RR + cb*64 + uj] = hn;
        if (t == SS-1) {
            if (hf_out) hf_out[((size_t)cell*BB + ub)*RR + cb*64 + uj] = hn;
            if (cf_out) cf_out[((size_t)cell*BB + ub)*RR + cb*64 + uj] = cn;
        }

        __threadfence();
        __syncthreads();
        if (tid == 0) {
            atomicAdd((int*)&g_cnt[cell], 1);
            int target = 8*(t+1);
            while (g_cnt[cell] < target) { }
        }
        __syncthreads();

        {
            const float* src = g_hbuf + (size_t)(par*NCELL + cell)*BB*RR + tid*8;
            float4 p0 = __ldcg((const float4*)src);
            float4 p1 = __ldcg((const float4*)(src + 4));
            *(float4*)&h_s[tid*8]     = p0;
            *(float4*)&h_s[tid*8 + 4] = p1;
        }
        __syncthreads();
    }
}

// ---------------- attention (q,k,v -> att) ----------------
__global__ __launch_bounds__(256)
void attn_kernel()
{
    int tb = blockIdx.x;                // t*8+b
    int t = tb >> 3, b = tb & 7;
    int h = threadIdx.x >> 5;
    int lane = threadIdx.x & 31;

    const float* qrow = g_qpre + (size_t)tb*DD + h*64;
    float q0 = qrow[2*lane], q1 = qrow[2*lane + 1];

    float s[NCELL];
    #pragma unroll
    for (int n = 0; n < NCELL; n++) {
        const float* kp = g_kv + (((size_t)n*SS + t)*BB + b)*1024 + h*64;
        float2 k2 = *(const float2*)(kp + 2*lane);
        float p = q0*k2.x + q1*k2.y;
        #pragma unroll
        for (int o = 16; o > 0; o >>= 1) p += __shfl_xor_sync(0xffffffffu, p, o);
        s[n] = p * 0.125f;
    }
    float m = s[0];
    #pragma unroll
    for (int n = 1; n < NCELL; n++) m = fmaxf(m, s[n]);
    float sum = 0.f;
    #pragma unroll
    for (int n = 0; n < NCELL; n++) { s[n] = expf(s[n] - m); sum += s[n]; }
    float inv = 1.f/sum;

    float a0 = 0.f, a1 = 0.f;
    #pragma unroll
    for (int n = 0; n < NCELL; n++) {
        const float* vp = g_kv + (((size_t)n*SS + t)*BB + b)*1024 + 512 + h*64;
        float2 v2 = *(const float2*)(vp + 2*lane);
        float w = s[n]*inv;
        a0 += w*v2.x; a1 += w*v2.y;
    }
    float* ap = g_att + (size_t)tb*DD + h*64;
    ap[2*lane]     = tf32r(a0);
    ap[2*lane + 1] = tf32r(a1);
}

// ---------------- residual + layernorm ----------------
__global__ __launch_bounds__(256)
void ln_kernel(const float* __restrict__ lng, const float* __restrict__ lnb)
{
    __shared__ float red[8];
    int tb = blockIdx.x;
    int tid = threadIdx.x;
    const float* yp = g_yraw + (size_t)tb*DD;
    const float* xp = g_xs   + (size_t)tb*DD;
    float y0 = yp[2*tid]   + xp[2*tid];
    float y1 = yp[2*tid+1] + xp[2*tid+1];

    float v = y0 + y1;
    #pragma unroll
    for (int o = 16; o > 0; o >>= 1) v += __shfl_xor_sync(0xffffffffu, v, o);
    if ((tid & 31) == 0) red[tid >> 5] = v;
    __syncthreads();
    float r = (tid < 8) ? red[tid] : 0.f;
    if (tid < 32) {
        #pragma unroll
        for (int o = 4; o > 0; o >>= 1) r += __shfl_xor_sync(0xffffffffu, r, o);
        if (tid == 0) red[0] = r;
    }
    __syncthreads();
    float mu = red[0] * (1.f/512.f);
    __syncthreads();

    float d0 = y0 - mu, d1 = y1 - mu;
    float sq = d0*d0 + d1*d1;
    #pragma unroll
    for (int o = 16; o > 0; o >>= 1) sq += __shfl_xor_sync(0xffffffffu, sq, o);
    if ((tid & 31) == 0) red[tid >> 5] = sq;
    __syncthreads();
    float r2 = (tid < 8) ? red[tid] : 0.f;
    if (tid < 32) {
        #pragma unroll
        for (int o = 4; o > 0; o >>= 1) r2 += __shfl_xor_sync(0xffffffffu, r2, o);
        if (tid == 0) red[0] = r2;
    }
    __syncthreads();
    float rstd = rsqrtf(red[0] * (1.f/512.f) + 1e-5f);

    float* mp = g_mixed + (size_t)tb*DD;
    mp[2*tid]   = tf32r(d0*rstd*lng[2*tid]   + lnb[2*tid]);
    mp[2*tid+1] = tf32r(d1*rstd*lng[2*tid+1] + lnb[2*tid+1]);
}

// ---------------- host launcher ----------------
extern "C" void kernel_launch(void* const* d_in, const int* in_sizes, int n_in,
                              void* d_out, int out_size)
{
    const int*   x      = (const int*)  d_in[0];
    const float* h0     = (const float*)d_in[1];
    const float* c0     = (const float*)d_in[2];
    const float* emb    = (const float*)d_in[3];
    const float* W_ih   = (const float*)d_in[4];
    const float* b_ih   = (const float*)d_in[5];
    const float* W_hh   = (const float*)d_in[6];
    const float* b_hh   = (const float*)d_in[7];
    const float* W_np   = (const float*)d_in[8];
    const float* b_np   = (const float*)d_in[9];
    const float* in_w   = (const float*)d_in[10];
    const float* in_b   = (const float*)d_in[11];
    const float* op_w   = (const float*)d_in[12];
    const float* op_b   = (const float*)d_in[13];
    const float* ln_g   = (const float*)d_in[14];
    const float* ln_b   = (const float*)d_in[15];
    const float* head_w = (const float*)d_in[16];
    const float* head_b = (const float*)d_in[17];
    float* out = (float*)d_out;

    float *xst, *qpre, *ihp, *hall, *nout, *kv, *att, *yraw, *mixed;
    float *inwt, *wiht, *wnpt, *opwt, *hdwt;
    cudaGetSymbolAddress((void**)&xst,   g_xst);
    cudaGetSymbolAddress((void**)&qpre,  g_qpre);
    cudaGetSymbolAddress((void**)&ihp,   g_ihp);
    cudaGetSymbolAddress((void**)&hall,  g_hall);
    cudaGetSymbolAddress((void**)&nout,  g_nout);
    cudaGetSymbolAddress((void**)&kv,    g_kv);
    cudaGetSymbolAddress((void**)&att,   g_att);
    cudaGetSymbolAddress((void**)&yraw,  g_yraw);
    cudaGetSymbolAddress((void**)&mixed, g_mixed);
    cudaGetSymbolAddress((void**)&inwt,  g_inwt);
    cudaGetSymbolAddress((void**)&wiht,  g_wiht);
    cudaGetSymbolAddress((void**)&wnpt,  g_wnpt);
    cudaGetSymbolAddress((void**)&opwt,  g_opwt);
    cudaGetSymbolAddress((void**)&hdwt,  g_hdwt);

    const int GEMM_SMEM = 2*NSTG*ST_F*(int)sizeof(float);   // 110592 B
    static int smem_set = 0;
    if (!smem_set) {
        cudaFuncSetAttribute(mma_gemm, cudaFuncAttributeMaxDynamicSharedMemorySize, GEMM_SMEM);
        smem_set = 1;
    }

    const long BSV = (long)BB*SS*VV;
    const long NBR = (long)NCELL*BB*RR;
    bool write_state = ((long)out_size >= BSV + 2*NBR);
    float* hf_out = write_state ? out + BSV        : nullptr;
    float* cf_out = write_state ? out + BSV + NBR  : nullptr;

    // 0. weight tf32 conversions (one-shot cheap)
    conv_kernel<<<  768, 256>>>(in_w,   inwt);
    conv_kernel<<<16384, 256>>>(W_ih,   wiht);
    conv_kernel<<< 4096, 256>>>(W_np,   wnpt);
    conv_kernel<<<  256, 256>>>(op_w,   opwt);
    conv_kernel<<<16000, 256>>>(head_w, hdwt);
    // 1. embed (+xst rounded) + counter reset
    embed_kernel<<<MROWS, 128>>>(x, emb);
    // 2. repack W_hh
    repack_kernel<<<(NCELL*GG*RR/4)/256, 256>>>(W_hh);
    // 3. q = xs @ Wq^T + bq
    mma_gemm<<<dim3(DD/128, MROWS/128, 1), 256, GEMM_SMEM>>>(
        xst, inwt, in_b, nullptr, qpre, DD, DD,
        0, 0, 0,
        8L*DD, DD, 1, 0, 0, 30, 0);
    // 4. gates_ih = xs @ W_ih^T + (b_ih+b_hh)  -> ihp[t][n][b][g]
    mma_gemm<<<dim3(NCELL*GG/128, MROWS/128, 1), 256, GEMM_SMEM>>>(
        xst, wiht, b_ih, b_hh, ihp, DD, DD,
        0, 0, 0,
        (long)NCELL*BB*GG, GG, 1, 0,
        (long)BB*GG, 11, 0);
    // 5. recurrence (persistent, 128 CTAs)
    recurrence_kernel<<<NCELL*8, 512>>>(h0, c0, hf_out, cf_out);
    // 6. nout[n] = hall[n] @ W_np[n]^T + b_np[n]   (round output: feeds kv GEMM)
    mma_gemm<<<dim3(DD/128, MROWS/128, NCELL), 256, GEMM_SMEM>>>(
        hall, wnpt, b_np, nullptr, nout, RR, RR,
        (long)SS*BB*RR, (long)DD*RR, DD,
        8L*DD, DD, 1, (long)SS*BB*DD, 0, 30, 1);
    // 7. kv = nout @ [Wk;Wv]^T + [bk;bv]
    mma_gemm<<<dim3(1024/128, (NCELL*MROWS)/128, 1), 256, GEMM_SMEM>>>(
        nout, inwt + (size_t)DD*DD, in_b + DD, nullptr, kv, DD, DD,
        0, 0, 0,
        8L*1024, 1024, 1, 0, 0, 30, 0);
    // 8. attention (writes att rounded)
    attn_kernel<<<MROWS, 256>>>();
    // 9. op projection
    mma_gemm<<<dim3(DD/128, MROWS/128, 1), 256, GEMM_SMEM>>>(
        att, opwt, op_b, nullptr, yraw, DD, DD,
        0, 0, 0,
        8L*DD, DD, 1, 0, 0, 30, 0);
    // 10. residual + LN (writes mixed rounded)
    ln_kernel<<<MROWS, 256>>>(ln_g, ln_b);
    // 11. head: logits -> out (B,S,V)
    mma_gemm<<<dim3(VV/128, MROWS/128, 1), 256, GEMM_SMEM>>>(
        mixed, hdwt, head_b, nullptr, out, DD, DD,
        0, 0, 0,
        (long)VV, (long)SS*VV, 1, 0, 0, 30, 0);
}

// round 12
// speedup vs baseline: 1.8129x; 1.1982x over previous
#include <cuda_runtime.h>
#include <cuda_fp16.h>
#include <cstdint>

#define SS   256
#define BB   8
#define VV   32000
#define DD   512
#define NCELL 16
#define RR   512
#define GG   2048   // 4*R
#define HH   8
#define MROWS 2048  // S*B

// ---------------- scratch (__device__ globals; no allocation) ----------------
__device__ float  g_xs   [(size_t)SS*BB*DD];           // raw embeddings (residual)
__device__ __half g_xsh  [(size_t)SS*BB*DD];           // fp16 embeddings
__device__ float  g_qpre [(size_t)SS*BB*DD];
__device__ float  g_ihp  [(size_t)SS*NCELL*BB*GG];     // (S,N,B,G) fp32
__device__ float  g_wp   [(size_t)NCELL*GG*RR];        // repacked W_hh fp32
__device__ __half g_hallh[(size_t)NCELL*SS*BB*RR];     // fp16 h history
__device__ __half g_nouth[(size_t)NCELL*SS*BB*DD];     // fp16 nout
__device__ float  g_kv   [(size_t)NCELL*SS*BB*1024];
__device__ __half g_atth [(size_t)SS*BB*DD];
__device__ float  g_yraw [(size_t)SS*BB*DD];
__device__ __half g_mixedh[(size_t)SS*BB*DD];
__device__ float  g_hbuf [2*NCELL*BB*RR];              // [parity][n][b][k]
__device__ volatile int g_cnt[NCELL];
// fp16 weight copies
__device__ __half g_inwh [(size_t)3*DD*DD];
__device__ __half g_wihh [(size_t)NCELL*GG*DD];
__device__ __half g_wnph [(size_t)NCELL*DD*RR];
__device__ __half g_opwh [(size_t)DD*DD];
__device__ __half g_hdwh [(size_t)VV*DD];

// ---------------- helpers ----------------
__device__ __forceinline__ void mma16(float* c, const uint32_t* a, const uint32_t* b) {
    asm volatile(
        "mma.sync.aligned.m16n8k16.row.col.f32.f16.f16.f32 "
        "{%0,%1,%2,%3}, {%4,%5,%6,%7}, {%8,%9}, {%0,%1,%2,%3};\n"
        : "+f"(c[0]), "+f"(c[1]), "+f"(c[2]), "+f"(c[3])
        : "r"(a[0]), "r"(a[1]), "r"(a[2]), "r"(a[3]), "r"(b[0]), "r"(b[1]));
}
__device__ __forceinline__ void ldsm4(uint32_t& r0, uint32_t& r1, uint32_t& r2, uint32_t& r3,
                                      uint32_t addr) {
    asm volatile("ldmatrix.sync.aligned.m8n8.x4.shared.b16 {%0,%1,%2,%3}, [%4];"
                 : "=r"(r0), "=r"(r1), "=r"(r2), "=r"(r3) : "r"(addr));
}
__device__ __forceinline__ void fma2(unsigned long long& d, unsigned long long a, unsigned long long b) {
    asm("fma.rn.f32x2 %0, %1, %2, %0;" : "+l"(d) : "l"(a), "l"(b));
}
__device__ __forceinline__ unsigned long long pk2(float lo, float hi) {
    unsigned long long r;
    asm("mov.b64 %0, {%1,%2};" : "=l"(r) : "f"(lo), "f"(hi));
    return r;
}
__device__ __forceinline__ float upk_sum(unsigned long long v) {
    float lo, hi;
    asm("mov.b64 {%0,%1}, %2;" : "=f"(lo), "=f"(hi) : "l"(v));
    return lo + hi;
}
__device__ __forceinline__ void cp16(uint32_t saddr, const void* gaddr) {
    asm volatile("cp.async.ca.shared.global [%0], [%1], 16;\n" :: "r"(saddr), "l"(gaddr));
}
#define CP_COMMIT() asm volatile("cp.async.commit_group;\n")
#define CP_WAIT1()  asm volatile("cp.async.wait_group 1;\n")

// ---------------- f32 -> f16 convert (4 elems/thread) ----------------
__global__ __launch_bounds__(256)
void convh_kernel(const float* __restrict__ src, __half* __restrict__ dst)
{
    size_t i = ((size_t)blockIdx.x*256 + threadIdx.x)*4;
    float4 v = *(const float4*)(src + i);
    __half2* d = (__half2*)(dst + i);
    d[0] = __floats2half2_rn(v.x, v.y);
    d[1] = __floats2half2_rn(v.z, v.w);
}

// ---------------- embed + counter reset ----------------
__global__ __launch_bounds__(128)
void embed_kernel(const int* __restrict__ x, const float* __restrict__ emb)
{
    int tb = blockIdx.x;               // t*8+b
    int t = tb >> 3, b = tb & 7;
    if (tb == 0 && threadIdx.x < NCELL) g_cnt[threadIdx.x] = 0;
    int idx = x[b*SS + t];
    float4 v = ((const float4*)(emb + (size_t)idx*DD))[threadIdx.x];
    ((float4*)(g_xs + (size_t)tb*DD))[threadIdx.x] = v;
    __half2* d = (__half2*)(g_xsh + (size_t)tb*DD) + threadIdx.x*2;
    d[0] = __floats2half2_rn(v.x, v.y);
    d[1] = __floats2half2_rn(v.z, v.w);
}

// ---------------- W_hh repack: Wp[n][c][k4][lr][0..3] ----------------
__global__ __launch_bounds__(256)
void repack_kernel(const float* __restrict__ whh)
{
    int o = blockIdx.x*256 + threadIdx.x;     // float4 index
    int lr = o & 255;
    int k4 = (o >> 8) & 127;
    int c  = (o >> 15) & 7;
    int n  = o >> 18;
    int grow = (lr >> 6)*512 + c*64 + (lr & 63);
    float4 v = *(const float4*)(whh + ((size_t)n*GG + grow)*RR + k4*4);
    ((float4*)g_wp)[o] = v;
}

// ---------------- FP16 tensor-core GEMM: C = A @ B^T + bias ----------------
// A,B fp16, K-contig rows. CTA tile 128x128, BK=64, 3-stage cp.async, 2 CTA/SM.
// SMEM rows padded to 72 halves (LDSM conflict-free).
// C elem (m,c): (m>>3)*sCt + (m&7)*sCb + (c>>blkLog)*sCcBlk + (c&mask)*sCc (+z*sCz)
#define ST_H   (128*72)      // halves per operand per stage
#define NSTG   3
__global__ __launch_bounds__(256, 2)
void mma_gemm(const __half* __restrict__ A, const __half* __restrict__ Bw,
              const float* __restrict__ bias1, const float* __restrict__ bias2,
              void* __restrict__ Cv, int K, long lda,
              long sAz, long sBz, long sBiasZ,
              long sCt, long sCb, long sCc, long sCz,
              long sCcBlk, int blkLog, int outHalf)
{
    extern __shared__ __half smem[];
    __half* Abuf = smem;                 // [3][128][72]
    __half* Bbuf = smem + NSTG*ST_H;

    int tid  = threadIdx.x;
    int lane = tid & 31;
    int warp = tid >> 5;
    int wm = warp & 1;
    int wn = warp >> 1;
    int bx = blockIdx.x, by = blockIdx.y, bz = blockIdx.z;

    const __half* Ab = A  + (size_t)bz * sAz;
    const __half* Bb = Bw + (size_t)bz * sBz;

    // load mapping: 256 threads; each 4 x 16B chunks per operand per stage
    int lm   = tid >> 1;           // 0..127 row
    int half = tid & 1;            // 0/1 -> k offset half*32 halves
    const __half* ag = Ab + (size_t)(by*128 + lm)*lda + half*32;
    const __half* bg = Bb + (size_t)(bx*128 + lm)*K   + half*32;
    uint32_t sA = (uint32_t)__cvta_generic_to_shared(Abuf) + (uint32_t)(lm*72 + half*32)*2u;
    uint32_t sB = (uint32_t)__cvta_generic_to_shared(Bbuf) + (uint32_t)(lm*72 + half*32)*2u;

    int qr = lane >> 2;
    int qc = lane & 3;
    int amBase = wm*64;
    int bnBase = wn*32;

    // fragment smem addresses (stage 0)
    uint32_t aFragBase = (uint32_t)__cvta_generic_to_shared(Abuf)
        + (uint32_t)((amBase + (lane & 15))*72 + (lane >> 4)*8)*2u;
    uint32_t bFragBase = (uint32_t)__cvta_generic_to_shared(Bbuf)
        + (uint32_t)((bnBase + (lane & 7) + ((lane >> 4) << 3))*72 + (lane & 8))*2u;

    float acc[4][4][4];
    #pragma unroll
    for (int i = 0; i < 4; i++)
        #pragma unroll
        for (int j = 0; j < 4; j++)
            #pragma unroll
            for (int e = 0; e < 4; e++) acc[i][j][e] = 0.f;

    int KT = K >> 6;                 // BK=64

    // prologue: stages 0,1
    #pragma unroll
    for (int p = 0; p < NSTG-1; p++) {
        uint32_t aoff = sA + p*ST_H*2;
        uint32_t boff = sB + p*ST_H*2;
        #pragma unroll
        for (int q = 0; q < 4; q++) {
            cp16(aoff + q*16, ag + p*64 + q*8);
            cp16(boff + q*16, bg + p*64 + q*8);
        }
        CP_COMMIT();
    }

    for (int kt = 0; kt < KT; kt++) {
        CP_WAIT1();
        __syncthreads();
        if (kt + NSTG-1 < KT) {
            int stg = (kt + NSTG-1) % NSTG;
            uint32_t aoff = sA + stg*ST_H*2;
            uint32_t boff = sB + stg*ST_H*2;
            #pragma unroll
            for (int q = 0; q < 4; q++) {
                cp16(aoff + q*16, ag + (kt+NSTG-1)*64 + q*8);
                cp16(boff + q*16, bg + (kt+NSTG-1)*64 + q*8);
            }
        }
        CP_COMMIT();

        uint32_t aS = aFragBase + (kt % NSTG)*ST_H*2;
        uint32_t bS = bFragBase + (kt % NSTG)*ST_H*2;
        #pragma unroll
        for (int ks = 0; ks < 4; ks++) {
            uint32_t k0b = ks*16*2;   // byte offset of k0
            uint32_t af[4][4], bf[4][2];
            #pragma unroll
            for (int i = 0; i < 4; i++)
                ldsm4(af[i][0], af[i][1], af[i][2], af[i][3],
                      aS + (uint32_t)(i*16*72)*2u + k0b);
            #pragma unroll
            for (int jp = 0; jp < 2; jp++)
                ldsm4(bf[jp*2][0], bf[jp*2][1], bf[jp*2+1][0], bf[jp*2+1][1],
                      bS + (uint32_t)(jp*16*72)*2u + k0b);
            #pragma unroll
            for (int i = 0; i < 4; i++)
                #pragma unroll
                for (int j = 0; j < 4; j++)
                    mma16(acc[i][j], af[i], bf[j]);
        }
    }

    long msk = (1L << blkLog) - 1;
    #pragma unroll
    for (int i = 0; i < 4; i++) {
        int r0 = by*128 + amBase + i*16 + qr;
        long ro  = (long)(r0 >> 3)*sCt + (long)(r0 & 7)*sCb;
        long ro8 = (long)((r0+8) >> 3)*sCt + (long)((r0+8) & 7)*sCb;
        #pragma unroll
        for (int j = 0; j < 4; j++) {
            int c0 = bx*128 + bnBase + j*8 + 2*qc;
            float b0v = 0.f, b1v = 0.f;
            if (bias1) { b0v  = bias1[(long)bz*sBiasZ + c0];
                         b1v  = bias1[(long)bz*sBiasZ + c0 + 1]; }
            if (bias2) { b0v += bias2[c0]; b1v += bias2[c0 + 1]; }
            long cc0 = (long)(c0 >> blkLog)*sCcBlk + (long)(c0 & msk)*sCc;
            long cc1 = (long)((c0+1) >> blkLog)*sCcBlk + (long)((c0+1) & msk)*sCc;
            float v00 = acc[i][j][0] + b0v, v01 = acc[i][j][1] + b1v;
            float v10 = acc[i][j][2] + b0v, v11 = acc[i][j][3] + b1v;
            if (outHalf) {
                __half* Cb = (__half*)Cv + (size_t)bz * sCz;
                Cb[ro  + cc0] = __float2half(v00);
                Cb[ro  + cc1] = __float2half(v01);
                Cb[ro8 + cc0] = __float2half(v10);
                Cb[ro8 + cc1] = __float2half(v11);
            } else {
                float* Cb = (float*)Cv + (size_t)bz * sCz;
                Cb[ro  + cc0] = v00;
                Cb[ro  + cc1] = v01;
                Cb[ro8 + cc0] = v10;
                Cb[ro8 + cc1] = v11;
            }
        }
    }
}

// ---------------- persistent LSTM recurrence (f32x2 FMA) ----------------
__global__ __launch_bounds__(512)
void recurrence_kernel(const float* __restrict__ h0, const float* __restrict__ c0,
                       float* hf_out, float* cf_out)
{
    __shared__ float h_s[BB*RR];        // [b][k] flat
    __shared__ float g_sm[256][9];

    int tid  = threadIdx.x;
    int cell = blockIdx.x >> 3;
    int cb   = blockIdx.x & 7;

    int lr = tid & 255;
    int bh = tid >> 8;
    int grow = (lr >> 6)*512 + cb*64 + (lr & 63);

    int ub = tid >> 6;
    int uj = tid & 63;

    {
        const float4* src = (const float4*)(h0 + (size_t)cell*BB*RR) + tid*2;
        float4* dst = (float4*)h_s + tid*2;
        dst[0] = src[0]; dst[1] = src[1];
    }
    float c_reg = c0[((size_t)cell*BB + ub)*RR + cb*64 + uj];
    __syncthreads();

    const ulonglong2* wbase = (const ulonglong2*)g_wp + (size_t)(cell*8 + cb)*128*256;

    for (int t = 0; t < SS; t++) {
        const float* ib = g_ihp + (((size_t)t*NCELL + cell)*BB + bh*4)*GG + grow;
        unsigned long long a0 = pk2(ib[0],    0.f);
        unsigned long long a1 = pk2(ib[GG],   0.f);
        unsigned long long a2 = pk2(ib[2*GG], 0.f);
        unsigned long long a3 = pk2(ib[3*GG], 0.f);
        #pragma unroll 4
        for (int k4 = 0; k4 < 128; k4++) {
            ulonglong2 w2 = __ldg(&wbase[k4*256 + lr]);
            ulonglong2 h0p = *(const ulonglong2*)&h_s[(bh*4+0)*RR + k4*4];
            ulonglong2 h1p = *(const ulonglong2*)&h_s[(bh*4+1)*RR + k4*4];
            ulonglong2 h2p = *(const ulonglong2*)&h_s[(bh*4+2)*RR + k4*4];
            ulonglong2 h3p = *(const ulonglong2*)&h_s[(bh*4+3)*RR + k4*4];
            fma2(a0, w2.x, h0p.x); fma2(a0, w2.y, h0p.y);
            fma2(a1, w2.x, h1p.x); fma2(a1, w2.y, h1p.y);
            fma2(a2, w2.x, h2p.x); fma2(a2, w2.y, h2p.y);
            fma2(a3, w2.x, h3p.x); fma2(a3, w2.y, h3p.y);
        }
        g_sm[lr][bh*4+0] = upk_sum(a0);
        g_sm[lr][bh*4+1] = upk_sum(a1);
        g_sm[lr][bh*4+2] = upk_sum(a2);
        g_sm[lr][bh*4+3] = upk_sum(a3);
        __syncthreads();

        float gi = g_sm[      uj][ub];
        float gf = g_sm[ 64 + uj][ub];
        float gg = g_sm[128 + uj][ub];
        float go = g_sm[192 + uj][ub];
        float si = 1.f/(1.f + expf(-gi));
        float sf = 1.f/(1.f + expf(-gf));
        float so = 1.f/(1.f + expf(-go));
        float cn = sf*c_reg + si*tanhf(gg);
        float hn = so*tanhf(cn);
        c_reg = cn;

        g_hallh[(((size_t)cell*SS + t)*BB + ub)*RR + cb*64 + uj] = __float2half(hn);
        int par = (t + 1) & 1;
        g_hbuf[((size_t)(par*NCELL + cell)*BB + ub)*RR + cb*64 + uj] = hn;
        if (t == SS-1) {
            if (hf_out) hf_out[((size_t)cell*BB + ub)*RR + cb*64 + uj] = hn;
            if (cf_out) cf_out[((size_t)cell*BB + ub)*RR + cb*64 + uj] = cn;
        }

        __threadfence();
        __syncthreads();
        if (tid == 0) {
            atomicAdd((int*)&g_cnt[cell], 1);
            int target = 8*(t+1);
            while (g_cnt[cell] < target) { }
        }
        __syncthreads();

        {
            const float* src = g_hbuf + (size_t)(par*NCELL + cell)*BB*RR + tid*8;
            float4 p0 = __ldcg((const float4*)src);
            float4 p1 = __ldcg((const float4*)(src + 4));
            *(float4*)&h_s[tid*8]     = p0;
            *(float4*)&h_s[tid*8 + 4] = p1;
        }
        __syncthreads();
    }
}

// ---------------- attention (q,k,v -> att fp16) ----------------
__global__ __launch_bounds__(256)
void attn_kernel()
{
    int tb = blockIdx.x;                // t*8+b
    int t = tb >> 3, b = tb & 7;
    int h = threadIdx.x >> 5;
    int lane = threadIdx.x & 31;

    const float* qrow = g_qpre + (size_t)tb*DD + h*64;
    float q0 = qrow[2*lane], q1 = qrow[2*lane + 1];

    float s[NCELL];
    #pragma unroll
    for (int n = 0; n < NCELL; n++) {
        const float* kp = g_kv + (((size_t)n*SS + t)*BB + b)*1024 + h*64;
        float2 k2 = *(const float2*)(kp + 2*lane);
        float p = q0*k2.x + q1*k2.y;
        #pragma unroll
        for (int o = 16; o > 0; o >>= 1) p += __shfl_xor_sync(0xffffffffu, p, o);
        s[n] = p * 0.125f;
    }
    float m = s[0];
    #pragma unroll
    for (int n = 1; n < NCELL; n++) m = fmaxf(m, s[n]);
    float sum = 0.f;
    #pragma unroll
    for (int n = 0; n < NCELL; n++) { s[n] = expf(s[n] - m); sum += s[n]; }
    float inv = 1.f/sum;

    float a0 = 0.f, a1 = 0.f;
    #pragma unroll
    for (int n = 0; n < NCELL; n++) {
        const float* vp = g_kv + (((size_t)n*SS + t)*BB + b)*1024 + 512 + h*64;
        float2 v2 = *(const float2*)(vp + 2*lane);
        float w = s[n]*inv;
        a0 += w*v2.x; a1 += w*v2.y;
    }
    __half2* ap = (__half2*)(g_atth + (size_t)tb*DD + h*64) + lane;
    *ap = __floats2half2_rn(a0, a1);
}

// ---------------- residual + layernorm (-> fp16) ----------------
__global__ __launch_bounds__(256)
void ln_kernel(const float* __restrict__ lng, const float* __restrict__ lnb)
{
    __shared__ float red[8];
    int tb = blockIdx.x;
    int tid = threadIdx.x;
    const float* yp = g_yraw + (size_t)tb*DD;
    const float* xp = g_xs   + (size_t)tb*DD;
    float y0 = yp[2*tid]   + xp[2*tid];
    float y1 = yp[2*tid+1] + xp[2*tid+1];

    float v = y0 + y1;
    #pragma unroll
    for (int o = 16; o > 0; o >>= 1) v += __shfl_xor_sync(0xffffffffu, v, o);
    if ((tid & 31) == 0) red[tid >> 5] = v;
    __syncthreads();
    float r = (tid < 8) ? red[tid] : 0.f;
    if (tid < 32) {
        #pragma unroll
        for (int o = 4; o > 0; o >>= 1) r += __shfl_xor_sync(0xffffffffu, r, o);
        if (tid == 0) red[0] = r;
    }
    __syncthreads();
    float mu = red[0] * (1.f/512.f);
    __syncthreads();

    float d0 = y0 - mu, d1 = y1 - mu;
    float sq = d0*d0 + d1*d1;
    #pragma unroll
    for (int o = 16; o > 0; o >>= 1) sq += __shfl_xor_sync(0xffffffffu, sq, o);
    if ((tid & 31) == 0) red[tid >> 5] = sq;
    __syncthreads();
    float r2 = (tid < 8) ? red[tid] : 0.f;
    if (tid < 32) {
        #pragma unroll
        for (int o = 4; o > 0; o >>= 1) r2 += __shfl_xor_sync(0xffffffffu, r2, o);
        if (tid == 0) red[0] = r2;
    }
    __syncthreads();
    float rstd = rsqrtf(red[0] * (1.f/512.f) + 1e-5f);

    __half2* mp = (__half2*)(g_mixedh + (size_t)tb*DD) + tid;
    *mp = __floats2half2_rn(d0*rstd*lng[2*tid]   + lnb[2*tid],
                            d1*rstd*lng[2*tid+1] + lnb[2*tid+1]);
}

// ---------------- host launcher ----------------
extern "C" void kernel_launch(void* const* d_in, const int* in_sizes, int n_in,
                              void* d_out, int out_size)
{
    const int*   x      = (const int*)  d_in[0];
    const float* h0     = (const float*)d_in[1];
    const float* c0     = (const float*)d_in[2];
    const float* emb    = (const float*)d_in[3];
    const float* W_ih   = (const float*)d_in[4];
    const float* b_ih   = (const float*)d_in[5];
    const float* W_hh   = (const float*)d_in[6];
    const float* b_hh   = (const float*)d_in[7];
    const float* W_np   = (const float*)d_in[8];
    const float* b_np   = (const float*)d_in[9];
    const float* in_w   = (const float*)d_in[10];
    const float* in_b   = (const float*)d_in[11];
    const float* op_w   = (const float*)d_in[12];
    const float* op_b   = (const float*)d_in[13];
    const float* ln_g   = (const float*)d_in[14];
    const float* ln_b   = (const float*)d_in[15];
    const float* head_w = (const float*)d_in[16];
    const float* head_b = (const float*)d_in[17];
    float* out = (float*)d_out;

    float *qpre, *ihp, *kv, *yraw;
    __half *xsh, *hallh, *nouth, *atth, *mixedh;
    __half *inwh, *wihh, *wnph, *opwh, *hdwh;
    cudaGetSymbolAddress((void**)&xsh,    g_xsh);
    cudaGetSymbolAddress((void**)&qpre,   g_qpre);
    cudaGetSymbolAddress((void**)&ihp,    g_ihp);
    cudaGetSymbolAddress((void**)&hallh,  g_hallh);
    cudaGetSymbolAddress((void**)&nouth,  g_nouth);
    cudaGetSymbolAddress((void**)&kv,     g_kv);
    cudaGetSymbolAddress((void**)&atth,   g_atth);
    cudaGetSymbolAddress((void**)&yraw,   g_yraw);
    cudaGetSymbolAddress((void**)&mixedh, g_mixedh);
    cudaGetSymbolAddress((void**)&inwh,   g_inwh);
    cudaGetSymbolAddress((void**)&wihh,   g_wihh);
    cudaGetSymbolAddress((void**)&wnph,   g_wnph);
    cudaGetSymbolAddress((void**)&opwh,   g_opwh);
    cudaGetSymbolAddress((void**)&hdwh,   g_hdwh);

    const int GEMM_SMEM = 2*NSTG*ST_H*(int)sizeof(__half);   // 110592 B
    static int smem_set = 0;
    if (!smem_set) {
        cudaFuncSetAttribute(mma_gemm, cudaFuncAttributeMaxDynamicSharedMemorySize, GEMM_SMEM);
        smem_set = 1;
    }

    const long BSV = (long)BB*SS*VV;
    const long NBR = (long)NCELL*BB*RR;
    bool write_state = ((long)out_size >= BSV + 2*NBR);
    float* hf_out = write_state ? out + BSV        : nullptr;
    float* cf_out = write_state ? out + BSV + NBR  : nullptr;

    // 0. fp16 weight conversions
    convh_kernel<<<  768, 256>>>(in_w,   inwh);
    convh_kernel<<<16384, 256>>>(W_ih,   wihh);
    convh_kernel<<< 4096, 256>>>(W_np,   wnph);
    convh_kernel<<<  256, 256>>>(op_w,   opwh);
    convh_kernel<<<16000, 256>>>(head_w, hdwh);
    // 1. embed + counter reset
    embed_kernel<<<MROWS, 128>>>(x, emb);
    // 2. repack W_hh (fp32)
    repack_kernel<<<(NCELL*GG*RR/4)/256, 256>>>(W_hh);
    // 3. q = xs @ Wq^T + bq
    mma_gemm<<<dim3(DD/128, MROWS/128, 1), 256, GEMM_SMEM>>>(
        xsh, inwh, in_b, nullptr, qpre, DD, DD,
        0, 0, 0,
        8L*DD, DD, 1, 0, 0, 30, 0);
    // 4. gates_ih = xs @ W_ih^T + (b_ih+b_hh)  -> ihp[t][n][b][g]
    mma_gemm<<<dim3(NCELL*GG/128, MROWS/128, 1), 256, GEMM_SMEM>>>(
        xsh, wihh, b_ih, b_hh, ihp, DD, DD,
        0, 0, 0,
        (long)NCELL*BB*GG, GG, 1, 0,
        (long)BB*GG, 11, 0);
    // 5. recurrence (persistent, 128 CTAs)
    recurrence_kernel<<<NCELL*8, 512>>>(h0, c0, hf_out, cf_out);
    // 6. nout[n] = hall[n] @ W_np[n]^T + b_np[n]  -> fp16
    mma_gemm<<<dim3(DD/128, MROWS/128, NCELL), 256, GEMM_SMEM>>>(
        hallh, wnph, b_np, nullptr, nouth, RR, RR,
        (long)SS*BB*RR, (long)DD*RR, DD,
        8L*DD, DD, 1, (long)SS*BB*DD, 0, 30, 1);
    // 7. kv = nout @ [Wk;Wv]^T + [bk;bv]  (fp32 out)
    mma_gemm<<<dim3(1024/128, (NCELL*MROWS)/128, 1), 256, GEMM_SMEM>>>(
        nouth, inwh + (size_t)DD*DD, in_b + DD, nullptr, kv, DD, DD,
        0, 0, 0,
        8L*1024, 1024, 1, 0, 0, 30, 0);
    // 8. attention (writes atth fp16)
    attn_kernel<<<MROWS, 256>>>();
    // 9. op projection (fp32 out)
    mma_gemm<<<dim3(DD/128, MROWS/128, 1), 256, GEMM_SMEM>>>(
        atth, opwh, op_b, nullptr, yraw, DD, DD,
        0, 0, 0,
        8L*DD, DD, 1, 0, 0, 30, 0);
    // 10. residual + LN (writes mixedh fp16)
    ln_kernel<<<MROWS, 256>>>(ln_g, ln_b);
    // 11. head: logits -> out (B,S,V) fp32
    mma_gemm<<<dim3(VV/128, MROWS/128, 1), 256, GEMM_SMEM>>>(
        mixedh, hdwh, head_b, nullptr, out, DD, DD,
        0, 0, 0,
        (long)VV, (long)SS*VV, 1, 0, 0, 30, 0);
}

// round 13
// speedup vs baseline: 3.8791x; 2.1397x over previous
#include <cuda_runtime.h>
#include <cuda_fp16.h>
#include <cstdint>

#define SS   256
#define BB   8
#define VV   32000
#define DD   512
#define NCELL 16
#define RR   512
#define GG   2048   // 4*R
#define HH   8
#define MROWS 2048  // S*B

// ---------------- scratch (__device__ globals; no allocation) ----------------
__device__ float  g_xs   [(size_t)SS*BB*DD];           // raw embeddings (residual)
__device__ __half g_xsh  [(size_t)SS*BB*DD];           // fp16 embeddings
__device__ float  g_qpre [(size_t)SS*BB*DD];
__device__ float  g_ihp  [(size_t)SS*NCELL*BB*GG];     // (S,N,B,G) fp32
__device__ __half g_wph  [(size_t)NCELL*GG*RR];        // W_hh fragment-packed fp16
__device__ __half g_hallh[(size_t)NCELL*SS*BB*RR];     // fp16 h history
__device__ __half g_nouth[(size_t)NCELL*SS*BB*DD];     // fp16 nout
__device__ float  g_kv   [(size_t)NCELL*SS*BB*1024];
__device__ __half g_atth [(size_t)SS*BB*DD];
__device__ float  g_yraw [(size_t)SS*BB*DD];
__device__ __half g_mixedh[(size_t)SS*BB*DD];
__device__ float  g_hbuf [2*NCELL*BB*RR];              // [parity][n][b][k]
__device__ volatile int g_cnt[NCELL];
// fp16 weight copies
__device__ __half g_inwh [(size_t)3*DD*DD];
__device__ __half g_wihh [(size_t)NCELL*GG*DD];
__device__ __half g_wnph [(size_t)NCELL*DD*RR];
__device__ __half g_opwh [(size_t)DD*DD];
__device__ __half g_hdwh [(size_t)VV*DD];

// ---------------- helpers ----------------
__device__ __forceinline__ void mma16(float* c, const uint32_t* a, const uint32_t* b) {
    asm volatile(
        "mma.sync.aligned.m16n8k16.row.col.f32.f16.f16.f32 "
        "{%0,%1,%2,%3}, {%4,%5,%6,%7}, {%8,%9}, {%0,%1,%2,%3};\n"
        : "+f"(c[0]), "+f"(c[1]), "+f"(c[2]), "+f"(c[3])
        : "r"(a[0]), "r"(a[1]), "r"(a[2]), "r"(a[3]), "r"(b[0]), "r"(b[1]));
}
__device__ __forceinline__ void ldsm4(uint32_t& r0, uint32_t& r1, uint32_t& r2, uint32_t& r3,
                                      uint32_t addr) {
    asm volatile("ldmatrix.sync.aligned.m8n8.x4.shared.b16 {%0,%1,%2,%3}, [%4];"
                 : "=r"(r0), "=r"(r1), "=r"(r2), "=r"(r3) : "r"(addr));
}
__device__ __forceinline__ void cp16(uint32_t saddr, const void* gaddr) {
    asm volatile("cp.async.ca.shared.global [%0], [%1], 16;\n" :: "r"(saddr), "l"(gaddr));
}
#define CP_COMMIT() asm volatile("cp.async.commit_group;\n")
#define CP_WAIT1()  asm volatile("cp.async.wait_group 1;\n")

// ---------------- f32 -> f16 convert (4 elems/thread) ----------------
__global__ __launch_bounds__(256)
void convh_kernel(const float* __restrict__ src, __half* __restrict__ dst)
{
    size_t i = ((size_t)blockIdx.x*256 + threadIdx.x)*4;
    float4 v = *(const float4*)(src + i);
    __half2* d = (__half2*)(dst + i);
    d[0] = __floats2half2_rn(v.x, v.y);
    d[1] = __floats2half2_rn(v.z, v.w);
}

// ---------------- embed + counter reset ----------------
__global__ __launch_bounds__(128)
void embed_kernel(const int* __restrict__ x, const float* __restrict__ emb)
{
    int tb = blockIdx.x;               // t*8+b
    int t = tb >> 3, b = tb & 7;
    if (tb == 0 && threadIdx.x < NCELL) g_cnt[threadIdx.x] = 0;
    int idx = x[b*SS + t];
    float4 v = ((const float4*)(emb + (size_t)idx*DD))[threadIdx.x];
    ((float4*)(g_xs + (size_t)tb*DD))[threadIdx.x] = v;
    __half2* d = (__half2*)(g_xsh + (size_t)tb*DD) + threadIdx.x*2;
    d[0] = __floats2half2_rn(v.x, v.y);
    d[1] = __floats2half2_rn(v.z, v.w);
}

// ---------------- W_hh repack into mma A-fragment order (fp16) ----------------
// layout: [cell][cb][warp][ks][lane] x 8 halves (16B per lane)
__global__ __launch_bounds__(256)
void repack_mma(const float* __restrict__ whh)
{
    int o = blockIdx.x*256 + threadIdx.x;     // uint4 index
    int l    = o & 31;
    int ks   = (o >> 5) & 31;
    int w    = (o >> 10) & 15;
    int cb   = (o >> 14) & 7;
    int cell = o >> 17;
    __half h[8];
    #pragma unroll
    for (int r = 0; r < 4; r++) {
        int lr = w*16 + (l >> 2) + (r & 1)*8;
        int grow = (lr >> 6)*512 + cb*64 + (lr & 63);
        int k = ks*16 + (l & 3)*2 + (r >> 1)*8;
        const float* s = whh + ((size_t)cell*GG + grow)*RR + k;
        h[r*2]   = __float2half(s[0]);
        h[r*2+1] = __float2half(s[1]);
    }
    ((uint4*)g_wph)[o] = *(uint4*)h;
}

// ---------------- FP16 tensor-core GEMM: C = A @ B^T + bias ----------------
#define ST_H   (128*72)      // halves per operand per stage
#define NSTG   3
__global__ __launch_bounds__(256, 2)
void mma_gemm(const __half* __restrict__ A, const __half* __restrict__ Bw,
              const float* __restrict__ bias1, const float* __restrict__ bias2,
              void* __restrict__ Cv, int K, long lda,
              long sAz, long sBz, long sBiasZ,
              long sCt, long sCb, long sCc, long sCz,
              long sCcBlk, int blkLog, int outHalf)
{
    extern __shared__ __half smem[];
    __half* Abuf = smem;                 // [3][128][72]
    __half* Bbuf = smem + NSTG*ST_H;

    int tid  = threadIdx.x;
    int lane = tid & 31;
    int warp = tid >> 5;
    int wm = warp & 1;
    int wn = warp >> 1;
    int bx = blockIdx.x, by = blockIdx.y, bz = blockIdx.z;

    const __half* Ab = A  + (size_t)bz * sAz;
    const __half* Bb = Bw + (size_t)bz * sBz;

    int lm   = tid >> 1;
    int half = tid & 1;
    const __half* ag = Ab + (size_t)(by*128 + lm)*lda + half*32;
    const __half* bg = Bb + (size_t)(bx*128 + lm)*K   + half*32;
    uint32_t sA = (uint32_t)__cvta_generic_to_shared(Abuf) + (uint32_t)(lm*72 + half*32)*2u;
    uint32_t sB = (uint32_t)__cvta_generic_to_shared(Bbuf) + (uint32_t)(lm*72 + half*32)*2u;

    int qr = lane >> 2;
    int qc = lane & 3;
    int amBase = wm*64;
    int bnBase = wn*32;

    uint32_t aFragBase = (uint32_t)__cvta_generic_to_shared(Abuf)
        + (uint32_t)((amBase + (lane & 15))*72 + (lane >> 4)*8)*2u;
    uint32_t bFragBase = (uint32_t)__cvta_generic_to_shared(Bbuf)
        + (uint32_t)((bnBase + (lane & 7) + ((lane >> 4) << 3))*72 + (lane & 8))*2u;

    float acc[4][4][4];
    #pragma unroll
    for (int i = 0; i < 4; i++)
        #pragma unroll
        for (int j = 0; j < 4; j++)
            #pragma unroll
            for (int e = 0; e < 4; e++) acc[i][j][e] = 0.f;

    int KT = K >> 6;

    #pragma unroll
    for (int p = 0; p < NSTG-1; p++) {
        uint32_t aoff = sA + p*ST_H*2;
        uint32_t boff = sB + p*ST_H*2;
        #pragma unroll
        for (int q = 0; q < 4; q++) {
            cp16(aoff + q*16, ag + p*64 + q*8);
            cp16(boff + q*16, bg + p*64 + q*8);
        }
        CP_COMMIT();
    }

    for (int kt = 0; kt < KT; kt++) {
        CP_WAIT1();
        __syncthreads();
        if (kt + NSTG-1 < KT) {
            int stg = (kt + NSTG-1) % NSTG;
            uint32_t aoff = sA + stg*ST_H*2;
            uint32_t boff = sB + stg*ST_H*2;
            #pragma unroll
            for (int q = 0; q < 4; q++) {
                cp16(aoff + q*16, ag + (kt+NSTG-1)*64 + q*8);
                cp16(boff + q*16, bg + (kt+NSTG-1)*64 + q*8);
            }
        }
        CP_COMMIT();

        uint32_t aS = aFragBase + (kt % NSTG)*ST_H*2;
        uint32_t bS = bFragBase + (kt % NSTG)*ST_H*2;
        #pragma unroll
        for (int ks = 0; ks < 4; ks++) {
            uint32_t k0b = ks*16*2;
            uint32_t af[4][4], bf[4][2];
            #pragma unroll
            for (int i = 0; i < 4; i++)
                ldsm4(af[i][0], af[i][1], af[i][2], af[i][3],
                      aS + (uint32_t)(i*16*72)*2u + k0b);
            #pragma unroll
            for (int jp = 0; jp < 2; jp++)
                ldsm4(bf[jp*2][0], bf[jp*2][1], bf[jp*2+1][0], bf[jp*2+1][1],
                      bS + (uint32_t)(jp*16*72)*2u + k0b);
            #pragma unroll
            for (int i = 0; i < 4; i++)
                #pragma unroll
                for (int j = 0; j < 4; j++)
                    mma16(acc[i][j], af[i], bf[j]);
        }
    }

    long msk = (1L << blkLog) - 1;
    #pragma unroll
    for (int i = 0; i < 4; i++) {
        int r0 = by*128 + amBase + i*16 + qr;
        long ro  = (long)(r0 >> 3)*sCt + (long)(r0 & 7)*sCb;
        long ro8 = (long)((r0+8) >> 3)*sCt + (long)((r0+8) & 7)*sCb;
        #pragma unroll
        for (int j = 0; j < 4; j++) {
            int c0 = bx*128 + bnBase + j*8 + 2*qc;
            float b0v = 0.f, b1v = 0.f;
            if (bias1) { b0v  = bias1[(long)bz*sBiasZ + c0];
                         b1v  = bias1[(long)bz*sBiasZ + c0 + 1]; }
            if (bias2) { b0v += bias2[c0]; b1v += bias2[c0 + 1]; }
            long cc0 = (long)(c0 >> blkLog)*sCcBlk + (long)(c0 & msk)*sCc;
            long cc1 = (long)((c0+1) >> blkLog)*sCcBlk + (long)((c0+1) & msk)*sCc;
            float v00 = acc[i][j][0] + b0v, v01 = acc[i][j][1] + b1v;
            float v10 = acc[i][j][2] + b0v, v11 = acc[i][j][3] + b1v;
            if (outHalf) {
                __half* Cb = (__half*)Cv + (size_t)bz * sCz;
                Cb[ro  + cc0] = __float2half(v00);
                Cb[ro  + cc1] = __float2half(v01);
                Cb[ro8 + cc0] = __float2half(v10);
                Cb[ro8 + cc1] = __float2half(v11);
            } else {
                float* Cb = (float*)Cv + (size_t)bz * sCz;
                Cb[ro  + cc0] = v00;
                Cb[ro  + cc1] = v01;
                Cb[ro8 + cc0] = v10;
                Cb[ro8 + cc1] = v11;
            }
        }
    }
}

// ---------------- persistent LSTM recurrence (tensor-core) ----------------
// grid 128: blockIdx = cell*8 + chunk. 512 threads = 16 warps x 16 gate rows.
#define HPAD 520
__global__ __launch_bounds__(512)
void recurrence_kernel(const float* __restrict__ h0, const float* __restrict__ c0,
                       float* hf_out, float* cf_out)
{
    __shared__ __half h_s[BB*HPAD];     // [b][k] padded, fp16
    __shared__ float g_sm[256][10];

    int tid  = threadIdx.x;
    int cell = blockIdx.x >> 3;
    int cb   = blockIdx.x & 7;
    int warp = tid >> 5;
    int l    = tid & 31;

    int ub = tid >> 6;                  // batch for update phase
    int uj = tid & 63;                  // unit for update phase

    // init h_s from h0 (fp32 -> fp16)
    {
        int b = tid >> 6, k = (tid & 63)*8;
        const float4* s = (const float4*)(h0 + ((size_t)cell*BB + b)*RR + k);
        float4 p0 = s[0], p1 = s[1];
        __half hh[8];
        hh[0]=__float2half(p0.x); hh[1]=__float2half(p0.y);
        hh[2]=__float2half(p0.z); hh[3]=__float2half(p0.w);
        hh[4]=__float2half(p1.x); hh[5]=__float2half(p1.y);
        hh[6]=__float2half(p1.z); hh[7]=__float2half(p1.w);
        *(uint4*)&h_s[b*HPAD + k] = *(uint4*)hh;
    }
    float c_reg = c0[((size_t)cell*BB + ub)*RR + cb*64 + uj];
    __syncthreads();

    const uint4* wf = (const uint4*)g_wph + ((size_t)((cell*8 + cb)*16 + warp))*1024 + l;
    int hb = (l >> 2)*HPAD + (l & 3)*2;       // half index of b-frag base
    int lw = warp*16 + (l >> 2);
    int n0 = (l & 3)*2;

    for (int t = 0; t < SS; t++) {
        float c4[4] = {0.f, 0.f, 0.f, 0.f};
        uint4 a = __ldcg(wf);
        #pragma unroll 4
        for (int ks = 0; ks < 32; ks++) {
            uint4 an;
            if (ks < 31) an = __ldcg(wf + (ks+1)*32);
            uint32_t bb[2];
            bb[0] = *(const uint32_t*)&h_s[hb + ks*16];
            bb[1] = *(const uint32_t*)&h_s[hb + ks*16 + 8];
            mma16(c4, (const uint32_t*)&a, bb);
            a = an;
        }
        *(float2*)&g_sm[lw][n0]     = make_float2(c4[0], c4[1]);
        *(float2*)&g_sm[lw + 8][n0] = make_float2(c4[2], c4[3]);
        __syncthreads();

        // LSTM update for (unit uj, batch ub); add precomputed ih+bias here
        const float* ib = g_ihp + (((size_t)t*NCELL + cell)*BB + ub)*GG + cb*64 + uj;
        float gi = g_sm[      uj][ub] + ib[0];
        float gf = g_sm[ 64 + uj][ub] + ib[512];
        float gg = g_sm[128 + uj][ub] + ib[1024];
        float go = g_sm[192 + uj][ub] + ib[1536];
        float si = 1.f/(1.f + expf(-gi));
        float sf = 1.f/(1.f + expf(-gf));
        float so = 1.f/(1.f + expf(-go));
        float cn = sf*c_reg + si*tanhf(gg);
        float hn = so*tanhf(cn);
        c_reg = cn;

        g_hallh[(((size_t)cell*SS + t)*BB + ub)*RR + cb*64 + uj] = __float2half(hn);
        int par = (t + 1) & 1;
        g_hbuf[((size_t)(par*NCELL + cell)*BB + ub)*RR + cb*64 + uj] = hn;
        if (t == SS-1) {
            if (hf_out) hf_out[((size_t)cell*BB + ub)*RR + cb*64 + uj] = hn;
            if (cf_out) cf_out[((size_t)cell*BB + ub)*RR + cb*64 + uj] = cn;
        }

        __threadfence();
        __syncthreads();
        if (tid == 0) {
            atomicAdd((int*)&g_cnt[cell], 1);
            int target = 8*(t+1);
            while (g_cnt[cell] < target) { }
        }
        __syncthreads();

        // rebuild h_s (fp16) from hbuf (fp32, written by peer CTAs)
        {
            int b = tid >> 6, k = (tid & 63)*8;
            const float* src = g_hbuf + ((size_t)(par*NCELL + cell)*BB + b)*RR + k;
            float4 p0 = __ldcg((const float4*)src);
            float4 p1 = __ldcg((const float4*)(src + 4));
            __half hh[8];
            hh[0]=__float2half(p0.x); hh[1]=__float2half(p0.y);
            hh[2]=__float2half(p0.z); hh[3]=__float2half(p0.w);
            hh[4]=__float2half(p1.x); hh[5]=__float2half(p1.y);
            hh[6]=__float2half(p1.z); hh[7]=__float2half(p1.w);
            *(uint4*)&h_s[b*HPAD + k] = *(uint4*)hh;
        }
        __syncthreads();
    }
}

// ---------------- attention (q,k,v -> att fp16) ----------------
__global__ __launch_bounds__(256)
void attn_kernel()
{
    int tb = blockIdx.x;                // t*8+b
    int t = tb >> 3, b = tb & 7;
    int h = threadIdx.x >> 5;
    int lane = threadIdx.x & 31;

    const float* qrow = g_qpre + (size_t)tb*DD + h*64;
    float q0 = qrow[2*lane], q1 = qrow[2*lane + 1];

    float s[NCELL];
    #pragma unroll
    for (int n = 0; n < NCELL; n++) {
        const float* kp = g_kv + (((size_t)n*SS + t)*BB + b)*1024 + h*64;
        float2 k2 = *(const float2*)(kp + 2*lane);
        float p = q0*k2.x + q1*k2.y;
        #pragma unroll
        for (int o = 16; o > 0; o >>= 1) p += __shfl_xor_sync(0xffffffffu, p, o);
        s[n] = p * 0.125f;
    }
    float m = s[0];
    #pragma unroll
    for (int n = 1; n < NCELL; n++) m = fmaxf(m, s[n]);
    float sum = 0.f;
    #pragma unroll
    for (int n = 0; n < NCELL; n++) { s[n] = expf(s[n] - m); sum += s[n]; }
    float inv = 1.f/sum;

    float a0 = 0.f, a1 = 0.f;
    #pragma unroll
    for (int n = 0; n < NCELL; n++) {
        const float* vp = g_kv + (((size_t)n*SS + t)*BB + b)*1024 + 512 + h*64;
        float2 v2 = *(const float2*)(vp + 2*lane);
        float w = s[n]*inv;
        a0 += w*v2.x; a1 += w*v2.y;
    }
    __half2* ap = (__half2*)(g_atth + (size_t)tb*DD + h*64) + lane;
    *ap = __floats2half2_rn(a0, a1);
}

// ---------------- residual + layernorm (-> fp16) ----------------
__global__ __launch_bounds__(256)
void ln_kernel(const float* __restrict__ lng, const float* __restrict__ lnb)
{
    __shared__ float red[8];
    int tb = blockIdx.x;
    int tid = threadIdx.x;
    const float* yp = g_yraw + (size_t)tb*DD;
    const float* xp = g_xs   + (size_t)tb*DD;
    float y0 = yp[2*tid]   + xp[2*tid];
    float y1 = yp[2*tid+1] + xp[2*tid+1];

    float v = y0 + y1;
    #pragma unroll
    for (int o = 16; o > 0; o >>= 1) v += __shfl_xor_sync(0xffffffffu, v, o);
    if ((tid & 31) == 0) red[tid >> 5] = v;
    __syncthreads();
    float r = (tid < 8) ? red[tid] : 0.f;
    if (tid < 32) {
        #pragma unroll
        for (int o = 4; o > 0; o >>= 1) r += __shfl_xor_sync(0xffffffffu, r, o);
        if (tid == 0) red[0] = r;
    }
    __syncthreads();
    float mu = red[0] * (1.f/512.f);
    __syncthreads();

    float d0 = y0 - mu, d1 = y1 - mu;
    float sq = d0*d0 + d1*d1;
    #pragma unroll
    for (int o = 16; o > 0; o >>= 1) sq += __shfl_xor_sync(0xffffffffu, sq, o);
    if ((tid & 31) == 0) red[tid >> 5] = sq;
    __syncthreads();
    float r2 = (tid < 8) ? red[tid] : 0.f;
    if (tid < 32) {
        #pragma unroll
        for (int o = 4; o > 0; o >>= 1) r2 += __shfl_xor_sync(0xffffffffu, r2, o);
        if (tid == 0) red[0] = r2;
    }
    __syncthreads();
    float rstd = rsqrtf(red[0] * (1.f/512.f) + 1e-5f);

    __half2* mp = (__half2*)(g_mixedh + (size_t)tb*DD) + tid;
    *mp = __floats2half2_rn(d0*rstd*lng[2*tid]   + lnb[2*tid],
                            d1*rstd*lng[2*tid+1] + lnb[2*tid+1]);
}

// ---------------- host launcher ----------------
extern "C" void kernel_launch(void* const* d_in, const int* in_sizes, int n_in,
                              void* d_out, int out_size)
{
    const int*   x      = (const int*)  d_in[0];
    const float* h0     = (const float*)d_in[1];
    const float* c0     = (const float*)d_in[2];
    const float* emb    = (const float*)d_in[3];
    const float* W_ih   = (const float*)d_in[4];
    const float* b_ih   = (const float*)d_in[5];
    const float* W_hh   = (const float*)d_in[6];
    const float* b_hh   = (const float*)d_in[7];
    const float* W_np   = (const float*)d_in[8];
    const float* b_np   = (const float*)d_in[9];
    const float* in_w   = (const float*)d_in[10];
    const float* in_b   = (const float*)d_in[11];
    const float* op_w   = (const float*)d_in[12];
    const float* op_b   = (const float*)d_in[13];
    const float* ln_g   = (const float*)d_in[14];
    const float* ln_b   = (const float*)d_in[15];
    const float* head_w = (const float*)d_in[16];
    const float* head_b = (const float*)d_in[17];
    float* out = (float*)d_out;

    float *qpre, *ihp, *kv, *yraw;
    __half *xsh, *hallh, *nouth, *atth, *mixedh;
    __half *inwh, *wihh, *wnph, *opwh, *hdwh;
    cudaGetSymbolAddress((void**)&xsh,    g_xsh);
    cudaGetSymbolAddress((void**)&qpre,   g_qpre);
    cudaGetSymbolAddress((void**)&ihp,    g_ihp);
    cudaGetSymbolAddress((void**)&hallh,  g_hallh);
    cudaGetSymbolAddress((void**)&nouth,  g_nouth);
    cudaGetSymbolAddress((void**)&kv,     g_kv);
    cudaGetSymbolAddress((void**)&atth,   g_atth);
    cudaGetSymbolAddress((void**)&yraw,   g_yraw);
    cudaGetSymbolAddress((void**)&mixedh, g_mixedh);
    cudaGetSymbolAddress((void**)&inwh,   g_inwh);
    cudaGetSymbolAddress((void**)&wihh,   g_wihh);
    cudaGetSymbolAddress((void**)&wnph,   g_wnph);
    cudaGetSymbolAddress((void**)&opwh,   g_opwh);
    cudaGetSymbolAddress((void**)&hdwh,   g_hdwh);

    const int GEMM_SMEM = 2*NSTG*ST_H*(int)sizeof(__half);   // 110592 B
    static int smem_set = 0;
    if (!smem_set) {
        cudaFuncSetAttribute(mma_gemm, cudaFuncAttributeMaxDynamicSharedMemorySize, GEMM_SMEM);
        smem_set = 1;
    }

    const long BSV = (long)BB*SS*VV;
    const long NBR = (long)NCELL*BB*RR;
    bool write_state = ((long)out_size >= BSV + 2*NBR);
    float* hf_out = write_state ? out + BSV        : nullptr;
    float* cf_out = write_state ? out + BSV + NBR  : nullptr;

    // 0. fp16 weight conversions
    convh_kernel<<<  768, 256>>>(in_w,   inwh);
    convh_kernel<<<16384, 256>>>(W_ih,   wihh);
    convh_kernel<<< 4096, 256>>>(W_np,   wnph);
    convh_kernel<<<  256, 256>>>(op_w,   opwh);
    convh_kernel<<<16000, 256>>>(head_w, hdwh);
    // 1. embed + counter reset
    embed_kernel<<<MROWS, 128>>>(x, emb);
    // 2. repack W_hh into fragment order (fp16)
    repack_mma<<<(NCELL*GG*RR/8)/256, 256>>>(W_hh);
    // 3. q = xs @ Wq^T + bq
    mma_gemm<<<dim3(DD/128, MROWS/128, 1), 256, GEMM_SMEM>>>(
        xsh, inwh, in_b, nullptr, qpre, DD, DD,
        0, 0, 0,
        8L*DD, DD, 1, 0, 0, 30, 0);
    // 4. gates_ih = xs @ W_ih^T + (b_ih+b_hh)  -> ihp[t][n][b][g]
    mma_gemm<<<dim3(NCELL*GG/128, MROWS/128, 1), 256, GEMM_SMEM>>>(
        xsh, wihh, b_ih, b_hh, ihp, DD, DD,
        0, 0, 0,
        (long)NCELL*BB*GG, GG, 1, 0,
        (long)BB*GG, 11, 0);
    // 5. recurrence (persistent, 128 CTAs, tensor-core)
    recurrence_kernel<<<NCELL*8, 512>>>(h0, c0, hf_out, cf_out);
    // 6. nout[n] = hall[n] @ W_np[n]^T + b_np[n]  -> fp16
    mma_gemm<<<dim3(DD/128, MROWS/128, NCELL), 256, GEMM_SMEM>>>(
        hallh, wnph, b_np, nullptr, nouth, RR, RR,
        (long)SS*BB*RR, (long)DD*RR, DD,
        8L*DD, DD, 1, (long)SS*BB*DD, 0, 30, 1);
    // 7. kv = nout @ [Wk;Wv]^T + [bk;bv]  (fp32 out)
    mma_gemm<<<dim3(1024/128, (NCELL*MROWS)/128, 1), 256, GEMM_SMEM>>>(
        nouth, inwh + (size_t)DD*DD, in_b + DD, nullptr, kv, DD, DD,
        0, 0, 0,
        8L*1024, 1024, 1, 0, 0, 30, 0);
    // 8. attention (writes atth fp16)
    attn_kernel<<<MROWS, 256>>>();
    // 9. op projection (fp32 out)
    mma_gemm<<<dim3(DD/128, MROWS/128, 1), 256, GEMM_SMEM>>>(
        atth, opwh, op_b, nullptr, yraw, DD, DD,
        0, 0, 0,
        8L*DD, DD, 1, 0, 0, 30, 0);
    // 10. residual + LN (writes mixedh fp16)
    ln_kernel<<<MROWS, 256>>>(ln_g, ln_b);
    // 11. head: logits -> out (B,S,V) fp32
    mma_gemm<<<dim3(VV/128, MROWS/128, 1), 256, GEMM_SMEM>>>(
        mixedh, hdwh, head_b, nullptr, out, DD, DD,
        0, 0, 0,
        (long)VV, (long)SS*VV, 1, 0, 0, 30, 0);
}

// round 14
// speedup vs baseline: 4.1733x; 1.0758x over previous
#include <cuda_runtime.h>
#include <cuda_fp16.h>
#include <cstdint>

#define SS   256
#define BB   8
#define VV   32000
#define DD   512
#define NCELL 16
#define RR   512
#define GG   2048   // 4*R
#define HH   8
#define MROWS 2048  // S*B

// ---------------- scratch (__device__ globals; no allocation) ----------------
__device__ float  g_xs   [(size_t)SS*BB*DD];           // raw embeddings (residual)
__device__ __half g_xsh  [(size_t)SS*BB*DD];           // fp16 embeddings
__device__ float  g_qpre [(size_t)SS*BB*DD];
__device__ float  g_ihp  [(size_t)SS*NCELL*BB*GG];     // (S,N,B,G) fp32
__device__ __half g_wph  [(size_t)NCELL*GG*RR];        // W_hh fragment-packed fp16
__device__ __half g_hallh[(size_t)NCELL*SS*BB*RR];     // fp16 h history
__device__ __half g_nouth[(size_t)NCELL*SS*BB*DD];     // fp16 nout
__device__ float  g_kv   [(size_t)NCELL*SS*BB*1024];
__device__ __half g_atth [(size_t)SS*BB*DD];
__device__ float  g_yraw [(size_t)SS*BB*DD];
__device__ __half g_mixedh[(size_t)SS*BB*DD];
__device__ float  g_hbuf [2*NCELL*BB*RR];              // [parity][n][b][k]
__device__ volatile int g_cnt[NCELL];
// fp16 weight copies
__device__ __half g_inwh [(size_t)3*DD*DD];
__device__ __half g_wihh [(size_t)NCELL*GG*DD];
__device__ __half g_wnph [(size_t)NCELL*DD*RR];
__device__ __half g_opwh [(size_t)DD*DD];
__device__ __half g_hdwh [(size_t)VV*DD];

// ---------------- helpers ----------------
__device__ __forceinline__ void mma16(float* c, const uint32_t* a, const uint32_t* b) {
    asm volatile(
        "mma.sync.aligned.m16n8k16.row.col.f32.f16.f16.f32 "
        "{%0,%1,%2,%3}, {%4,%5,%6,%7}, {%8,%9}, {%0,%1,%2,%3};\n"
        : "+f"(c[0]), "+f"(c[1]), "+f"(c[2]), "+f"(c[3])
        : "r"(a[0]), "r"(a[1]), "r"(a[2]), "r"(a[3]), "r"(b[0]), "r"(b[1]));
}
__device__ __forceinline__ void ldsm4(uint32_t& r0, uint32_t& r1, uint32_t& r2, uint32_t& r3,
                                      uint32_t addr) {
    asm volatile("ldmatrix.sync.aligned.m8n8.x4.shared.b16 {%0,%1,%2,%3}, [%4];"
                 : "=r"(r0), "=r"(r1), "=r"(r2), "=r"(r3) : "r"(addr));
}
__device__ __forceinline__ void cp16(uint32_t saddr, const void* gaddr) {
    asm volatile("cp.async.ca.shared.global [%0], [%1], 16;\n" :: "r"(saddr), "l"(gaddr));
}
#define CP_COMMIT() asm volatile("cp.async.commit_group;\n")
#define CP_WAIT1()  asm volatile("cp.async.wait_group 1;\n")

// ---------------- f32 -> f16 convert (4 elems/thread) ----------------
__global__ __launch_bounds__(256)
void convh_kernel(const float* __restrict__ src, __half* __restrict__ dst)
{
    size_t i = ((size_t)blockIdx.x*256 + threadIdx.x)*4;
    float4 v = *(const float4*)(src + i);
    __half2* d = (__half2*)(dst + i);
    d[0] = __floats2half2_rn(v.x, v.y);
    d[1] = __floats2half2_rn(v.z, v.w);
}

// ---------------- embed + counter reset ----------------
__global__ __launch_bounds__(128)
void embed_kernel(const int* __restrict__ x, const float* __restrict__ emb)
{
    int tb = blockIdx.x;               // t*8+b
    int t = tb >> 3, b = tb & 7;
    if (tb == 0 && threadIdx.x < NCELL) g_cnt[threadIdx.x] = 0;
    int idx = x[b*SS + t];
    float4 v = ((const float4*)(emb + (size_t)idx*DD))[threadIdx.x];
    ((float4*)(g_xs + (size_t)tb*DD))[threadIdx.x] = v;
    __half2* d = (__half2*)(g_xsh + (size_t)tb*DD) + threadIdx.x*2;
    d[0] = __floats2half2_rn(v.x, v.y);
    d[1] = __floats2half2_rn(v.z, v.w);
}

// ---------------- W_hh repack into mma A-fragment order (fp16) ----------------
// layout: [cell][cb][warp][ks][lane] x 8 halves (16B per lane)
__global__ __launch_bounds__(256)
void repack_mma(const float* __restrict__ whh)
{
    int o = blockIdx.x*256 + threadIdx.x;     // uint4 index
    int l    = o & 31;
    int ks   = (o >> 5) & 31;
    int w    = (o >> 10) & 15;
    int cb   = (o >> 14) & 7;
    int cell = o >> 17;
    __half h[8];
    #pragma unroll
    for (int r = 0; r < 4; r++) {
        int lr = w*16 + (l >> 2) + (r & 1)*8;
        int grow = (lr >> 6)*512 + cb*64 + (lr & 63);
        int k = ks*16 + (l & 3)*2 + (r >> 1)*8;
        const float* s = whh + ((size_t)cell*GG + grow)*RR + k;
        h[r*2]   = __float2half(s[0]);
        h[r*2+1] = __float2half(s[1]);
    }
    ((uint4*)g_wph)[o] = *(uint4*)h;
}

// ---------------- FP16 tensor-core GEMM: C = A @ B^T + bias ----------------
#define ST_H   (128*72)      // halves per operand per stage
#define NSTG   3
__global__ __launch_bounds__(256, 2)
void mma_gemm(const __half* __restrict__ A, const __half* __restrict__ Bw,
              const float* __restrict__ bias1, const float* __restrict__ bias2,
              void* __restrict__ Cv, int K, long lda,
              long sAz, long sBz, long sBiasZ,
              long sCt, long sCb, long sCc, long sCz,
              long sCcBlk, int blkLog, int outHalf)
{
    extern __shared__ __half smem[];
    __half* Abuf = smem;                 // [3][128][72]
    __half* Bbuf = smem + NSTG*ST_H;

    int tid  = threadIdx.x;
    int lane = tid & 31;
    int warp = tid >> 5;
    int wm = warp & 1;
    int wn = warp >> 1;
    int bx = blockIdx.x, by = blockIdx.y, bz = blockIdx.z;

    const __half* Ab = A  + (size_t)bz * sAz;
    const __half* Bb = Bw + (size_t)bz * sBz;

    int lm   = tid >> 1;
    int half = tid & 1;
    const __half* ag = Ab + (size_t)(by*128 + lm)*lda + half*32;
    const __half* bg = Bb + (size_t)(bx*128 + lm)*K   + half*32;
    uint32_t sA = (uint32_t)__cvta_generic_to_shared(Abuf) + (uint32_t)(lm*72 + half*32)*2u;
    uint32_t sB = (uint32_t)__cvta_generic_to_shared(Bbuf) + (uint32_t)(lm*72 + half*32)*2u;

    int qr = lane >> 2;
    int qc = lane & 3;
    int amBase = wm*64;
    int bnBase = wn*32;

    uint32_t aFragBase = (uint32_t)__cvta_generic_to_shared(Abuf)
        + (uint32_t)((amBase + (lane & 15))*72 + (lane >> 4)*8)*2u;
    uint32_t bFragBase = (uint32_t)__cvta_generic_to_shared(Bbuf)
        + (uint32_t)((bnBase + (lane & 7) + ((lane >> 4) << 3))*72 + (lane & 8))*2u;

    float acc[4][4][4];
    #pragma unroll
    for (int i = 0; i < 4; i++)
        #pragma unroll
        for (int j = 0; j < 4; j++)
            #pragma unroll
            for (int e = 0; e < 4; e++) acc[i][j][e] = 0.f;

    int KT = K >> 6;

    #pragma unroll
    for (int p = 0; p < NSTG-1; p++) {
        uint32_t aoff = sA + p*ST_H*2;
        uint32_t boff = sB + p*ST_H*2;
        #pragma unroll
        for (int q = 0; q < 4; q++) {
            cp16(aoff + q*16, ag + p*64 + q*8);
            cp16(boff + q*16, bg + p*64 + q*8);
        }
        CP_COMMIT();
    }

    for (int kt = 0; kt < KT; kt++) {
        CP_WAIT1();
        __syncthreads();
        if (kt + NSTG-1 < KT) {
            int stg = (kt + NSTG-1) % NSTG;
            uint32_t aoff = sA + stg*ST_H*2;
            uint32_t boff = sB + stg*ST_H*2;
            #pragma unroll
            for (int q = 0; q < 4; q++) {
                cp16(aoff + q*16, ag + (kt+NSTG-1)*64 + q*8);
                cp16(boff + q*16, bg + (kt+NSTG-1)*64 + q*8);
            }
        }
        CP_COMMIT();

        uint32_t aS = aFragBase + (kt % NSTG)*ST_H*2;
        uint32_t bS = bFragBase + (kt % NSTG)*ST_H*2;
        #pragma unroll
        for (int ks = 0; ks < 4; ks++) {
            uint32_t k0b = ks*16*2;
            uint32_t af[4][4], bf[4][2];
            #pragma unroll
            for (int i = 0; i < 4; i++)
                ldsm4(af[i][0], af[i][1], af[i][2], af[i][3],
                      aS + (uint32_t)(i*16*72)*2u + k0b);
            #pragma unroll
            for (int jp = 0; jp < 2; jp++)
                ldsm4(bf[jp*2][0], bf[jp*2][1], bf[jp*2+1][0], bf[jp*2+1][1],
                      bS + (uint32_t)(jp*16*72)*2u + k0b);
            #pragma unroll
            for (int i = 0; i < 4; i++)
                #pragma unroll
                for (int j = 0; j < 4; j++)
                    mma16(acc[i][j], af[i], bf[j]);
        }
    }

    long msk = (1L << blkLog) - 1;
    #pragma unroll
    for (int i = 0; i < 4; i++) {
        int r0 = by*128 + amBase + i*16 + qr;
        long ro  = (long)(r0 >> 3)*sCt + (long)(r0 & 7)*sCb;
        long ro8 = (long)((r0+8) >> 3)*sCt + (long)((r0+8) & 7)*sCb;
        #pragma unroll
        for (int j = 0; j < 4; j++) {
            int c0 = bx*128 + bnBase + j*8 + 2*qc;
            float b0v = 0.f, b1v = 0.f;
            if (bias1) { b0v  = bias1[(long)bz*sBiasZ + c0];
                         b1v  = bias1[(long)bz*sBiasZ + c0 + 1]; }
            if (bias2) { b0v += bias2[c0]; b1v += bias2[c0 + 1]; }
            long cc0 = (long)(c0 >> blkLog)*sCcBlk + (long)(c0 & msk)*sCc;
            long cc1 = (long)((c0+1) >> blkLog)*sCcBlk + (long)((c0+1) & msk)*sCc;
            float v00 = acc[i][j][0] + b0v, v01 = acc[i][j][1] + b1v;
            float v10 = acc[i][j][2] + b0v, v11 = acc[i][j][3] + b1v;
            if (outHalf) {
                __half* Cb = (__half*)Cv + (size_t)bz * sCz;
                Cb[ro  + cc0] = __float2half(v00);
                Cb[ro  + cc1] = __float2half(v01);
                Cb[ro8 + cc0] = __float2half(v10);
                Cb[ro8 + cc1] = __float2half(v11);
            } else {
                float* Cb = (float*)Cv + (size_t)bz * sCz;
                Cb[ro  + cc0] = v00;
                Cb[ro  + cc1] = v01;
                Cb[ro8 + cc0] = v10;
                Cb[ro8 + cc1] = v11;
            }
        }
    }
}

// ---------------- persistent LSTM recurrence (tensor-core + smem W cache) ----
// grid 128: blockIdx = cell*8 + chunk. 512 threads = 16 warps x 16 gate rows.
// Dynamic smem: Wcache[16 warps][24 ks][32 lanes] uint4 (192KB)
//             + h_s[8][520] fp16 (8320B) + g_sm[256][10] fp32 (10240B)
#define HPAD 520
#define KS_SMEM 24
#define W_SMEM_B (16*KS_SMEM*32*16)          // 196608
#define REC_SMEM (W_SMEM_B + BB*HPAD*2 + 256*10*4)   // 215168
__global__ __launch_bounds__(512)
void recurrence_kernel(const float* __restrict__ h0, const float* __restrict__ c0,
                       float* hf_out, float* cf_out)
{
    extern __shared__ char dsm[];
    uint4*  wsm = (uint4*)dsm;                          // [16][24][32]
    __half* h_s = (__half*)(dsm + W_SMEM_B);            // [b][k] padded
    float (*g_sm)[10] = (float(*)[10])(dsm + W_SMEM_B + BB*HPAD*2);

    int tid  = threadIdx.x;
    int cell = blockIdx.x >> 3;
    int cb   = blockIdx.x & 7;
    int warp = tid >> 5;
    int l    = tid & 31;

    int ub = tid >> 6;                  // batch for update phase
    int uj = tid & 63;                  // unit for update phase

    const uint4* wf = (const uint4*)g_wph + ((size_t)((cell*8 + cb)*16 + warp))*1024 + l;

    // fill W smem cache (warp-local: each lane stores/reloads only its own frag)
    #pragma unroll 4
    for (int ks = 0; ks < KS_SMEM; ks++)
        wsm[(warp*KS_SMEM + ks)*32 + l] = __ldg(wf + ks*32);

    // init h_s from h0 (fp32 -> fp16)
    {
        int b = tid >> 6, k = (tid & 63)*8;
        const float4* s = (const float4*)(h0 + ((size_t)cell*BB + b)*RR + k);
        float4 p0 = s[0], p1 = s[1];
        __half hh[8];
        hh[0]=__float2half(p0.x); hh[1]=__float2half(p0.y);
        hh[2]=__float2half(p0.z); hh[3]=__float2half(p0.w);
        hh[4]=__float2half(p1.x); hh[5]=__float2half(p1.y);
        hh[6]=__float2half(p1.z); hh[7]=__float2half(p1.w);
        *(uint4*)&h_s[b*HPAD + k] = *(uint4*)hh;
    }
    float c_reg = c0[((size_t)cell*BB + ub)*RR + cb*64 + uj];
    __syncthreads();

    int hb = (l >> 2)*HPAD + (l & 3)*2;       // half index of b-frag base
    int lw = warp*16 + (l >> 2);
    int n0 = (l & 3)*2;

    for (int t = 0; t < SS; t++) {
        // prefetch the streamed tail (ks 24..31) — latency hides under smem MMAs
        uint4 wreg[8];
        #pragma unroll
        for (int i = 0; i < 8; i++)
            wreg[i] = __ldcg(wf + (KS_SMEM + i)*32);

        float c4a[4] = {0.f, 0.f, 0.f, 0.f};
        float c4b[4] = {0.f, 0.f, 0.f, 0.f};
        #pragma unroll 8
        for (int ks = 0; ks < KS_SMEM; ks++) {
            uint4 a = wsm[(warp*KS_SMEM + ks)*32 + l];
            uint32_t bb[2];
            bb[0] = *(const uint32_t*)&h_s[hb + ks*16];
            bb[1] = *(const uint32_t*)&h_s[hb + ks*16 + 8];
            mma16((ks & 1) ? c4b : c4a, (const uint32_t*)&a, bb);
        }
        #pragma unroll
        for (int i = 0; i < 8; i++) {
            int ks = KS_SMEM + i;
            uint32_t bb[2];
            bb[0] = *(const uint32_t*)&h_s[hb + ks*16];
            bb[1] = *(const uint32_t*)&h_s[hb + ks*16 + 8];
            mma16((i & 1) ? c4b : c4a, (const uint32_t*)&wreg[i], bb);
        }
        float c4[4];
        #pragma unroll
        for (int e = 0; e < 4; e++) c4[e] = c4a[e] + c4b[e];

        *(float2*)&g_sm[lw][n0]     = make_float2(c4[0], c4[1]);
        *(float2*)&g_sm[lw + 8][n0] = make_float2(c4[2], c4[3]);
        __syncthreads();

        // LSTM update for (unit uj, batch ub); add precomputed ih+bias here
        const float* ib = g_ihp + (((size_t)t*NCELL + cell)*BB + ub)*GG + cb*64 + uj;
        float gi = g_sm[      uj][ub] + ib[0];
        float gf = g_sm[ 64 + uj][ub] + ib[512];
        float gg = g_sm[128 + uj][ub] + ib[1024];
        float go = g_sm[192 + uj][ub] + ib[1536];
        float si = 1.f/(1.f + expf(-gi));
        float sf = 1.f/(1.f + expf(-gf));
        float so = 1.f/(1.f + expf(-go));
        float cn = sf*c_reg + si*tanhf(gg);
        float hn = so*tanhf(cn);
        c_reg = cn;

        g_hallh[(((size_t)cell*SS + t)*BB + ub)*RR + cb*64 + uj] = __float2half(hn);
        int par = (t + 1) & 1;
        g_hbuf[((size_t)(par*NCELL + cell)*BB + ub)*RR + cb*64 + uj] = hn;
        if (t == SS-1) {
            if (hf_out) hf_out[((size_t)cell*BB + ub)*RR + cb*64 + uj] = hn;
            if (cf_out) cf_out[((size_t)cell*BB + ub)*RR + cb*64 + uj] = cn;
        }

        __threadfence();
        __syncthreads();
        if (tid == 0) {
            atomicAdd((int*)&g_cnt[cell], 1);
            int target = 8*(t+1);
            while (g_cnt[cell] < target) { }
        }
        __syncthreads();

        // rebuild h_s (fp16) from hbuf (fp32, written by peer CTAs)
        {
            int b = tid >> 6, k = (tid & 63)*8;
            const float* src = g_hbuf + ((size_t)(par*NCELL + cell)*BB + b)*RR + k;
            float4 p0 = __ldcg((const float4*)src);
            float4 p1 = __ldcg((const float4*)(src + 4));
            __half hh[8];
            hh[0]=__float2half(p0.x); hh[1]=__float2half(p0.y);
            hh[2]=__float2half(p0.z); hh[3]=__float2half(p0.w);
            hh[4]=__float2half(p1.x); hh[5]=__float2half(p1.y);
            hh[6]=__float2half(p1.z); hh[7]=__float2half(p1.w);
            *(uint4*)&h_s[b*HPAD + k] = *(uint4*)hh;
        }
        __syncthreads();
    }
}

// ---------------- attention (q,k,v -> att fp16) ----------------
__global__ __launch_bounds__(256)
void attn_kernel()
{
    int tb = blockIdx.x;                // t*8+b
    int t = tb >> 3, b = tb & 7;
    int h = threadIdx.x >> 5;
    int lane = threadIdx.x & 31;

    const float* qrow = g_qpre + (size_t)tb*DD + h*64;
    float q0 = qrow[2*lane], q1 = qrow[2*lane + 1];

    float s[NCELL];
    #pragma unroll
    for (int n = 0; n < NCELL; n++) {
        const float* kp = g_kv + (((size_t)n*SS + t)*BB + b)*1024 + h*64;
        float2 k2 = *(const float2*)(kp + 2*lane);
        float p = q0*k2.x + q1*k2.y;
        #pragma unroll
        for (int o = 16; o > 0; o >>= 1) p += __shfl_xor_sync(0xffffffffu, p, o);
        s[n] = p * 0.125f;
    }
    float m = s[0];
    #pragma unroll
    for (int n = 1; n < NCELL; n++) m = fmaxf(m, s[n]);
    float sum = 0.f;
    #pragma unroll
    for (int n = 0; n < NCELL; n++) { s[n] = expf(s[n] - m); sum += s[n]; }
    float inv = 1.f/sum;

    float a0 = 0.f, a1 = 0.f;
    #pragma unroll
    for (int n = 0; n < NCELL; n++) {
        const float* vp = g_kv + (((size_t)n*SS + t)*BB + b)*1024 + 512 + h*64;
        float2 v2 = *(const float2*)(vp + 2*lane);
        float w = s[n]*inv;
        a0 += w*v2.x; a1 += w*v2.y;
    }
    __half2* ap = (__half2*)(g_atth + (size_t)tb*DD + h*64) + lane;
    *ap = __floats2half2_rn(a0, a1);
}

// ---------------- residual + layernorm (-> fp16) ----------------
__global__ __launch_bounds__(256)
void ln_kernel(const float* __restrict__ lng, const float* __restrict__ lnb)
{
    __shared__ float red[8];
    int tb = blockIdx.x;
    int tid = threadIdx.x;
    const float* yp = g_yraw + (size_t)tb*DD;
    const float* xp = g_xs   + (size_t)tb*DD;
    float y0 = yp[2*tid]   + xp[2*tid];
    float y1 = yp[2*tid+1] + xp[2*tid+1];

    float v = y0 + y1;
    #pragma unroll
    for (int o = 16; o > 0; o >>= 1) v += __shfl_xor_sync(0xffffffffu, v, o);
    if ((tid & 31) == 0) red[tid >> 5] = v;
    __syncthreads();
    float r = (tid < 8) ? red[tid] : 0.f;
    if (tid < 32) {
        #pragma unroll
        for (int o = 4; o > 0; o >>= 1) r += __shfl_xor_sync(0xffffffffu, r, o);
        if (tid == 0) red[0] = r;
    }
    __syncthreads();
    float mu = red[0] * (1.f/512.f);
    __syncthreads();

    float d0 = y0 - mu, d1 = y1 - mu;
    float sq = d0*d0 + d1*d1;
    #pragma unroll
    for (int o = 16; o > 0; o >>= 1) sq += __shfl_xor_sync(0xffffffffu, sq, o);
    if ((tid & 31) == 0) red[tid >> 5] = sq;
    __syncthreads();
    float r2 = (tid < 8) ? red[tid] : 0.f;
    if (tid < 32) {
        #pragma unroll
        for (int o = 4; o > 0; o >>= 1) r2 += __shfl_xor_sync(0xffffffffu, r2, o);
        if (tid == 0) red[0] = r2;
    }
    __syncthreads();
    float rstd = rsqrtf(red[0] * (1.f/512.f) + 1e-5f);

    __half2* mp = (__half2*)(g_mixedh + (size_t)tb*DD) + tid;
    *mp = __floats2half2_rn(d0*rstd*lng[2*tid]   + lnb[2*tid],
                            d1*rstd*lng[2*tid+1] + lnb[2*tid+1]);
}

// ---------------- host launcher ----------------
extern "C" void kernel_launch(void* const* d_in, const int* in_sizes, int n_in,
                              void* d_out, int out_size)
{
    const int*   x      = (const int*)  d_in[0];
    const float* h0     = (const float*)d_in[1];
    const float* c0     = (const float*)d_in[2];
    const float* emb    = (const float*)d_in[3];
    const float* W_ih   = (const float*)d_in[4];
    const float* b_ih   = (const float*)d_in[5];
    const float* W_hh   = (const float*)d_in[6];
    const float* b_hh   = (const float*)d_in[7];
    const float* W_np   = (const float*)d_in[8];
    const float* b_np   = (const float*)d_in[9];
    const float* in_w   = (const float*)d_in[10];
    const float* in_b   = (const float*)d_in[11];
    const float* op_w   = (const float*)d_in[12];
    const float* op_b   = (const float*)d_in[13];
    const float* ln_g   = (const float*)d_in[14];
    const float* ln_b   = (const float*)d_in[15];
    const float* head_w = (const float*)d_in[16];
    const float* head_b = (const float*)d_in[17];
    float* out = (float*)d_out;

    float *qpre, *ihp, *kv, *yraw;
    __half *xsh, *hallh, *nouth, *atth, *mixedh;
    __half *inwh, *wihh, *wnph, *opwh, *hdwh;
    cudaGetSymbolAddress((void**)&xsh,    g_xsh);
    cudaGetSymbolAddress((void**)&qpre,   g_qpre);
    cudaGetSymbolAddress((void**)&ihp,    g_ihp);
    cudaGetSymbolAddress((void**)&hallh,  g_hallh);
    cudaGetSymbolAddress((void**)&nouth,  g_nouth);
    cudaGetSymbolAddress((void**)&kv,     g_kv);
    cudaGetSymbolAddress((void**)&atth,   g_atth);
    cudaGetSymbolAddress((void**)&yraw,   g_yraw);
    cudaGetSymbolAddress((void**)&mixedh, g_mixedh);
    cudaGetSymbolAddress((void**)&inwh,   g_inwh);
    cudaGetSymbolAddress((void**)&wihh,   g_wihh);
    cudaGetSymbolAddress((void**)&wnph,   g_wnph);
    cudaGetSymbolAddress((void**)&opwh,   g_opwh);
    cudaGetSymbolAddress((void**)&hdwh,   g_hdwh);

    const int GEMM_SMEM = 2*NSTG*ST_H*(int)sizeof(__half);   // 110592 B
    static int smem_set = 0;
    if (!smem_set) {
        cudaFuncSetAttribute(mma_gemm, cudaFuncAttributeMaxDynamicSharedMemorySize, GEMM_SMEM);
        cudaFuncSetAttribute(recurrence_kernel, cudaFuncAttributeMaxDynamicSharedMemorySize, REC_SMEM);
        smem_set = 1;
    }

    const long BSV = (long)BB*SS*VV;
    const long NBR = (long)NCELL*BB*RR;
    bool write_state = ((long)out_size >= BSV + 2*NBR);
    float* hf_out = write_state ? out + BSV        : nullptr;
    float* cf_out = write_state ? out + BSV + NBR  : nullptr;

    // 0. fp16 weight conversions
    convh_kernel<<<  768, 256>>>(in_w,   inwh);
    convh_kernel<<<16384, 256>>>(W_ih,   wihh);
    convh_kernel<<< 4096, 256>>>(W_np,   wnph);
    convh_kernel<<<  256, 256>>>(op_w,   opwh);
    convh_kernel<<<16000, 256>>>(head_w, hdwh);
    // 1. embed + counter reset
    embed_kernel<<<MROWS, 128>>>(x, emb);
    // 2. repack W_hh into fragment order (fp16)
    repack_mma<<<(NCELL*GG*RR/8)/256, 256>>>(W_hh);
    // 3. q = xs @ Wq^T + bq
    mma_gemm<<<dim3(DD/128, MROWS/128, 1), 256, GEMM_SMEM>>>(
        xsh, inwh, in_b, nullptr, qpre, DD, DD,
        0, 0, 0,
        8L*DD, DD, 1, 0, 0, 30, 0);
    // 4. gates_ih = xs @ W_ih^T + (b_ih+b_hh)  -> ihp[t][n][b][g]
    mma_gemm<<<dim3(NCELL*GG/128, MROWS/128, 1), 256, GEMM_SMEM>>>(
        xsh, wihh, b_ih, b_hh, ihp, DD, DD,
        0, 0, 0,
        (long)NCELL*BB*GG, GG, 1, 0,
        (long)BB*GG, 11, 0);
    // 5. recurrence (persistent, 128 CTAs, tensor-core, smem W cache)
    recurrence_kernel<<<NCELL*8, 512, REC_SMEM>>>(h0, c0, hf_out, cf_out);
    // 6. nout[n] = hall[n] @ W_np[n]^T + b_np[n]  -> fp16
    mma_gemm<<<dim3(DD/128, MROWS/128, NCELL), 256, GEMM_SMEM>>>(
        hallh, wnph, b_np, nullptr, nouth, RR, RR,
        (long)SS*BB*RR, (long)DD*RR, DD,
        8L*DD, DD, 1, (long)SS*BB*DD, 0, 30, 1);
    // 7. kv = nout @ [Wk;Wv]^T + [bk;bv]  (fp32 out)
    mma_gemm<<<dim3(1024/128, (NCELL*MROWS)/128, 1), 256, GEMM_SMEM>>>(
        nouth, inwh + (size_t)DD*DD, in_b + DD, nullptr, kv, DD, DD,
        0, 0, 0,
        8L*1024, 1024, 1, 0, 0, 30, 0);
    // 8. attention (writes atth fp16)
    attn_kernel<<<MROWS, 256>>>();
    // 9. op projection (fp32 out)
    mma_gemm<<<dim3(DD/128, MROWS/128, 1), 256, GEMM_SMEM>>>(
        atth, opwh, op_b, nullptr, yraw, DD, DD,
        0, 0, 0,
        8L*DD, DD, 1, 0, 0, 30, 0);
    // 10. residual + LN (writes mixedh fp16)
    ln_kernel<<<MROWS, 256>>>(ln_g, ln_b);
    // 11. head: logits -> out (B,S,V) fp32
    mma_gemm<<<dim3(VV/128, MROWS/128, 1), 256, GEMM_SMEM>>>(
        mixedh, hdwh, head_b, nullptr, out, DD, DD,
        0, 0, 0,
        (long)VV, (long)SS*VV, 1, 0, 0, 30, 0);
}

// round 15
// speedup vs baseline: 4.2333x; 1.0144x over previous
#include <cuda_runtime.h>
#include <cuda_fp16.h>
#include <cstdint>

#define SS   256
#define BB   8
#define VV   32000
#define DD   512
#define NCELL 16
#define RR   512
#define GG   2048   // 4*R
#define HH   8
#define MROWS 2048  // S*B

// ---------------- scratch (__device__ globals; no allocation) ----------------
__device__ float  g_xs   [(size_t)SS*BB*DD];           // raw embeddings (residual)
__device__ __half g_xsh  [(size_t)SS*BB*DD];           // fp16 embeddings
__device__ float  g_qpre [(size_t)SS*BB*DD];
__device__ float  g_ihp  [(size_t)SS*NCELL*BB*GG];     // (S,N,B,G) fp32
__device__ __half g_wph  [(size_t)NCELL*GG*RR];        // W_hh fragment-packed fp16
__device__ __half g_hallh[(size_t)NCELL*SS*BB*RR];     // fp16 h history
__device__ __half g_nouth[(size_t)NCELL*SS*BB*DD];     // fp16 nout
__device__ float  g_kv   [(size_t)NCELL*SS*BB*1024];
__device__ __half g_atth [(size_t)SS*BB*DD];
__device__ float  g_yraw [(size_t)SS*BB*DD];
__device__ __half g_mixedh[(size_t)SS*BB*DD];
__device__ __half g_hbufh[2*NCELL*BB*RR];              // [parity][n][b][k] fp16
__device__ int    g_cnt  [NCELL];
// fp16 weight copies
__device__ __half g_inwh [(size_t)3*DD*DD];
__device__ __half g_wihh [(size_t)NCELL*GG*DD];
__device__ __half g_wnph [(size_t)NCELL*DD*RR];
__device__ __half g_opwh [(size_t)DD*DD];
__device__ __half g_hdwh [(size_t)VV*DD];

// ---------------- helpers ----------------
__device__ __forceinline__ void mma16(float* c, const uint32_t* a, const uint32_t* b) {
    asm volatile(
        "mma.sync.aligned.m16n8k16.row.col.f32.f16.f16.f32 "
        "{%0,%1,%2,%3}, {%4,%5,%6,%7}, {%8,%9}, {%0,%1,%2,%3};\n"
        : "+f"(c[0]), "+f"(c[1]), "+f"(c[2]), "+f"(c[3])
        : "r"(a[0]), "r"(a[1]), "r"(a[2]), "r"(a[3]), "r"(b[0]), "r"(b[1]));
}
__device__ __forceinline__ void ldsm4(uint32_t& r0, uint32_t& r1, uint32_t& r2, uint32_t& r3,
                                      uint32_t addr) {
    asm volatile("ldmatrix.sync.aligned.m8n8.x4.shared.b16 {%0,%1,%2,%3}, [%4];"
                 : "=r"(r0), "=r"(r1), "=r"(r2), "=r"(r3) : "r"(addr));
}
__device__ __forceinline__ void cp16(uint32_t saddr, const void* gaddr) {
    asm volatile("cp.async.ca.shared.global [%0], [%1], 16;\n" :: "r"(saddr), "l"(gaddr));
}
#define CP_COMMIT() asm volatile("cp.async.commit_group;\n")
#define CP_WAIT1()  asm volatile("cp.async.wait_group 1;\n")
__device__ __forceinline__ void rel_add1(int* p) {
    asm volatile("red.release.gpu.global.add.u32 [%0], 1;" :: "l"(p) : "memory");
}
__device__ __forceinline__ int acq_ld(const int* p) {
    int v;
    asm volatile("ld.acquire.gpu.global.u32 %0, [%1];" : "=r"(v) : "l"(p) : "memory");
    return v;
}

// ---------------- fused f32 -> f16 weight convert (5 regions) ----------------
// float4-unit region boundaries
#define CV_R0 196608u     // in_w   (3*512*512/4)
#define CV_R1 4390912u    // + W_ih (16*2048*512/4)
#define CV_R2 5439488u    // + W_np (16*512*512/4)
#define CV_R3 5505024u    // + op_w (512*512/4)
#define CV_R4 9601024u    // + head (32000*512/4)
__global__ __launch_bounds__(256)
void convall_kernel(const float* __restrict__ s0, const float* __restrict__ s1,
                    const float* __restrict__ s2, const float* __restrict__ s3,
                    const float* __restrict__ s4,
                    __half* d0, __half* d1, __half* d2, __half* d3, __half* d4)
{
    uint32_t o = blockIdx.x*256 + threadIdx.x;
    if (o >= CV_R4) return;
    const float* s; __half* d; uint32_t r;
    if      (o < CV_R0) { s = s0; d = d0; r = o; }
    else if (o < CV_R1) { s = s1; d = d1; r = o - CV_R0; }
    else if (o < CV_R2) { s = s2; d = d2; r = o - CV_R1; }
    else if (o < CV_R3) { s = s3; d = d3; r = o - CV_R2; }
    else                { s = s4; d = d4; r = o - CV_R3; }
    float4 v = ((const float4*)s)[r];
    __half2* dd = (__half2*)d + (size_t)r*2;
    dd[0] = __floats2half2_rn(v.x, v.y);
    dd[1] = __floats2half2_rn(v.z, v.w);
}

// ---------------- embed + counter reset ----------------
__global__ __launch_bounds__(128)
void embed_kernel(const int* __restrict__ x, const float* __restrict__ emb)
{
    int tb = blockIdx.x;               // t*8+b
    int t = tb >> 3, b = tb & 7;
    if (tb == 0 && threadIdx.x < NCELL) g_cnt[threadIdx.x] = 0;
    int idx = x[b*SS + t];
    float4 v = ((const float4*)(emb + (size_t)idx*DD))[threadIdx.x];
    ((float4*)(g_xs + (size_t)tb*DD))[threadIdx.x] = v;
    __half2* d = (__half2*)(g_xsh + (size_t)tb*DD) + threadIdx.x*2;
    d[0] = __floats2half2_rn(v.x, v.y);
    d[1] = __floats2half2_rn(v.z, v.w);
}

// ---------------- W_hh repack into mma A-fragment order (fp16) ----------------
__global__ __launch_bounds__(256)
void repack_mma(const float* __restrict__ whh)
{
    int o = blockIdx.x*256 + threadIdx.x;     // uint4 index
    int l    = o & 31;
    int ks   = (o >> 5) & 31;
    int w    = (o >> 10) & 15;
    int cb   = (o >> 14) & 7;
    int cell = o >> 17;
    __half h[8];
    #pragma unroll
    for (int r = 0; r < 4; r++) {
        int lr = w*16 + (l >> 2) + (r & 1)*8;
        int grow = (lr >> 6)*512 + cb*64 + (lr & 63);
        int k = ks*16 + (l & 3)*2 + (r >> 1)*8;
        const float* s = whh + ((size_t)cell*GG + grow)*RR + k;
        h[r*2]   = __float2half(s[0]);
        h[r*2+1] = __float2half(s[1]);
    }
    ((uint4*)g_wph)[o] = *(uint4*)h;
}

// ---------------- FP16 tensor-core GEMM: C = A @ B^T + bias ----------------
// Optional fused q-region: columns >= qColStart read BwQ/biasQ and write CQ
// with layout [t][b][d] (row m: (m>>3)*8D + (m&7)*D + c').
#define ST_H   (128*72)      // halves per operand per stage
#define NSTG   3
__global__ __launch_bounds__(256, 2)
void mma_gemm(const __half* __restrict__ A, const __half* __restrict__ Bw,
              const float* __restrict__ bias1, const float* __restrict__ bias2,
              void* __restrict__ Cv, int K, long lda,
              long sAz, long sBz, long sBiasZ,
              long sCt, long sCb, long sCc, long sCz,
              long sCcBlk, int blkLog, int outHalf,
              const __half* __restrict__ BwQ, const float* __restrict__ biasQ,
              float* __restrict__ CQ, int qColStart)
{
    extern __shared__ __half smem[];
    __half* Abuf = smem;                 // [3][128][72]
    __half* Bbuf = smem + NSTG*ST_H;

    int tid  = threadIdx.x;
    int lane = tid & 31;
    int warp = tid >> 5;
    int wm = warp & 1;
    int wn = warp >> 1;
    int bx = blockIdx.x, by = blockIdx.y, bz = blockIdx.z;

    bool qreg = (qColStart >= 0) && (bx*128 >= qColStart);

    const __half* Ab = A  + (size_t)bz * sAz;
    const __half* Bb = Bw + (size_t)bz * sBz;

    int lm   = tid >> 1;
    int half = tid & 1;
    const __half* ag = Ab + (size_t)(by*128 + lm)*lda + half*32;
    const __half* bg;
    if (qreg) bg = BwQ + (size_t)(bx*128 - qColStart + lm)*K + half*32;
    else      bg = Bb  + (size_t)(bx*128 + lm)*K + half*32;
    uint32_t sA = (uint32_t)__cvta_generic_to_shared(Abuf) + (uint32_t)(lm*72 + half*32)*2u;
    uint32_t sB = (uint32_t)__cvta_generic_to_shared(Bbuf) + (uint32_t)(lm*72 + half*32)*2u;

    int qr = lane >> 2;
    int qc = lane & 3;
    int amBase = wm*64;
    int bnBase = wn*32;

    uint32_t aFragBase = (uint32_t)__cvta_generic_to_shared(Abuf)
        + (uint32_t)((amBase + (lane & 15))*72 + (lane >> 4)*8)*2u;
    uint32_t bFragBase = (uint32_t)__cvta_generic_to_shared(Bbuf)
        + (uint32_t)((bnBase + (lane & 7) + ((lane >> 4) << 3))*72 + (lane & 8))*2u;

    float acc[4][4][4];
    #pragma unroll
    for (int i = 0; i < 4; i++)
        #pragma unroll
        for (int j = 0; j < 4; j++)
            #pragma unroll
            for (int e = 0; e < 4; e++) acc[i][j][e] = 0.f;

    int KT = K >> 6;

    #pragma unroll
    for (int p = 0; p < NSTG-1; p++) {
        uint32_t aoff = sA + p*ST_H*2;
        uint32_t boff = sB + p*ST_H*2;
        #pragma unroll
        for (int q = 0; q < 4; q++) {
            cp16(aoff + q*16, ag + p*64 + q*8);
            cp16(boff + q*16, bg + p*64 + q*8);
        }
        CP_COMMIT();
    }

    for (int kt = 0; kt < KT; kt++) {
        CP_WAIT1();
        __syncthreads();
        if (kt + NSTG-1 < KT) {
            int stg = (kt + NSTG-1) % NSTG;
            uint32_t aoff = sA + stg*ST_H*2;
            uint32_t boff = sB + stg*ST_H*2;
            #pragma unroll
            for (int q = 0; q < 4; q++) {
                cp16(aoff + q*16, ag + (kt+NSTG-1)*64 + q*8);
                cp16(boff + q*16, bg + (kt+NSTG-1)*64 + q*8);
            }
        }
        CP_COMMIT();

        uint32_t aS = aFragBase + (kt % NSTG)*ST_H*2;
        uint32_t bS = bFragBase + (kt % NSTG)*ST_H*2;
        #pragma unroll
        for (int ks = 0; ks < 4; ks++) {
            uint32_t k0b = ks*16*2;
            uint32_t af[4][4], bf[4][2];
            #pragma unroll
            for (int i = 0; i < 4; i++)
                ldsm4(af[i][0], af[i][1], af[i][2], af[i][3],
                      aS + (uint32_t)(i*16*72)*2u + k0b);
            #pragma unroll
            for (int jp = 0; jp < 2; jp++)
                ldsm4(bf[jp*2][0], bf[jp*2][1], bf[jp*2+1][0], bf[jp*2+1][1],
                      bS + (uint32_t)(jp*16*72)*2u + k0b);
            #pragma unroll
            for (int i = 0; i < 4; i++)
                #pragma unroll
                for (int j = 0; j < 4; j++)
                    mma16(acc[i][j], af[i], bf[j]);
        }
    }

    long msk = (1L << blkLog) - 1;
    #pragma unroll
    for (int i = 0; i < 4; i++) {
        int r0 = by*128 + amBase + i*16 + qr;
        #pragma unroll
        for (int j = 0; j < 4; j++) {
            int c0 = bx*128 + bnBase + j*8 + 2*qc;
            if (qreg) {
                int cq = c0 - qColStart;
                float b0v = biasQ[cq], b1v = biasQ[cq + 1];
                long ro  = (long)(r0 >> 3)*(8*DD) + (long)(r0 & 7)*DD;
                long ro8 = (long)((r0+8) >> 3)*(8*DD) + (long)((r0+8) & 7)*DD;
                CQ[ro  + cq]     = acc[i][j][0] + b0v;
                CQ[ro  + cq + 1] = acc[i][j][1] + b1v;
                CQ[ro8 + cq]     = acc[i][j][2] + b0v;
                CQ[ro8 + cq + 1] = acc[i][j][3] + b1v;
            } else {
                long ro  = (long)(r0 >> 3)*sCt + (long)(r0 & 7)*sCb;
                long ro8 = (long)((r0+8) >> 3)*sCt + (long)((r0+8) & 7)*sCb;
                float b0v = 0.f, b1v = 0.f;
                if (bias1) { b0v  = bias1[(long)bz*sBiasZ + c0];
                             b1v  = bias1[(long)bz*sBiasZ + c0 + 1]; }
                if (bias2) { b0v += bias2[c0]; b1v += bias2[c0 + 1]; }
                long cc0 = (long)(c0 >> blkLog)*sCcBlk + (long)(c0 & msk)*sCc;
                long cc1 = (long)((c0+1) >> blkLog)*sCcBlk + (long)((c0+1) & msk)*sCc;
                float v00 = acc[i][j][0] + b0v, v01 = acc[i][j][1] + b1v;
                float v10 = acc[i][j][2] + b0v, v11 = acc[i][j][3] + b1v;
                if (outHalf) {
                    __half* Cb = (__half*)Cv + (size_t)bz * sCz;
                    Cb[ro  + cc0] = __float2half(v00);
                    Cb[ro  + cc1] = __float2half(v01);
                    Cb[ro8 + cc0] = __float2half(v10);
                    Cb[ro8 + cc1] = __float2half(v11);
                } else {
                    float* Cb = (float*)Cv + (size_t)bz * sCz;
                    Cb[ro  + cc0] = v00;
                    Cb[ro  + cc1] = v01;
                    Cb[ro8 + cc0] = v10;
                    Cb[ro8 + cc1] = v11;
                }
            }
        }
    }
}

// ---------------- persistent LSTM recurrence (tensor-core + smem W cache) ----
#define HPAD 520
#define KS_SMEM 24
#define W_SMEM_B (16*KS_SMEM*32*16)          // 196608
#define REC_SMEM (W_SMEM_B + BB*HPAD*2 + 256*10*4)   // 215168
__global__ __launch_bounds__(512)
void recurrence_kernel(const float* __restrict__ h0, const float* __restrict__ c0,
                       float* hf_out, float* cf_out)
{
    extern __shared__ char dsm[];
    uint4*  wsm = (uint4*)dsm;                          // [16][24][32]
    __half* h_s = (__half*)(dsm + W_SMEM_B);            // [b][k] padded
    float (*g_sm)[10] = (float(*)[10])(dsm + W_SMEM_B + BB*HPAD*2);

    int tid  = threadIdx.x;
    int cell = blockIdx.x >> 3;
    int cb   = blockIdx.x & 7;
    int warp = tid >> 5;
    int l    = tid & 31;

    int ub = tid >> 6;                  // batch for update phase
    int uj = tid & 63;                  // unit for update phase

    const uint4* wf = (const uint4*)g_wph + ((size_t)((cell*8 + cb)*16 + warp))*1024 + l;

    // fill W smem cache (warp-local: each lane stores/reloads only its own frag)
    #pragma unroll 4
    for (int ks = 0; ks < KS_SMEM; ks++)
        wsm[(warp*KS_SMEM + ks)*32 + l] = __ldg(wf + ks*32);

    // init h_s from h0 (fp32 -> fp16)
    {
        int b = tid >> 6, k = (tid & 63)*8;
        const float4* s = (const float4*)(h0 + ((size_t)cell*BB + b)*RR + k);
        float4 p0 = s[0], p1 = s[1];
        __half hh[8];
        hh[0]=__float2half(p0.x); hh[1]=__float2half(p0.y);
        hh[2]=__float2half(p0.z); hh[3]=__float2half(p0.w);
        hh[4]=__float2half(p1.x); hh[5]=__float2half(p1.y);
        hh[6]=__float2half(p1.z); hh[7]=__float2half(p1.w);
        *(uint4*)&h_s[b*HPAD + k] = *(uint4*)hh;
    }
    float c_reg = c0[((size_t)cell*BB + ub)*RR + cb*64 + uj];
    __syncthreads();

    int hb = (l >> 2)*HPAD + (l & 3)*2;       // half index of b-frag base
    int lw = warp*16 + (l >> 2);
    int n0 = (l & 3)*2;

    for (int t = 0; t < SS; t++) {
        // prefetch the streamed tail (ks 24..31)
        uint4 wreg[8];
        #pragma unroll
        for (int i = 0; i < 8; i++)
            wreg[i] = __ldcg(wf + (KS_SMEM + i)*32);

        float c4a[4] = {0.f, 0.f, 0.f, 0.f};
        float c4b[4] = {0.f, 0.f, 0.f, 0.f};
        #pragma unroll 8
        for (int ks = 0; ks < KS_SMEM; ks++) {
            uint4 a = wsm[(warp*KS_SMEM + ks)*32 + l];
            uint32_t bb[2];
            bb[0] = *(const uint32_t*)&h_s[hb + ks*16];
            bb[1] = *(const uint32_t*)&h_s[hb + ks*16 + 8];
            mma16((ks & 1) ? c4b : c4a, (const uint32_t*)&a, bb);
        }
        #pragma unroll
        for (int i = 0; i < 8; i++) {
            int ks = KS_SMEM + i;
            uint32_t bb[2];
            bb[0] = *(const uint32_t*)&h_s[hb + ks*16];
            bb[1] = *(const uint32_t*)&h_s[hb + ks*16 + 8];
            mma16((i & 1) ? c4b : c4a, (const uint32_t*)&wreg[i], bb);
        }
        float c4[4];
        #pragma unroll
        for (int e = 0; e < 4; e++) c4[e] = c4a[e] + c4b[e];

        *(float2*)&g_sm[lw][n0]     = make_float2(c4[0], c4[1]);
        *(float2*)&g_sm[lw + 8][n0] = make_float2(c4[2], c4[3]);
        __syncthreads();

        // LSTM update for (unit uj, batch ub); add precomputed ih+bias here
        const float* ib = g_ihp + (((size_t)t*NCELL + cell)*BB + ub)*GG + cb*64 + uj;
        float gi = g_sm[      uj][ub] + ib[0];
        float gf = g_sm[ 64 + uj][ub] + ib[512];
        float gg = g_sm[128 + uj][ub] + ib[1024];
        float go = g_sm[192 + uj][ub] + ib[1536];
        float si = 1.f/(1.f + expf(-gi));
        float sf = 1.f/(1.f + expf(-gf));
        float so = 1.f/(1.f + expf(-go));
        float cn = sf*c_reg + si*tanhf(gg);
        float hn = so*tanhf(cn);
        c_reg = cn;

        __half hnh = __float2half(hn);
        g_hallh[(((size_t)cell*SS + t)*BB + ub)*RR + cb*64 + uj] = hnh;
        int par = (t + 1) & 1;
        g_hbufh[((size_t)(par*NCELL + cell)*BB + ub)*RR + cb*64 + uj] = hnh;
        if (t == SS-1) {
            if (hf_out) hf_out[((size_t)cell*BB + ub)*RR + cb*64 + uj] = hn;
            if (cf_out) cf_out[((size_t)cell*BB + ub)*RR + cb*64 + uj] = cn;
        }

        __syncthreads();                 // all stores of this CTA done
        if (tid == 0) {
            rel_add1(&g_cnt[cell]);      // release: publishes CTA's stores
            int target = 8*(t+1);
            while (acq_ld(&g_cnt[cell]) < target) { }
        }
        __syncthreads();

        // reload h_s directly as fp16 (peer CTAs' writes; L1-bypass)
        {
            int b = tid >> 6, k = (tid & 63)*8;
            uint4 v = __ldcg((const uint4*)&g_hbufh[((size_t)(par*NCELL + cell)*BB + b)*RR + k]);
            *(uint4*)&h_s[b*HPAD + k] = v;
        }
        __syncthreads();
    }
}

// ---------------- attention (q,k,v -> att fp16) ----------------
__global__ __launch_bounds__(256)
void attn_kernel()
{
    int tb = blockIdx.x;                // t*8+b
    int t = tb >> 3, b = tb & 7;
    int h = threadIdx.x >> 5;
    int lane = threadIdx.x & 31;

    const float* qrow = g_qpre + (size_t)tb*DD + h*64;
    float q0 = qrow[2*lane], q1 = qrow[2*lane + 1];

    float s[NCELL];
    #pragma unroll
    for (int n = 0; n < NCELL; n++) {
        const float* kp = g_kv + (((size_t)n*SS + t)*BB + b)*1024 + h*64;
        float2 k2 = *(const float2*)(kp + 2*lane);
        float p = q0*k2.x + q1*k2.y;
        #pragma unroll
        for (int o = 16; o > 0; o >>= 1) p += __shfl_xor_sync(0xffffffffu, p, o);
        s[n] = p * 0.125f;
    }
    float m = s[0];
    #pragma unroll
    for (int n = 1; n < NCELL; n++) m = fmaxf(m, s[n]);
    float sum = 0.f;
    #pragma unroll
    for (int n = 0; n < NCELL; n++) { s[n] = expf(s[n] - m); sum += s[n]; }
    float inv = 1.f/sum;

    float a0 = 0.f, a1 = 0.f;
    #pragma unroll
    for (int n = 0; n < NCELL; n++) {
        const float* vp = g_kv + (((size_t)n*SS + t)*BB + b)*1024 + 512 + h*64;
        float2 v2 = *(const float2*)(vp + 2*lane);
        float w = s[n]*inv;
        a0 += w*v2.x; a1 += w*v2.y;
    }
    __half2* ap = (__half2*)(g_atth + (size_t)tb*DD + h*64) + lane;
    *ap = __floats2half2_rn(a0, a1);
}

// ---------------- residual + layernorm (-> fp16) ----------------
__global__ __launch_bounds__(256)
void ln_kernel(const float* __restrict__ lng, const float* __restrict__ lnb)
{
    __shared__ float red[8];
    int tb = blockIdx.x;
    int tid = threadIdx.x;
    const float* yp = g_yraw + (size_t)tb*DD;
    const float* xp = g_xs   + (size_t)tb*DD;
    float y0 = yp[2*tid]   + xp[2*tid];
    float y1 = yp[2*tid+1] + xp[2*tid+1];

    float v = y0 + y1;
    #pragma unroll
    for (int o = 16; o > 0; o >>= 1) v += __shfl_xor_sync(0xffffffffu, v, o);
    if ((tid & 31) == 0) red[tid >> 5] = v;
    __syncthreads();
    float r = (tid < 8) ? red[tid] : 0.f;
    if (tid < 32) {
        #pragma unroll
        for (int o = 4; o > 0; o >>= 1) r += __shfl_xor_sync(0xffffffffu, r, o);
        if (tid == 0) red[0] = r;
    }
    __syncthreads();
    float mu = red[0] * (1.f/512.f);
    __syncthreads();

    float d0 = y0 - mu, d1 = y1 - mu;
    float sq = d0*d0 + d1*d1;
    #pragma unroll
    for (int o = 16; o > 0; o >>= 1) sq += __shfl_xor_sync(0xffffffffu, sq, o);
    if ((tid & 31) == 0) red[tid >> 5] = sq;
    __syncthreads();
    float r2 = (tid < 8) ? red[tid] : 0.f;
    if (tid < 32) {
        #pragma unroll
        for (int o = 4; o > 0; o >>= 1) r2 += __shfl_xor_sync(0xffffffffu, r2, o);
        if (tid == 0) red[0] = r2;
    }
    __syncthreads();
    float rstd = rsqrtf(red[0] * (1.f/512.f) + 1e-5f);

    __half2* mp = (__half2*)(g_mixedh + (size_t)tb*DD) + tid;
    *mp = __floats2half2_rn(d0*rstd*lng[2*tid]   + lnb[2*tid],
                            d1*rstd*lng[2*tid+1] + lnb[2*tid+1]);
}

// ---------------- host launcher ----------------
extern "C" void kernel_launch(void* const* d_in, const int* in_sizes, int n_in,
                              void* d_out, int out_size)
{
    const int*   x      = (const int*)  d_in[0];
    const float* h0     = (const float*)d_in[1];
    const float* c0     = (const float*)d_in[2];
    const float* emb    = (const float*)d_in[3];
    const float* W_ih   = (const float*)d_in[4];
    const float* b_ih   = (const float*)d_in[5];
    const float* W_hh   = (const float*)d_in[6];
    const float* b_hh   = (const float*)d_in[7];
    const float* W_np   = (const float*)d_in[8];
    const float* b_np   = (const float*)d_in[9];
    const float* in_w   = (const float*)d_in[10];
    const float* in_b   = (const float*)d_in[11];
    const float* op_w   = (const float*)d_in[12];
    const float* op_b   = (const float*)d_in[13];
    const float* ln_g   = (const float*)d_in[14];
    const float* ln_b   = (const float*)d_in[15];
    const float* head_w = (const float*)d_in[16];
    const float* head_b = (const float*)d_in[17];
    float* out = (float*)d_out;

    float *qpre, *ihp, *kv, *yraw;
    __half *xsh, *hallh, *nouth, *atth, *mixedh;
    __half *inwh, *wihh, *wnph, *opwh, *hdwh;
    cudaGetSymbolAddress((void**)&xsh,    g_xsh);
    cudaGetSymbolAddress((void**)&qpre,   g_qpre);
    cudaGetSymbolAddress((void**)&ihp,    g_ihp);
    cudaGetSymbolAddress((void**)&hallh,  g_hallh);
    cudaGetSymbolAddress((void**)&nouth,  g_nouth);
    cudaGetSymbolAddress((void**)&kv,     g_kv);
    cudaGetSymbolAddress((void**)&atth,   g_atth);
    cudaGetSymbolAddress((void**)&yraw,   g_yraw);
    cudaGetSymbolAddress((void**)&mixedh, g_mixedh);
    cudaGetSymbolAddress((void**)&inwh,   g_inwh);
    cudaGetSymbolAddress((void**)&wihh,   g_wihh);
    cudaGetSymbolAddress((void**)&wnph,   g_wnph);
    cudaGetSymbolAddress((void**)&opwh,   g_opwh);
    cudaGetSymbolAddress((void**)&hdwh,   g_hdwh);

    const int GEMM_SMEM = 2*NSTG*ST_H*(int)sizeof(__half);   // 110592 B
    static int smem_set = 0;
    if (!smem_set) {
        cudaFuncSetAttribute(mma_gemm, cudaFuncAttributeMaxDynamicSharedMemorySize, GEMM_SMEM);
        cudaFuncSetAttribute(recurrence_kernel, cudaFuncAttributeMaxDynamicSharedMemorySize, REC_SMEM);
        smem_set = 1;
    }

    const long BSV = (long)BB*SS*VV;
    const long NBR = (long)NCELL*BB*RR;
    bool write_state = ((long)out_size >= BSV + 2*NBR);
    float* hf_out = write_state ? out + BSV        : nullptr;
    float* cf_out = write_state ? out + BSV + NBR  : nullptr;

    // 0. fused fp16 weight conversions (one launch)
    convall_kernel<<<(CV_R4 + 255)/256, 256>>>(in_w, W_ih, W_np, op_w, head_w,
                                               inwh, wihh, wnph, opwh, hdwh);
    // 1. embed + counter reset
    embed_kernel<<<MROWS, 128>>>(x, emb);
    // 2. repack W_hh into fragment order (fp16)
    repack_mma<<<(NCELL*GG*RR/8)/256, 256>>>(W_hh);
    // 3. fused gates_ih + q GEMM: cols [0,32768) -> ihp, [32768,33280) -> qpre
    mma_gemm<<<dim3((NCELL*GG + DD)/128, MROWS/128, 1), 256, GEMM_SMEM>>>(
        xsh, wihh, b_ih, b_hh, ihp, DD, DD,
        0, 0, 0,
        (long)NCELL*BB*GG, GG, 1, 0,
        (long)BB*GG, 11, 0,
        inwh, in_b, qpre, NCELL*GG);
    // 4. recurrence (persistent, 128 CTAs, tensor-core, smem W cache)
    recurrence_kernel<<<NCELL*8, 512, REC_SMEM>>>(h0, c0, hf_out, cf_out);
    // 5. nout[n] = hall[n] @ W_np[n]^T + b_np[n]  -> fp16
    mma_gemm<<<dim3(DD/128, MROWS/128, NCELL), 256, GEMM_SMEM>>>(
        hallh, wnph, b_np, nullptr, nouth, RR, RR,
        (long)SS*BB*RR, (long)DD*RR, DD,
        8L*DD, DD, 1, (long)SS*BB*DD, 0, 30, 1,
        nullptr, nullptr, nullptr, -1);
    // 6. kv = nout @ [Wk;Wv]^T + [bk;bv]  (fp32 out)
    mma_gemm<<<dim3(1024/128, (NCELL*MROWS)/128, 1), 256, GEMM_SMEM>>>(
        nouth, inwh + (size_t)DD*DD, in_b + DD, nullptr, kv, DD, DD,
        0, 0, 0,
        8L*1024, 1024, 1, 0, 0, 30, 0,
        nullptr, nullptr, nullptr, -1);
    // 7. attention (writes atth fp16)
    attn_kernel<<<MROWS, 256>>>();
    // 8. op projection (fp32 out)
    mma_gemm<<<dim3(DD/128, MROWS/128, 1), 256, GEMM_SMEM>>>(
        atth, opwh, op_b, nullptr, yraw, DD, DD,
        0, 0, 0,
        8L*DD, DD, 1, 0, 0, 30, 0,
        nullptr, nullptr, nullptr, -1);
    // 9. residual + LN (writes mixedh fp16)
    ln_kernel<<<MROWS, 256>>>(ln_g, ln_b);
    // 10. head: logits -> out (B,S,V) fp32
    mma_gemm<<<dim3(VV/128, MROWS/128, 1), 256, GEMM_SMEM>>>(
        mixedh, hdwh, head_b, nullptr, out, DD, DD,
        0, 0, 0,
        (long)VV, (long)SS*VV, 1, 0, 0, 30, 0,
        nullptr, nullptr, nullptr, -1);
}